// round 5
// baseline (speedup 1.0000x reference)
#include <cuda_runtime.h>
#include <math.h>
#include <stdint.h>

#define BDIM   512
#define SDIM   1024
#define BATCH  8
#define NHEADS 8
#define HD     64
#define DFF    2048
#define NTOK   (BATCH * SDIM)   // 8192

// Scratch
__device__ float    g_q [BATCH * BDIM * SDIM];   // [B,H,S,64]
__device__ float    g_k [BATCH * BDIM * SDIM];   // [B,H,S,64]
__device__ float    g_v [BATCH * BDIM * SDIM];   // [B,D,S]
__device__ float    g_av[NTOK * BDIM];
__device__ float    g_t1[NTOK * BDIM];
__device__ float    g_x1[NTOK * BDIM];
__device__ float    g_ff[NTOK * DFF];
__device__ uint32_t g_wt[2 * 3 * BDIM * BDIM];   // tf32 Wq/Wk: [mat][tap][co][ci]
__device__ uint32_t g_wc[2 * BDIM * BDIM + 2 * DFF * BDIM];  // tf32 Wv,Wo,W1,W2

#define WC_WV 0
#define WC_WO (BDIM * BDIM)
#define WC_W1 (2 * BDIM * BDIM)
#define WC_W2 (2 * BDIM * BDIM + DFF * BDIM)

__device__ __forceinline__ uint32_t f2tf(float f) {
    uint32_t r;
    asm("cvt.rna.tf32.f32 %0, %1;" : "=r"(r) : "f"(f));
    return r;
}

__device__ __forceinline__ void mma_tf32(float c[4], const uint32_t a[4], const uint32_t b[2]) {
    asm volatile(
        "mma.sync.aligned.m16n8k8.row.col.f32.tf32.tf32.f32 "
        "{%0,%1,%2,%3}, {%4,%5,%6,%7}, {%8,%9}, {%0,%1,%2,%3};"
        : "+f"(c[0]), "+f"(c[1]), "+f"(c[2]), "+f"(c[3])
        : "r"(a[0]), "r"(a[1]), "r"(a[2]), "r"(a[3]), "r"(b[0]), "r"(b[1]));
}

// ---------------------------------------------------------------------------
// Merged prep: all weight conversions in one launch.
// Ranges: [0, WTN): wtrans of Wq/Wk ; then Wv, Wo, W1, W2 plain cvt.
// ---------------------------------------------------------------------------
#define WTN (2 * 3 * BDIM * BDIM)
__global__ void wprep_kernel(const float* __restrict__ Wq, const float* __restrict__ Wk,
                             const float* __restrict__ Wv, const float* __restrict__ Wo,
                             const float* __restrict__ W1, const float* __restrict__ W2,
                             uint32_t* __restrict__ wt, uint32_t* __restrict__ wc) {
    int e = blockIdx.x * 256 + threadIdx.x;
    if (e < WTN) {
        int m  = (e >= 3 * BDIM * BDIM);
        int e2 = e - m * 3 * BDIM * BDIM;
        int t  = e2 >> 18;
        int co = (e2 >> 9) & 511;
        int ci = e2 & 511;
        const float* src = m ? Wk : Wq;
        wt[e] = f2tf(src[(size_t)co * 1536 + ci * 3 + t]);
        return;
    }
    int f = e - WTN;
    if (f < BDIM * BDIM)            { wc[WC_WV + f] = f2tf(Wv[f]); return; }
    f -= BDIM * BDIM;
    if (f < BDIM * BDIM)            { wc[WC_WO + f] = f2tf(Wo[f]); return; }
    f -= BDIM * BDIM;
    if (f < DFF * BDIM)             { wc[WC_W1 + f] = f2tf(W1[f]); return; }
    f -= DFF * BDIM;
    if (f < DFF * BDIM)             { wc[WC_W2 + f] = f2tf(W2[f]); return; }
}
#define WPREP_TOTAL (WTN + 2 * BDIM * BDIM + 2 * DFF * BDIM)

// ===========================================================================
// GEMM core v3: block 128(n) x 64(m), 8 warps (32x32), KT=32,
// fragment-major XOR-swizzled smem, double-buffered smem + DOUBLE register
// staging (LDG issued 2 stages ahead).
// MODE 0: +res | 1: relu | 2: +res | 3: V-conv layout [B,D,S] (bias only)
// ===========================================================================
template <int MODE>
__global__ __launch_bounds__(256, 2) void gemm2(const float* __restrict__ A,
                                                const uint32_t* __restrict__ W,
                                                const float* __restrict__ bias,
                                                const float* __restrict__ res,
                                                float* __restrict__ out, int M, int K) {
    __shared__ uint4 Af[2][8][4][32];   // 32KB
    __shared__ uint2 Bf[2][8][4][32];   // 16KB

    const int n0 = blockIdx.x * 128;
    const int m0 = blockIdx.y * 64;
    const int tid = threadIdx.x, lane = tid & 31, warp = tid >> 5;
    const int lq = lane >> 2, lr = lane & 3;
    const int wiB = (warp >> 1) * 2;
    const int wjB = (warp & 1) * 4;
    const int nk = K >> 5;   // always even (>=16)

    float acc[2][4][4];
    #pragma unroll
    for (int mi = 0; mi < 2; mi++)
        #pragma unroll
        for (int ni = 0; ni < 4; ni++)
            #pragma unroll
            for (int c = 0; c < 4; c++) acc[mi][ni][c] = 0.f;

    float4 sa0[4], sa1[4];
    uint4  sb0[2], sb1[2];

    #define G2_LDG(SA, SB, KO)                                                        \
        { int ko_ = (KO);                                                             \
          _Pragma("unroll")                                                           \
          for (int r = 0; r < 4; r++) {                                               \
              int v = tid + 256 * r;                                                  \
              SA[r] = *(const float4*)&A[(size_t)(n0 + (v >> 3)) * K + ko_ + (v & 7) * 4]; } \
          _Pragma("unroll")                                                           \
          for (int r = 0; r < 2; r++) {                                               \
              int v = tid + 256 * r;                                                  \
              SB[r] = *(const uint4*)&W[(size_t)(m0 + (v >> 3)) * K + ko_ + (v & 7) * 4]; } }

    #define G2_STS(SA, SB, ST)                                                        \
        { _Pragma("unroll")                                                           \
          for (int r = 0; r < 4; r++) {                                               \
              int v = tid + 256 * r;                                                  \
              int row = v >> 3, kc4 = v & 7;                                          \
              int ks = kc4 >> 1, half = kc4 & 1, rb = row >> 4, alq = row & 7, r8 = (row >> 3) & 1; \
              int comp = r8 + 2 * half;                                               \
              uint32_t* base = (uint32_t*)&Af[ST][rb][ks][0];                         \
              uint32_t vals[4] = {f2tf(SA[r].x), f2tf(SA[r].y), f2tf(SA[r].z), f2tf(SA[r].w)}; \
              _Pragma("unroll")                                                       \
              for (int e = 0; e < 4; e++) base[(((alq * 4 + e) ^ ks) << 2) + comp] = vals[e]; } \
          _Pragma("unroll")                                                           \
          for (int r = 0; r < 2; r++) {                                               \
              int v = tid + 256 * r;                                                  \
              int row = v >> 3, kc4 = v & 7;                                          \
              int ks = kc4 >> 1, half = kc4 & 1, nb = row >> 3, blq = row & 7;        \
              uint32_t* base = (uint32_t*)&Bf[ST][nb][ks][0];                         \
              uint32_t vals[4] = {SB[r].x, SB[r].y, SB[r].z, SB[r].w};                \
              _Pragma("unroll")                                                       \
              for (int e = 0; e < 4; e++) base[(((blq * 4 + e) ^ ks) << 1) + half] = vals[e]; } }

    #define G2_COMP(ST)                                                               \
        { _Pragma("unroll")                                                           \
          for (int ks = 0; ks < 4; ks++) {                                            \
              uint4 a0 = Af[ST][wiB][ks][lane ^ ks];                                  \
              uint4 a1 = Af[ST][wiB + 1][ks][lane ^ ks];                              \
              uint32_t aa0[4] = {a0.x, a0.y, a0.z, a0.w};                             \
              uint32_t aa1[4] = {a1.x, a1.y, a1.z, a1.w};                             \
              _Pragma("unroll")                                                       \
              for (int ni = 0; ni < 4; ni++) {                                        \
                  uint2 b = Bf[ST][wjB + ni][ks][lane ^ ks];                          \
                  uint32_t bb[2] = {b.x, b.y};                                        \
                  mma_tf32(acc[0][ni], aa0, bb);                                      \
                  mma_tf32(acc[1][ni], aa1, bb); } } }

    // Prologue: stage 0 and 1 into regs; stage 0 into smem.
    G2_LDG(sa0, sb0, 0)
    G2_LDG(sa1, sb1, 32)
    G2_STS(sa0, sb0, 0)
    __syncthreads();

    for (int kb = 0; kb < nk; kb += 2) {
        if (kb + 2 < nk) G2_LDG(sa0, sb0, (kb + 2) << 5)
        G2_COMP(0)
        G2_STS(sa1, sb1, 1)
        __syncthreads();

        if (kb + 3 < nk) G2_LDG(sa1, sb1, (kb + 3) << 5)
        G2_COMP(1)
        if (kb + 2 < nk) G2_STS(sa0, sb0, 0)
        __syncthreads();
    }

    #undef G2_LDG
    #undef G2_STS
    #undef G2_COMP

    // Epilogue
    #pragma unroll
    for (int mi = 0; mi < 2; mi++) {
        #pragma unroll
        for (int ni = 0; ni < 4; ni++) {
            int col = m0 + (warp & 1) * 32 + ni * 8 + 2 * lr;
            float bv0 = bias[col], bv1 = bias[col + 1];
            #pragma unroll
            for (int h = 0; h < 2; h++) {
                int n = n0 + (warp >> 1) * 32 + mi * 16 + lq + h * 8;
                float x0 = acc[mi][ni][2 * h] + bv0;
                float x1 = acc[mi][ni][2 * h + 1] + bv1;
                if (MODE == 1) { x0 = fmaxf(x0, 0.f); x1 = fmaxf(x1, 0.f); }
                if (MODE == 0 || MODE == 2) {
                    x0 += res[(size_t)n * M + col];
                    x1 += res[(size_t)n * M + col + 1];
                }
                if (MODE == 3) {
                    int b = n >> 10, s = n & 1023;
                    out[((size_t)(b * BDIM + col)) * SDIM + s]     = x0;
                    out[((size_t)(b * BDIM + col + 1)) * SDIM + s] = x1;
                } else {
                    *(float2*)&out[(size_t)n * M + col] = make_float2(x0, x1);
                }
            }
        }
    }
}

// ===========================================================================
// Fused Q+K conv: block 128(tok) x 32(co) x 2 mats, double register staging.
// ===========================================================================
__global__ __launch_bounds__(256, 2) void convqk(const float* __restrict__ A,
                                                 const uint32_t* __restrict__ Wt,
                                                 const float* __restrict__ bq,
                                                 const float* __restrict__ bk,
                                                 float* __restrict__ qo,
                                                 float* __restrict__ ko) {
    __shared__ uint4 Af[2][8][4][32];        // 32KB
    __shared__ uint2 Bf[2][2][4][4][32];     // 16KB

    const int n0 = blockIdx.x * 128;
    const int c0 = blockIdx.y * 32;
    const int tid = threadIdx.x, lane = tid & 31, warp = tid >> 5;
    const int lq = lane >> 2, lr = lane & 3;
    const int NST = 48;  // 3 taps x 16 kb

    float acc[2][4][4];
    #pragma unroll
    for (int m = 0; m < 2; m++)
        #pragma unroll
        for (int ni = 0; ni < 4; ni++)
            #pragma unroll
            for (int c = 0; c < 4; c++) acc[m][ni][c] = 0.f;

    float4 sa0[4], sa1[4];
    uint4  sb0[2], sb1[2];

    #define CQ_LDG(SA, SB, T)                                                         \
        { int t_ = (T);                                                               \
          int tap_ = t_ >> 4, ko_ = (t_ & 15) << 5, roff_ = tap_ - 1;                 \
          _Pragma("unroll")                                                           \
          for (int r = 0; r < 4; r++) {                                               \
              int v = tid + 256 * r;                                                  \
              int row = v >> 3;                                                       \
              int n = n0 + row;                                                       \
              int s = (n & 1023) + roff_;                                             \
              SA[r] = make_float4(0.f, 0.f, 0.f, 0.f);                                \
              if ((unsigned)s < 1024u)                                                \
                  SA[r] = *(const float4*)&A[((size_t)(n & ~1023) + s) * BDIM + ko_ + (v & 7) * 4]; } \
          { int row = tid >> 3;                                                       \
            _Pragma("unroll")                                                         \
            for (int m = 0; m < 2; m++)                                               \
                SB[m] = *(const uint4*)&Wt[((size_t)(m * 3 + tap_) * BDIM + c0 + row) * BDIM + ko_ + (tid & 7) * 4]; } }

    #define CQ_STS(SA, SB, ST)                                                        \
        { _Pragma("unroll")                                                           \
          for (int r = 0; r < 4; r++) {                                               \
              int v = tid + 256 * r;                                                  \
              int row = v >> 3, kc4 = v & 7;                                          \
              int ks = kc4 >> 1, half = kc4 & 1, rb = row >> 4, alq = row & 7, r8 = (row >> 3) & 1; \
              int comp = r8 + 2 * half;                                               \
              uint32_t* base = (uint32_t*)&Af[ST][rb][ks][0];                         \
              uint32_t vals[4] = {f2tf(SA[r].x), f2tf(SA[r].y), f2tf(SA[r].z), f2tf(SA[r].w)}; \
              _Pragma("unroll")                                                       \
              for (int e = 0; e < 4; e++) base[(((alq * 4 + e) ^ ks) << 2) + comp] = vals[e]; } \
          { int row = tid >> 3, kc4 = tid & 7;                                        \
            int ks = kc4 >> 1, half = kc4 & 1, nb = row >> 3, blq = row & 7;          \
            _Pragma("unroll")                                                         \
            for (int m = 0; m < 2; m++) {                                             \
                uint32_t* base = (uint32_t*)&Bf[ST][m][nb][ks][0];                    \
                uint32_t vals[4] = {SB[m].x, SB[m].y, SB[m].z, SB[m].w};              \
                _Pragma("unroll")                                                     \
                for (int e = 0; e < 4; e++) base[(((blq * 4 + e) ^ ks) << 1) + half] = vals[e]; } } }

    #define CQ_COMP(ST)                                                               \
        { _Pragma("unroll")                                                           \
          for (int ks = 0; ks < 4; ks++) {                                            \
              uint4 a = Af[ST][warp][ks][lane ^ ks];                                  \
              uint32_t aa[4] = {a.x, a.y, a.z, a.w};                                  \
              _Pragma("unroll")                                                       \
              for (int m = 0; m < 2; m++)                                             \
                  _Pragma("unroll")                                                   \
                  for (int ni = 0; ni < 4; ni++) {                                    \
                      uint2 b = Bf[ST][m][ni][ks][lane ^ ks];                         \
                      uint32_t bb[2] = {b.x, b.y};                                    \
                      mma_tf32(acc[m][ni], aa, bb); } } }

    CQ_LDG(sa0, sb0, 0)
    CQ_LDG(sa1, sb1, 1)
    CQ_STS(sa0, sb0, 0)
    __syncthreads();

    for (int t = 0; t < NST; t += 2) {
        if (t + 2 < NST) CQ_LDG(sa0, sb0, t + 2)
        CQ_COMP(0)
        CQ_STS(sa1, sb1, 1)
        __syncthreads();

        if (t + 3 < NST) CQ_LDG(sa1, sb1, t + 3)
        CQ_COMP(1)
        if (t + 2 < NST) CQ_STS(sa0, sb0, 0)
        __syncthreads();
    }

    #undef CQ_LDG
    #undef CQ_STS
    #undef CQ_COMP

    // Epilogue -> [B,H,S,64]
    #pragma unroll
    for (int m = 0; m < 2; m++) {
        float* outp = m ? ko : qo;
        const float* bp = m ? bk : bq;
        #pragma unroll
        for (int ni = 0; ni < 4; ni++) {
            int col = c0 + ni * 8 + 2 * lr;
            float bv0 = bp[col], bv1 = bp[col + 1];
            int hh = col >> 6, dd = col & 63;
            #pragma unroll
            for (int h = 0; h < 2; h++) {
                int n = n0 + warp * 16 + lq + h * 8;
                int b = n >> 10, s = n & 1023;
                float2 o2 = make_float2(acc[m][ni][2 * h] + bv0, acc[m][ni][2 * h + 1] + bv1);
                *(float2*)&outp[(((size_t)(b * NHEADS + hh)) * SDIM + s) * HD + dd] = o2;
            }
        }
    }
}

// ---------------------------------------------------------------------------
// tf32 tensor-core flash attention v2: fragment-major K/V (uint2, XOR swizzle),
// P row-layout with XOR bank swizzle (no padding). smem = 48KB exactly.
// ---------------------------------------------------------------------------
__global__ __launch_bounds__(128) void attn_mma(const float* __restrict__ q,
                                                const float* __restrict__ k,
                                                const float* __restrict__ v,
                                                float* __restrict__ av) {
    const int s0 = blockIdx.x * 64;
    const int h  = blockIdx.y;
    const int b  = blockIdx.z;
    const float* qb = q + (size_t)(b * NHEADS + h) * SDIM * HD;
    const float* kb = k + (size_t)(b * NHEADS + h) * SDIM * HD;
    const float* vb = v + (size_t)(b * NHEADS + h) * HD * SDIM;

    __shared__ uint2 Kf[8][8][32];   // [ni][ks][lane^ks] 16KB
    __shared__ uint2 Vf[8][8][32];   // 16KB
    __shared__ uint32_t Ps[64][64];  // row-swizzled, 16KB

    const int tid  = threadIdx.x;
    const int lane = tid & 31;
    const int warp = tid >> 5;
    const int lq = lane >> 2;
    const int lr = lane & 3;

    // Fill helper: element (row, col4) of a [64 x 64] tile, 4 consecutive cols.
    // frag: ni=row>>3, lqv=row&7, ks=col4>>3, half=(col4>>2)&1, j=0..3
    // store idx lane' = (lqv*4+j) ^ ks, component half.
    #define FRAG_STS(DST, ROW, COL4, VV)                                              \
        { int ni_ = (ROW) >> 3, lqv_ = (ROW) & 7;                                     \
          int ks_ = (COL4) >> 3, half_ = ((COL4) >> 2) & 1;                           \
          uint32_t* base_ = (uint32_t*)&DST[ni_][ks_][0];                             \
          uint32_t vl_[4] = {f2tf(VV.x), f2tf(VV.y), f2tf(VV.z), f2tf(VV.w)};         \
          _Pragma("unroll")                                                           \
          for (int j = 0; j < 4; j++)                                                 \
              base_[(((lqv_ * 4 + j) ^ ks_) << 1) + half_] = vl_[j]; }

    // Stage Q (scaled) into Kf, pull A-fragments
    #pragma unroll
    for (int r = 0; r < 8; r++) {
        int vdx = tid + 128 * r;
        int row = vdx >> 4, col = (vdx & 15) * 4;
        float4 x = *(const float4*)&qb[(size_t)(s0 + row) * HD + col];
        x.x *= 0.015625f; x.y *= 0.015625f; x.z *= 0.015625f; x.w *= 0.015625f;
        FRAG_STS(Kf, row, col, x)
    }
    __syncthreads();
    uint32_t qf[8][4];
    #pragma unroll
    for (int ks = 0; ks < 8; ks++) {
        uint2 a0 = Kf[warp * 2][ks][lane ^ ks];
        uint2 a1 = Kf[warp * 2 + 1][ks][lane ^ ks];
        qf[ks][0] = a0.x; qf[ks][1] = a1.x; qf[ks][2] = a0.y; qf[ks][3] = a1.y;
    }
    __syncthreads();

    float m0v = -1e30f, m1v = -1e30f, l0 = 0.f, l1 = 0.f;
    float o[8][4];
    #pragma unroll
    for (int ni = 0; ni < 8; ni++)
        #pragma unroll
        for (int c = 0; c < 4; c++) o[ni][c] = 0.f;

    const int prow = warp * 16 + lq;
    const int psw  = lq << 3;       // row-dependent column XOR for Ps

    for (int t0 = 0; t0 < SDIM; t0 += 64) {
        // K tile [t][d] and V tile [d][t] -> fragment-major
        #pragma unroll
        for (int r = 0; r < 8; r++) {
            int vdx = tid + 128 * r;
            int row = vdx >> 4, col = (vdx & 15) * 4;
            float4 x = *(const float4*)&kb[(size_t)(t0 + row) * HD + col];
            FRAG_STS(Kf, row, col, x)
            float4 y = *(const float4*)&vb[(size_t)row * SDIM + t0 + col];
            FRAG_STS(Vf, row, col, y)
        }
        __syncthreads();

        // scores: 16 rows x 64 t
        float sc[8][4];
        #pragma unroll
        for (int ni = 0; ni < 8; ni++)
            #pragma unroll
            for (int c = 0; c < 4; c++) sc[ni][c] = 0.f;
        #pragma unroll
        for (int ks = 0; ks < 8; ks++) {
            #pragma unroll
            for (int ni = 0; ni < 8; ni++) {
                uint2 bfr = Kf[ni][ks][lane ^ ks];
                uint32_t bb[2] = {bfr.x, bfr.y};
                mma_tf32(sc[ni], qf[ks], bb);
            }
        }

        // Online softmax
        float rm0 = -1e30f, rm1 = -1e30f;
        #pragma unroll
        for (int ni = 0; ni < 8; ni++) {
            rm0 = fmaxf(rm0, fmaxf(sc[ni][0], sc[ni][1]));
            rm1 = fmaxf(rm1, fmaxf(sc[ni][2], sc[ni][3]));
        }
        rm0 = fmaxf(rm0, __shfl_xor_sync(0xffffffffu, rm0, 1));
        rm0 = fmaxf(rm0, __shfl_xor_sync(0xffffffffu, rm0, 2));
        rm1 = fmaxf(rm1, __shfl_xor_sync(0xffffffffu, rm1, 1));
        rm1 = fmaxf(rm1, __shfl_xor_sync(0xffffffffu, rm1, 2));
        float mn0 = fmaxf(m0v, rm0), mn1 = fmaxf(m1v, rm1);
        float cr0 = __expf(m0v - mn0), cr1 = __expf(m1v - mn1);
        float rs0 = 0.f, rs1 = 0.f;
        #pragma unroll
        for (int ni = 0; ni < 8; ni++) {
            float p0 = __expf(sc[ni][0] - mn0);
            float p1 = __expf(sc[ni][1] - mn0);
            float p2 = __expf(sc[ni][2] - mn1);
            float p3 = __expf(sc[ni][3] - mn1);
            int col = ni * 8 + 2 * lr;
            Ps[prow][(col) ^ psw]         = f2tf(p0);
            Ps[prow][(col + 1) ^ psw]     = f2tf(p1);
            Ps[prow + 8][(col) ^ psw]     = f2tf(p2);
            Ps[prow + 8][(col + 1) ^ psw] = f2tf(p3);
            rs0 += p0 + p1;
            rs1 += p2 + p3;
        }
        rs0 += __shfl_xor_sync(0xffffffffu, rs0, 1);
        rs0 += __shfl_xor_sync(0xffffffffu, rs0, 2);
        rs1 += __shfl_xor_sync(0xffffffffu, rs1, 1);
        rs1 += __shfl_xor_sync(0xffffffffu, rs1, 2);
        l0 = l0 * cr0 + rs0;
        l1 = l1 * cr1 + rs1;
        m0v = mn0; m1v = mn1;
        #pragma unroll
        for (int ni = 0; ni < 8; ni++) {
            o[ni][0] *= cr0; o[ni][1] *= cr0;
            o[ni][2] *= cr1; o[ni][3] *= cr1;
        }
        __syncwarp();   // warp reads only its own P rows

        // PV: O[16 s][64 d] += P[16 s][64 t] * V[d][t]
        #pragma unroll
        for (int ks = 0; ks < 8; ks++) {
            int k8 = ks * 8 + lr;
            uint32_t a[4];
            a[0] = Ps[prow][k8 ^ psw];
            a[1] = Ps[prow + 8][k8 ^ psw];
            a[2] = Ps[prow][(k8 + 4) ^ psw];
            a[3] = Ps[prow + 8][(k8 + 4) ^ psw];
            #pragma unroll
            for (int ni = 0; ni < 8; ni++) {
                uint2 bfr = Vf[ni][ks][lane ^ ks];
                uint32_t bb[2] = {bfr.x, bfr.y};
                mma_tf32(o[ni], a, bb);
            }
        }
        __syncthreads();
    }
    #undef FRAG_STS

    float inv0 = 1.0f / l0, inv1 = 1.0f / l1;
    const int rbase = s0 + warp * 16;
    #pragma unroll
    for (int ni = 0; ni < 8; ni++) {
        int col = h * HD + ni * 8 + 2 * lr;
        float2 a = make_float2(o[ni][0] * inv0, o[ni][1] * inv0);
        float2 c = make_float2(o[ni][2] * inv1, o[ni][3] * inv1);
        *(float2*)&av[(size_t)(b * SDIM + rbase + lq) * BDIM + col]     = a;
        *(float2*)&av[(size_t)(b * SDIM + rbase + lq + 8) * BDIM + col] = c;
    }
}

// ---------------------------------------------------------------------------
// LayerNorm over last dim (512).
// ---------------------------------------------------------------------------
__global__ void ln_kernel(const float* __restrict__ in, const float* __restrict__ g,
                          const float* __restrict__ beta, float* __restrict__ out) {
    const int row = blockIdx.x;
    const float* x = in + (size_t)row * BDIM;
    const int tid = threadIdx.x;
    const int wid = tid >> 5, lane = tid & 31;

    float v0 = x[tid], v1 = x[tid + 256];
    __shared__ float red[8];

    float s = v0 + v1;
    #pragma unroll
    for (int off = 16; off > 0; off >>= 1)
        s += __shfl_xor_sync(0xffffffffu, s, off);
    if (lane == 0) red[wid] = s;
    __syncthreads();
    float tot = 0.f;
    #pragma unroll
    for (int i = 0; i < 8; i++) tot += red[i];
    float mu = tot * (1.0f / 512.0f);
    __syncthreads();

    float d0 = v0 - mu, d1 = v1 - mu;
    float sq = d0 * d0 + d1 * d1;
    #pragma unroll
    for (int off = 16; off > 0; off >>= 1)
        sq += __shfl_xor_sync(0xffffffffu, sq, off);
    if (lane == 0) red[wid] = sq;
    __syncthreads();
    float tot2 = 0.f;
    #pragma unroll
    for (int i = 0; i < 8; i++) tot2 += red[i];
    float rstd = rsqrtf(tot2 * (1.0f / 512.0f) + 1e-5f);

    out[(size_t)row * BDIM + tid]       = d0 * rstd * g[tid]       + beta[tid];
    out[(size_t)row * BDIM + tid + 256] = d1 * rstd * g[tid + 256] + beta[tid + 256];
}

// ---------------------------------------------------------------------------
extern "C" void kernel_launch(void* const* d_in, const int* in_sizes, int n_in,
                              void* d_out, int out_size) {
    const float* src = (const float*)d_in[0];
    const float* Wq  = (const float*)d_in[1];
    const float* bq  = (const float*)d_in[2];
    const float* Wk  = (const float*)d_in[3];
    const float* bk  = (const float*)d_in[4];
    const float* Wv  = (const float*)d_in[5];
    const float* bv  = (const float*)d_in[6];
    const float* Wo  = (const float*)d_in[7];
    const float* bo  = (const float*)d_in[8];
    const float* W1  = (const float*)d_in[9];
    const float* b1  = (const float*)d_in[10];
    const float* W2  = (const float*)d_in[11];
    const float* b2  = (const float*)d_in[12];
    const float* g1  = (const float*)d_in[13];
    const float* be1 = (const float*)d_in[14];
    const float* g2  = (const float*)d_in[15];
    const float* be2 = (const float*)d_in[16];
    float* out = (float*)d_out;

    float *q, *k, *v, *av, *t1, *x1, *ff;
    uint32_t *wt, *wc;
    cudaGetSymbolAddress((void**)&q,  g_q);
    cudaGetSymbolAddress((void**)&k,  g_k);
    cudaGetSymbolAddress((void**)&v,  g_v);
    cudaGetSymbolAddress((void**)&av, g_av);
    cudaGetSymbolAddress((void**)&t1, g_t1);
    cudaGetSymbolAddress((void**)&x1, g_x1);
    cudaGetSymbolAddress((void**)&ff, g_ff);
    cudaGetSymbolAddress((void**)&wt, g_wt);
    cudaGetSymbolAddress((void**)&wc, g_wc);

    // Prep (single launch)
    wprep_kernel<<<(WPREP_TOTAL + 255) / 256, 256>>>(Wq, Wk, Wv, Wo, W1, W2, wt, wc);

    // Convs
    convqk<<<dim3(NTOK / 128, BDIM / 32), 256>>>(src, wt, bq, bk, q, k);
    gemm2<3><<<dim3(NTOK / 128, BDIM / 64), 256>>>(src, wc + WC_WV, bv, nullptr, v, BDIM, BDIM);

    attn_mma<<<dim3(SDIM / 64, NHEADS, BATCH), 128>>>(q, k, v, av);

    gemm2<0><<<dim3(NTOK / 128, BDIM / 64), 256>>>(av, wc + WC_WO, bo, src, t1, BDIM, BDIM);
    ln_kernel<<<NTOK, 256>>>(t1, g1, be1, x1);

    gemm2<1><<<dim3(NTOK / 128, DFF / 64), 256>>>(x1, wc + WC_W1, b1, nullptr, ff, DFF, BDIM);
    gemm2<2><<<dim3(NTOK / 128, BDIM / 64), 256>>>(ff, wc + WC_W2, b2, x1, t1, BDIM, DFF);
    ln_kernel<<<NTOK, 256>>>(t1, g2, be2, out);
}

// round 6
// speedup vs baseline: 1.0289x; 1.0289x over previous
#include <cuda_runtime.h>
#include <math.h>
#include <stdint.h>

#define BDIM   512
#define SDIM   1024
#define BATCH  8
#define NHEADS 8
#define HD     64
#define DFF    2048
#define NTOK   (BATCH * SDIM)   // 8192

// Scratch
__device__ float    g_q [BATCH * BDIM * SDIM];   // [B,H,S,64]
__device__ float    g_k [BATCH * BDIM * SDIM];   // [B,H,S,64]
__device__ float    g_v [BATCH * BDIM * SDIM];   // [B,D,S]
__device__ float    g_av[NTOK * BDIM];
__device__ float    g_t1[NTOK * BDIM];
__device__ float    g_x1[NTOK * BDIM];
__device__ float    g_ff[NTOK * DFF];
__device__ uint32_t g_wt[2 * 3 * BDIM * BDIM];   // tf32 Wq/Wk: [mat][tap][co][ci]
__device__ uint32_t g_wc[2 * BDIM * BDIM + 2 * DFF * BDIM];  // tf32 Wv,Wo,W1,W2

#define WC_WV 0
#define WC_WO (BDIM * BDIM)
#define WC_W1 (2 * BDIM * BDIM)
#define WC_W2 (2 * BDIM * BDIM + DFF * BDIM)

__device__ __forceinline__ uint32_t f2tf(float f) {
    uint32_t r;
    asm("cvt.rna.tf32.f32 %0, %1;" : "=r"(r) : "f"(f));
    return r;
}

__device__ __forceinline__ void mma_tf32(float c[4], const uint32_t a[4], const uint32_t b[2]) {
    asm volatile(
        "mma.sync.aligned.m16n8k8.row.col.f32.tf32.tf32.f32 "
        "{%0,%1,%2,%3}, {%4,%5,%6,%7}, {%8,%9}, {%0,%1,%2,%3};"
        : "+f"(c[0]), "+f"(c[1]), "+f"(c[2]), "+f"(c[3])
        : "r"(a[0]), "r"(a[1]), "r"(a[2]), "r"(a[3]), "r"(b[0]), "r"(b[1]));
}

// ---------------------------------------------------------------------------
// Merged prep: all weight conversions in one launch.
// ---------------------------------------------------------------------------
#define WTN (2 * 3 * BDIM * BDIM)
__global__ void wprep_kernel(const float* __restrict__ Wq, const float* __restrict__ Wk,
                             const float* __restrict__ Wv, const float* __restrict__ Wo,
                             const float* __restrict__ W1, const float* __restrict__ W2,
                             uint32_t* __restrict__ wt, uint32_t* __restrict__ wc) {
    int e = blockIdx.x * 256 + threadIdx.x;
    if (e < WTN) {
        int m  = (e >= 3 * BDIM * BDIM);
        int e2 = e - m * 3 * BDIM * BDIM;
        int t  = e2 >> 18;
        int co = (e2 >> 9) & 511;
        int ci = e2 & 511;
        const float* src = m ? Wk : Wq;
        wt[e] = f2tf(src[(size_t)co * 1536 + ci * 3 + t]);
        return;
    }
    int f = e - WTN;
    if (f < BDIM * BDIM)            { wc[WC_WV + f] = f2tf(Wv[f]); return; }
    f -= BDIM * BDIM;
    if (f < BDIM * BDIM)            { wc[WC_WO + f] = f2tf(Wo[f]); return; }
    f -= BDIM * BDIM;
    if (f < DFF * BDIM)             { wc[WC_W1 + f] = f2tf(W1[f]); return; }
    f -= DFF * BDIM;
    if (f < DFF * BDIM)             { wc[WC_W2 + f] = f2tf(W2[f]); return; }
}
#define WPREP_TOTAL (WTN + 2 * BDIM * BDIM + 2 * DFF * BDIM)

// ===========================================================================
// GEMM core: block 128(n) x 64(m), 8 warps (32x32), KT=32, fragment-major
// XOR-swizzled smem, double-buffered smem + double register staging
// (LDG two stages ahead). NO min-blocks clamp (avoid spills).
// MODE 0: +res | 1: relu | 2: +res | 3: V-conv layout [B,D,S] (bias only)
// ===========================================================================
template <int MODE>
__global__ __launch_bounds__(256) void gemm2(const float* __restrict__ A,
                                             const uint32_t* __restrict__ W,
                                             const float* __restrict__ bias,
                                             const float* __restrict__ res,
                                             float* __restrict__ out, int M, int K) {
    __shared__ uint4 Af[2][8][4][32];   // 32KB
    __shared__ uint2 Bf[2][8][4][32];   // 16KB

    const int n0 = blockIdx.x * 128;
    const int m0 = blockIdx.y * 64;
    const int tid = threadIdx.x, lane = tid & 31, warp = tid >> 5;
    const int lq = lane >> 2, lr = lane & 3;
    const int wiB = (warp >> 1) * 2;
    const int wjB = (warp & 1) * 4;
    const int nk = K >> 5;   // even (>=16)

    float acc[2][4][4];
    #pragma unroll
    for (int mi = 0; mi < 2; mi++)
        #pragma unroll
        for (int ni = 0; ni < 4; ni++)
            #pragma unroll
            for (int c = 0; c < 4; c++) acc[mi][ni][c] = 0.f;

    float4 sa0[4], sa1[4];
    uint4  sb0[2], sb1[2];

    #define G2_LDG(SA, SB, KO)                                                        \
        { int ko_ = (KO);                                                             \
          _Pragma("unroll")                                                           \
          for (int r = 0; r < 4; r++) {                                               \
              int v = tid + 256 * r;                                                  \
              SA[r] = *(const float4*)&A[(size_t)(n0 + (v >> 3)) * K + ko_ + (v & 7) * 4]; } \
          _Pragma("unroll")                                                           \
          for (int r = 0; r < 2; r++) {                                               \
              int v = tid + 256 * r;                                                  \
              SB[r] = *(const uint4*)&W[(size_t)(m0 + (v >> 3)) * K + ko_ + (v & 7) * 4]; } }

    #define G2_STS(SA, SB, ST)                                                        \
        { _Pragma("unroll")                                                           \
          for (int r = 0; r < 4; r++) {                                               \
              int v = tid + 256 * r;                                                  \
              int row = v >> 3, kc4 = v & 7;                                          \
              int ks = kc4 >> 1, half = kc4 & 1, rb = row >> 4, alq = row & 7, r8 = (row >> 3) & 1; \
              int comp = r8 + 2 * half;                                               \
              uint32_t* base = (uint32_t*)&Af[ST][rb][ks][0];                         \
              uint32_t vals[4] = {f2tf(SA[r].x), f2tf(SA[r].y), f2tf(SA[r].z), f2tf(SA[r].w)}; \
              _Pragma("unroll")                                                       \
              for (int e = 0; e < 4; e++) base[(((alq * 4 + e) ^ ks) << 2) + comp] = vals[e]; } \
          _Pragma("unroll")                                                           \
          for (int r = 0; r < 2; r++) {                                               \
              int v = tid + 256 * r;                                                  \
              int row = v >> 3, kc4 = v & 7;                                          \
              int ks = kc4 >> 1, half = kc4 & 1, nb = row >> 3, blq = row & 7;        \
              uint32_t* base = (uint32_t*)&Bf[ST][nb][ks][0];                         \
              uint32_t vals[4] = {SB[r].x, SB[r].y, SB[r].z, SB[r].w};                \
              _Pragma("unroll")                                                       \
              for (int e = 0; e < 4; e++) base[(((blq * 4 + e) ^ ks) << 1) + half] = vals[e]; } }

    #define G2_COMP(ST)                                                               \
        { _Pragma("unroll")                                                           \
          for (int ks = 0; ks < 4; ks++) {                                            \
              uint4 a0 = Af[ST][wiB][ks][lane ^ ks];                                  \
              uint4 a1 = Af[ST][wiB + 1][ks][lane ^ ks];                              \
              uint32_t aa0[4] = {a0.x, a0.y, a0.z, a0.w};                             \
              uint32_t aa1[4] = {a1.x, a1.y, a1.z, a1.w};                             \
              _Pragma("unroll")                                                       \
              for (int ni = 0; ni < 4; ni++) {                                        \
                  uint2 b = Bf[ST][wjB + ni][ks][lane ^ ks];                          \
                  uint32_t bb[2] = {b.x, b.y};                                        \
                  mma_tf32(acc[0][ni], aa0, bb);                                      \
                  mma_tf32(acc[1][ni], aa1, bb); } } }

    G2_LDG(sa0, sb0, 0)
    G2_LDG(sa1, sb1, 32)
    G2_STS(sa0, sb0, 0)
    __syncthreads();

    for (int kb = 0; kb < nk; kb += 2) {
        if (kb + 2 < nk) G2_LDG(sa0, sb0, (kb + 2) << 5)
        G2_COMP(0)
        G2_STS(sa1, sb1, 1)
        __syncthreads();

        if (kb + 3 < nk) G2_LDG(sa1, sb1, (kb + 3) << 5)
        G2_COMP(1)
        if (kb + 2 < nk) G2_STS(sa0, sb0, 0)
        __syncthreads();
    }

    #undef G2_LDG
    #undef G2_STS
    #undef G2_COMP

    #pragma unroll
    for (int mi = 0; mi < 2; mi++) {
        #pragma unroll
        for (int ni = 0; ni < 4; ni++) {
            int col = m0 + (warp & 1) * 32 + ni * 8 + 2 * lr;
            float bv0 = bias[col], bv1 = bias[col + 1];
            #pragma unroll
            for (int h = 0; h < 2; h++) {
                int n = n0 + (warp >> 1) * 32 + mi * 16 + lq + h * 8;
                float x0 = acc[mi][ni][2 * h] + bv0;
                float x1 = acc[mi][ni][2 * h + 1] + bv1;
                if (MODE == 1) { x0 = fmaxf(x0, 0.f); x1 = fmaxf(x1, 0.f); }
                if (MODE == 0 || MODE == 2) {
                    x0 += res[(size_t)n * M + col];
                    x1 += res[(size_t)n * M + col + 1];
                }
                if (MODE == 3) {
                    int b = n >> 10, s = n & 1023;
                    out[((size_t)(b * BDIM + col)) * SDIM + s]     = x0;
                    out[((size_t)(b * BDIM + col + 1)) * SDIM + s] = x1;
                } else {
                    *(float2*)&out[(size_t)n * M + col] = make_float2(x0, x1);
                }
            }
        }
    }
}

// ===========================================================================
// Fused Q+K conv: block 128(tok) x 32(co) x 2 mats, double register staging,
// no min-blocks clamp.
// ===========================================================================
__global__ __launch_bounds__(256) void convqk(const float* __restrict__ A,
                                              const uint32_t* __restrict__ Wt,
                                              const float* __restrict__ bq,
                                              const float* __restrict__ bk,
                                              float* __restrict__ qo,
                                              float* __restrict__ ko) {
    __shared__ uint4 Af[2][8][4][32];        // 32KB
    __shared__ uint2 Bf[2][2][4][4][32];     // 16KB

    const int n0 = blockIdx.x * 128;
    const int c0 = blockIdx.y * 32;
    const int tid = threadIdx.x, lane = tid & 31, warp = tid >> 5;
    const int lq = lane >> 2, lr = lane & 3;
    const int NST = 48;  // 3 taps x 16 kb

    float acc[2][4][4];
    #pragma unroll
    for (int m = 0; m < 2; m++)
        #pragma unroll
        for (int ni = 0; ni < 4; ni++)
            #pragma unroll
            for (int c = 0; c < 4; c++) acc[m][ni][c] = 0.f;

    float4 sa0[4], sa1[4];
    uint4  sb0[2], sb1[2];

    #define CQ_LDG(SA, SB, T)                                                         \
        { int t_ = (T);                                                               \
          int tap_ = t_ >> 4, ko_ = (t_ & 15) << 5, roff_ = tap_ - 1;                 \
          _Pragma("unroll")                                                           \
          for (int r = 0; r < 4; r++) {                                               \
              int v = tid + 256 * r;                                                  \
              int row = v >> 3;                                                       \
              int n = n0 + row;                                                       \
              int s = (n & 1023) + roff_;                                             \
              SA[r] = make_float4(0.f, 0.f, 0.f, 0.f);                                \
              if ((unsigned)s < 1024u)                                                \
                  SA[r] = *(const float4*)&A[((size_t)(n & ~1023) + s) * BDIM + ko_ + (v & 7) * 4]; } \
          { int row = tid >> 3;                                                       \
            _Pragma("unroll")                                                         \
            for (int m = 0; m < 2; m++)                                               \
                SB[m] = *(const uint4*)&Wt[((size_t)(m * 3 + tap_) * BDIM + c0 + row) * BDIM + ko_ + (tid & 7) * 4]; } }

    #define CQ_STS(SA, SB, ST)                                                        \
        { _Pragma("unroll")                                                           \
          for (int r = 0; r < 4; r++) {                                               \
              int v = tid + 256 * r;                                                  \
              int row = v >> 3, kc4 = v & 7;                                          \
              int ks = kc4 >> 1, half = kc4 & 1, rb = row >> 4, alq = row & 7, r8 = (row >> 3) & 1; \
              int comp = r8 + 2 * half;                                               \
              uint32_t* base = (uint32_t*)&Af[ST][rb][ks][0];                         \
              uint32_t vals[4] = {f2tf(SA[r].x), f2tf(SA[r].y), f2tf(SA[r].z), f2tf(SA[r].w)}; \
              _Pragma("unroll")                                                       \
              for (int e = 0; e < 4; e++) base[(((alq * 4 + e) ^ ks) << 2) + comp] = vals[e]; } \
          { int row = tid >> 3, kc4 = tid & 7;                                        \
            int ks = kc4 >> 1, half = kc4 & 1, nb = row >> 3, blq = row & 7;          \
            _Pragma("unroll")                                                         \
            for (int m = 0; m < 2; m++) {                                             \
                uint32_t* base = (uint32_t*)&Bf[ST][m][nb][ks][0];                    \
                uint32_t vals[4] = {SB[m].x, SB[m].y, SB[m].z, SB[m].w};              \
                _Pragma("unroll")                                                     \
                for (int e = 0; e < 4; e++) base[(((blq * 4 + e) ^ ks) << 1) + half] = vals[e]; } } }

    #define CQ_COMP(ST)                                                               \
        { _Pragma("unroll")                                                           \
          for (int ks = 0; ks < 4; ks++) {                                            \
              uint4 a = Af[ST][warp][ks][lane ^ ks];                                  \
              uint32_t aa[4] = {a.x, a.y, a.z, a.w};                                  \
              _Pragma("unroll")                                                       \
              for (int m = 0; m < 2; m++)                                             \
                  _Pragma("unroll")                                                   \
                  for (int ni = 0; ni < 4; ni++) {                                    \
                      uint2 b = Bf[ST][m][ni][ks][lane ^ ks];                         \
                      uint32_t bb[2] = {b.x, b.y};                                    \
                      mma_tf32(acc[m][ni], aa, bb); } } }

    CQ_LDG(sa0, sb0, 0)
    CQ_LDG(sa1, sb1, 1)
    CQ_STS(sa0, sb0, 0)
    __syncthreads();

    for (int t = 0; t < NST; t += 2) {
        if (t + 2 < NST) CQ_LDG(sa0, sb0, t + 2)
        CQ_COMP(0)
        CQ_STS(sa1, sb1, 1)
        __syncthreads();

        if (t + 3 < NST) CQ_LDG(sa1, sb1, t + 3)
        CQ_COMP(1)
        if (t + 2 < NST) CQ_STS(sa0, sb0, 0)
        __syncthreads();
    }

    #undef CQ_LDG
    #undef CQ_STS
    #undef CQ_COMP

    #pragma unroll
    for (int m = 0; m < 2; m++) {
        float* outp = m ? ko : qo;
        const float* bp = m ? bk : bq;
        #pragma unroll
        for (int ni = 0; ni < 4; ni++) {
            int col = c0 + ni * 8 + 2 * lr;
            float bv0 = bp[col], bv1 = bp[col + 1];
            int hh = col >> 6, dd = col & 63;
            #pragma unroll
            for (int h = 0; h < 2; h++) {
                int n = n0 + warp * 16 + lq + h * 8;
                int b = n >> 10, s = n & 1023;
                float2 o2 = make_float2(acc[m][ni][2 * h] + bv0, acc[m][ni][2 * h + 1] + bv1);
                *(float2*)&outp[(((size_t)(b * NHEADS + hh)) * SDIM + s) * HD + dd] = o2;
            }
        }
    }
}

// ---------------------------------------------------------------------------
// tf32 tensor-core flash attention (R4 version — known good, ~150us).
// ---------------------------------------------------------------------------
__global__ __launch_bounds__(128) void attn_mma(const float* __restrict__ q,
                                                const float* __restrict__ k,
                                                const float* __restrict__ v,
                                                float* __restrict__ av) {
    const int s0 = blockIdx.x * 64;
    const int h  = blockIdx.y;
    const int b  = blockIdx.z;
    const float* qb = q + (size_t)(b * NHEADS + h) * SDIM * HD;
    const float* kb = k + (size_t)(b * NHEADS + h) * SDIM * HD;
    const float* vb = v + (size_t)(b * NHEADS + h) * HD * SDIM;

    __shared__ uint32_t Ks[64][68];
    __shared__ uint32_t Vs[64][68];

    const int tid  = threadIdx.x;
    const int lane = tid & 31;
    const int warp = tid >> 5;
    const int lq = lane >> 2;
    const int lr = lane & 3;

    #pragma unroll
    for (int r = 0; r < 8; r++) {
        int vdx = tid + 128 * r;
        int row = vdx >> 4, col = (vdx & 15) * 4;
        float4 x = *(const float4*)&qb[(size_t)(s0 + row) * HD + col];
        Ks[row][col + 0] = f2tf(x.x * 0.015625f);
        Ks[row][col + 1] = f2tf(x.y * 0.015625f);
        Ks[row][col + 2] = f2tf(x.z * 0.015625f);
        Ks[row][col + 3] = f2tf(x.w * 0.015625f);
    }
    __syncthreads();
    uint32_t qf[8][4];
    #pragma unroll
    for (int ks = 0; ks < 8; ks++) {
        int k8 = ks * 8 + lr;
        int r0 = warp * 16 + lq;
        qf[ks][0] = Ks[r0][k8];
        qf[ks][1] = Ks[r0 + 8][k8];
        qf[ks][2] = Ks[r0][k8 + 4];
        qf[ks][3] = Ks[r0 + 8][k8 + 4];
    }
    __syncthreads();

    float m0v = -1e30f, m1v = -1e30f, l0 = 0.f, l1 = 0.f;
    float o[8][4];
    #pragma unroll
    for (int ni = 0; ni < 8; ni++)
        #pragma unroll
        for (int c = 0; c < 4; c++) o[ni][c] = 0.f;

    for (int t0 = 0; t0 < SDIM; t0 += 64) {
        #pragma unroll
        for (int r = 0; r < 8; r++) {
            int vdx = tid + 128 * r;
            int row = vdx >> 4, col = (vdx & 15) * 4;
            float4 x = *(const float4*)&kb[(size_t)(t0 + row) * HD + col];
            Ks[row][col + 0] = f2tf(x.x);
            Ks[row][col + 1] = f2tf(x.y);
            Ks[row][col + 2] = f2tf(x.z);
            Ks[row][col + 3] = f2tf(x.w);
            float4 y = *(const float4*)&vb[(size_t)row * SDIM + t0 + col];
            Vs[row][col + 0] = f2tf(y.x);
            Vs[row][col + 1] = f2tf(y.y);
            Vs[row][col + 2] = f2tf(y.z);
            Vs[row][col + 3] = f2tf(y.w);
        }
        __syncthreads();

        float sc[8][4];
        #pragma unroll
        for (int ni = 0; ni < 8; ni++)
            #pragma unroll
            for (int c = 0; c < 4; c++) sc[ni][c] = 0.f;
        #pragma unroll
        for (int ks = 0; ks < 8; ks++) {
            int k8 = ks * 8 + lr;
            #pragma unroll
            for (int ni = 0; ni < 8; ni++) {
                uint32_t bb[2];
                bb[0] = Ks[ni * 8 + lq][k8];
                bb[1] = Ks[ni * 8 + lq][k8 + 4];
                mma_tf32(sc[ni], qf[ks], bb);
            }
        }
        __syncthreads();

        float rm0 = -1e30f, rm1 = -1e30f;
        #pragma unroll
        for (int ni = 0; ni < 8; ni++) {
            rm0 = fmaxf(rm0, fmaxf(sc[ni][0], sc[ni][1]));
            rm1 = fmaxf(rm1, fmaxf(sc[ni][2], sc[ni][3]));
        }
        rm0 = fmaxf(rm0, __shfl_xor_sync(0xffffffffu, rm0, 1));
        rm0 = fmaxf(rm0, __shfl_xor_sync(0xffffffffu, rm0, 2));
        rm1 = fmaxf(rm1, __shfl_xor_sync(0xffffffffu, rm1, 1));
        rm1 = fmaxf(rm1, __shfl_xor_sync(0xffffffffu, rm1, 2));
        float mn0 = fmaxf(m0v, rm0), mn1 = fmaxf(m1v, rm1);
        float cr0 = __expf(m0v - mn0), cr1 = __expf(m1v - mn1);
        float rs0 = 0.f, rs1 = 0.f;
        const int prow = warp * 16 + lq;
        #pragma unroll
        for (int ni = 0; ni < 8; ni++) {
            float p0 = __expf(sc[ni][0] - mn0);
            float p1 = __expf(sc[ni][1] - mn0);
            float p2 = __expf(sc[ni][2] - mn1);
            float p3 = __expf(sc[ni][3] - mn1);
            int col = ni * 8 + 2 * lr;
            Ks[prow][col]         = f2tf(p0);
            Ks[prow][col + 1]     = f2tf(p1);
            Ks[prow + 8][col]     = f2tf(p2);
            Ks[prow + 8][col + 1] = f2tf(p3);
            rs0 += p0 + p1;
            rs1 += p2 + p3;
        }
        rs0 += __shfl_xor_sync(0xffffffffu, rs0, 1);
        rs0 += __shfl_xor_sync(0xffffffffu, rs0, 2);
        rs1 += __shfl_xor_sync(0xffffffffu, rs1, 1);
        rs1 += __shfl_xor_sync(0xffffffffu, rs1, 2);
        l0 = l0 * cr0 + rs0;
        l1 = l1 * cr1 + rs1;
        m0v = mn0; m1v = mn1;
        #pragma unroll
        for (int ni = 0; ni < 8; ni++) {
            o[ni][0] *= cr0; o[ni][1] *= cr0;
            o[ni][2] *= cr1; o[ni][3] *= cr1;
        }
        __syncwarp();

        #pragma unroll
        for (int ks = 0; ks < 8; ks++) {
            int k8 = ks * 8 + lr;
            uint32_t a[4];
            a[0] = Ks[prow][k8];
            a[1] = Ks[prow + 8][k8];
            a[2] = Ks[prow][k8 + 4];
            a[3] = Ks[prow + 8][k8 + 4];
            #pragma unroll
            for (int ni = 0; ni < 8; ni++) {
                uint32_t bb[2];
                bb[0] = Vs[ni * 8 + lq][k8];
                bb[1] = Vs[ni * 8 + lq][k8 + 4];
                mma_tf32(o[ni], a, bb);
            }
        }
        __syncthreads();
    }

    float inv0 = 1.0f / l0, inv1 = 1.0f / l1;
    const int rbase = s0 + warp * 16;
    #pragma unroll
    for (int ni = 0; ni < 8; ni++) {
        int col = h * HD + ni * 8 + 2 * lr;
        float2 a = make_float2(o[ni][0] * inv0, o[ni][1] * inv0);
        float2 c = make_float2(o[ni][2] * inv1, o[ni][3] * inv1);
        *(float2*)&av[(size_t)(b * SDIM + rbase + lq) * BDIM + col]     = a;
        *(float2*)&av[(size_t)(b * SDIM + rbase + lq + 8) * BDIM + col] = c;
    }
}

// ---------------------------------------------------------------------------
// LayerNorm over last dim (512).
// ---------------------------------------------------------------------------
__global__ void ln_kernel(const float* __restrict__ in, const float* __restrict__ g,
                          const float* __restrict__ beta, float* __restrict__ out) {
    const int row = blockIdx.x;
    const float* x = in + (size_t)row * BDIM;
    const int tid = threadIdx.x;
    const int wid = tid >> 5, lane = tid & 31;

    float v0 = x[tid], v1 = x[tid + 256];
    __shared__ float red[8];

    float s = v0 + v1;
    #pragma unroll
    for (int off = 16; off > 0; off >>= 1)
        s += __shfl_xor_sync(0xffffffffu, s, off);
    if (lane == 0) red[wid] = s;
    __syncthreads();
    float tot = 0.f;
    #pragma unroll
    for (int i = 0; i < 8; i++) tot += red[i];
    float mu = tot * (1.0f / 512.0f);
    __syncthreads();

    float d0 = v0 - mu, d1 = v1 - mu;
    float sq = d0 * d0 + d1 * d1;
    #pragma unroll
    for (int off = 16; off > 0; off >>= 1)
        sq += __shfl_xor_sync(0xffffffffu, sq, off);
    if (lane == 0) red[wid] = sq;
    __syncthreads();
    float tot2 = 0.f;
    #pragma unroll
    for (int i = 0; i < 8; i++) tot2 += red[i];
    float rstd = rsqrtf(tot2 * (1.0f / 512.0f) + 1e-5f);

    out[(size_t)row * BDIM + tid]       = d0 * rstd * g[tid]       + beta[tid];
    out[(size_t)row * BDIM + tid + 256] = d1 * rstd * g[tid + 256] + beta[tid + 256];
}

// ---------------------------------------------------------------------------
extern "C" void kernel_launch(void* const* d_in, const int* in_sizes, int n_in,
                              void* d_out, int out_size) {
    const float* src = (const float*)d_in[0];
    const float* Wq  = (const float*)d_in[1];
    const float* bq  = (const float*)d_in[2];
    const float* Wk  = (const float*)d_in[3];
    const float* bk  = (const float*)d_in[4];
    const float* Wv  = (const float*)d_in[5];
    const float* bv  = (const float*)d_in[6];
    const float* Wo  = (const float*)d_in[7];
    const float* bo  = (const float*)d_in[8];
    const float* W1  = (const float*)d_in[9];
    const float* b1  = (const float*)d_in[10];
    const float* W2  = (const float*)d_in[11];
    const float* b2  = (const float*)d_in[12];
    const float* g1  = (const float*)d_in[13];
    const float* be1 = (const float*)d_in[14];
    const float* g2  = (const float*)d_in[15];
    const float* be2 = (const float*)d_in[16];
    float* out = (float*)d_out;

    float *q, *k, *v, *av, *t1, *x1, *ff;
    uint32_t *wt, *wc;
    cudaGetSymbolAddress((void**)&q,  g_q);
    cudaGetSymbolAddress((void**)&k,  g_k);
    cudaGetSymbolAddress((void**)&v,  g_v);
    cudaGetSymbolAddress((void**)&av, g_av);
    cudaGetSymbolAddress((void**)&t1, g_t1);
    cudaGetSymbolAddress((void**)&x1, g_x1);
    cudaGetSymbolAddress((void**)&ff, g_ff);
    cudaGetSymbolAddress((void**)&wt, g_wt);
    cudaGetSymbolAddress((void**)&wc, g_wc);

    wprep_kernel<<<(WPREP_TOTAL + 255) / 256, 256>>>(Wq, Wk, Wv, Wo, W1, W2, wt, wc);

    convqk<<<dim3(NTOK / 128, BDIM / 32), 256>>>(src, wt, bq, bk, q, k);
    gemm2<3><<<dim3(NTOK / 128, BDIM / 64), 256>>>(src, wc + WC_WV, bv, nullptr, v, BDIM, BDIM);

    attn_mma<<<dim3(SDIM / 64, NHEADS, BATCH), 128>>>(q, k, v, av);

    gemm2<0><<<dim3(NTOK / 128, BDIM / 64), 256>>>(av, wc + WC_WO, bo, src, t1, BDIM, BDIM);
    ln_kernel<<<NTOK, 256>>>(t1, g1, be1, x1);

    gemm2<1><<<dim3(NTOK / 128, DFF / 64), 256>>>(x1, wc + WC_W1, b1, nullptr, ff, DFF, BDIM);
    gemm2<2><<<dim3(NTOK / 128, BDIM / 64), 256>>>(ff, wc + WC_W2, b2, x1, t1, BDIM, DFF);
    ln_kernel<<<NTOK, 256>>>(t1, g2, be2, out);
}

// round 7
// speedup vs baseline: 1.1305x; 1.0988x over previous
#include <cuda_runtime.h>
#include <math.h>
#include <stdint.h>

#define BDIM   512
#define SDIM   1024
#define BATCH  8
#define NHEADS 8
#define HD     64
#define DFF    2048
#define NTOK   (BATCH * SDIM)   // 8192

// Scratch
__device__ float    g_q [BATCH * BDIM * SDIM];   // [B,H,S,64]
__device__ float    g_k [BATCH * BDIM * SDIM];   // [B,H,S,64]
__device__ float    g_v [BATCH * BDIM * SDIM];   // [B,D,S]
__device__ float    g_av[NTOK * BDIM];
__device__ float    g_t1[NTOK * BDIM];
__device__ float    g_x1[NTOK * BDIM];
__device__ float    g_ff[NTOK * DFF];
__device__ uint32_t g_wt[2 * 3 * BDIM * BDIM];   // tf32 Wq/Wk: [mat][tap][co][ci]
__device__ uint32_t g_wc[2 * BDIM * BDIM + 2 * DFF * BDIM];  // tf32 Wv,Wo,W1,W2

#define WC_WV 0
#define WC_WO (BDIM * BDIM)
#define WC_W1 (2 * BDIM * BDIM)
#define WC_W2 (2 * BDIM * BDIM + DFF * BDIM)

__device__ __forceinline__ uint32_t f2tf(float f) {
    uint32_t r;
    asm("cvt.rna.tf32.f32 %0, %1;" : "=r"(r) : "f"(f));
    return r;
}

__device__ __forceinline__ void mma_tf32(float c[4], const uint32_t a[4], const uint32_t b[2]) {
    asm volatile(
        "mma.sync.aligned.m16n8k8.row.col.f32.tf32.tf32.f32 "
        "{%0,%1,%2,%3}, {%4,%5,%6,%7}, {%8,%9}, {%0,%1,%2,%3};"
        : "+f"(c[0]), "+f"(c[1]), "+f"(c[2]), "+f"(c[3])
        : "r"(a[0]), "r"(a[1]), "r"(a[2]), "r"(a[3]), "r"(b[0]), "r"(b[1]));
}

// ---------------------------------------------------------------------------
// Merged prep: all weight conversions in one launch.
// ---------------------------------------------------------------------------
#define WTN (2 * 3 * BDIM * BDIM)
__global__ void wprep_kernel(const float* __restrict__ Wq, const float* __restrict__ Wk,
                             const float* __restrict__ Wv, const float* __restrict__ Wo,
                             const float* __restrict__ W1, const float* __restrict__ W2,
                             uint32_t* __restrict__ wt, uint32_t* __restrict__ wc) {
    int e = blockIdx.x * 256 + threadIdx.x;
    if (e < WTN) {
        int m  = (e >= 3 * BDIM * BDIM);
        int e2 = e - m * 3 * BDIM * BDIM;
        int t  = e2 >> 18;
        int co = (e2 >> 9) & 511;
        int ci = e2 & 511;
        const float* src = m ? Wk : Wq;
        wt[e] = f2tf(src[(size_t)co * 1536 + ci * 3 + t]);
        return;
    }
    int f = e - WTN;
    if (f < BDIM * BDIM)            { wc[WC_WV + f] = f2tf(Wv[f]); return; }
    f -= BDIM * BDIM;
    if (f < BDIM * BDIM)            { wc[WC_WO + f] = f2tf(Wo[f]); return; }
    f -= BDIM * BDIM;
    if (f < DFF * BDIM)             { wc[WC_W1 + f] = f2tf(W1[f]); return; }
    f -= DFF * BDIM;
    if (f < DFF * BDIM)             { wc[WC_W2 + f] = f2tf(W2[f]); return; }
}
#define WPREP_TOTAL (WTN + 2 * BDIM * BDIM + 2 * DFF * BDIM)

// ===========================================================================
// GEMM core v4: block 128(n) x 128(m), 8 warps (32x64 each), KT=16,
// fragment-major XOR-swizzled smem (32KB total), double-buffered,
// SINGLE-stage-ahead register staging (R4-proven pattern).
// MODE 0: +res | 1: relu | 2: +res | 3: V-conv layout [B,D,S] (bias only)
// ===========================================================================
template <int MODE>
__global__ __launch_bounds__(256) void gemm2(const float* __restrict__ A,
                                             const uint32_t* __restrict__ W,
                                             const float* __restrict__ bias,
                                             const float* __restrict__ res,
                                             float* __restrict__ out, int M, int K) {
    __shared__ uint4 Af[2][8][2][32];    // [st][rb16][ks][slot] 16KB
    __shared__ uint2 Bf[2][16][2][32];   // [st][nb8][ks][slot]  16KB

    const int n0 = blockIdx.x * 128;
    const int m0 = blockIdx.y * 128;
    const int tid = threadIdx.x, lane = tid & 31, warp = tid >> 5;
    const int lq = lane >> 2, lr = lane & 3;
    const int wiB = (warp >> 1) * 2;    // row-block16 base (0,2,4,6)
    const int nbB = (warp & 1) * 8;     // nb8 base (0,8)
    const int nk = K >> 4;              // K/16 stages

    float acc[2][8][4];
    #pragma unroll
    for (int mi = 0; mi < 2; mi++)
        #pragma unroll
        for (int ni = 0; ni < 8; ni++)
            #pragma unroll
            for (int c = 0; c < 4; c++) acc[mi][ni][c] = 0.f;

    float4 sa[2];
    uint4  sb[2];

    #define G2_LDG(KO)                                                                \
        { int ko_ = (KO);                                                             \
          _Pragma("unroll")                                                           \
          for (int r = 0; r < 2; r++) {                                               \
              int v = tid + 256 * r;                                                  \
              sa[r] = *(const float4*)&A[(size_t)(n0 + (v >> 2)) * K + ko_ + (v & 3) * 4]; } \
          _Pragma("unroll")                                                           \
          for (int r = 0; r < 2; r++) {                                               \
              int v = tid + 256 * r;                                                  \
              sb[r] = *(const uint4*)&W[(size_t)(m0 + (v >> 2)) * K + ko_ + (v & 3) * 4]; } }

    #define G2_STS(ST)                                                                \
        { _Pragma("unroll")                                                           \
          for (int r = 0; r < 2; r++) {                                               \
              int v = tid + 256 * r;                                                  \
              int row = v >> 2, kc4 = v & 3;                                          \
              int ks = kc4 >> 1, half = kc4 & 1, rb = row >> 4, alq = row & 7, r8 = (row >> 3) & 1; \
              int comp = r8 + 2 * half;                                               \
              uint32_t* base = (uint32_t*)&Af[ST][rb][ks][0];                         \
              uint32_t vals[4] = {f2tf(sa[r].x), f2tf(sa[r].y), f2tf(sa[r].z), f2tf(sa[r].w)}; \
              _Pragma("unroll")                                                       \
              for (int e = 0; e < 4; e++) base[(((alq * 4 + e) ^ ks) << 2) + comp] = vals[e]; } \
          _Pragma("unroll")                                                           \
          for (int r = 0; r < 2; r++) {                                               \
              int v = tid + 256 * r;                                                  \
              int row = v >> 2, kc4 = v & 3;                                          \
              int ks = kc4 >> 1, half = kc4 & 1, nb = row >> 3, blq = row & 7;        \
              uint32_t* base = (uint32_t*)&Bf[ST][nb][ks][0];                         \
              uint32_t vals[4] = {sb[r].x, sb[r].y, sb[r].z, sb[r].w};                \
              _Pragma("unroll")                                                       \
              for (int e = 0; e < 4; e++) base[(((blq * 4 + e) ^ ks) << 1) + half] = vals[e]; } }

    #define G2_COMP(ST)                                                               \
        { _Pragma("unroll")                                                           \
          for (int ks = 0; ks < 2; ks++) {                                            \
              uint4 a0 = Af[ST][wiB][ks][lane ^ ks];                                  \
              uint4 a1 = Af[ST][wiB + 1][ks][lane ^ ks];                              \
              uint32_t aa0[4] = {a0.x, a0.y, a0.z, a0.w};                             \
              uint32_t aa1[4] = {a1.x, a1.y, a1.z, a1.w};                             \
              _Pragma("unroll")                                                       \
              for (int ni = 0; ni < 8; ni++) {                                        \
                  uint2 b = Bf[ST][nbB + ni][ks][lane ^ ks];                          \
                  uint32_t bb[2] = {b.x, b.y};                                        \
                  mma_tf32(acc[0][ni], aa0, bb);                                      \
                  mma_tf32(acc[1][ni], aa1, bb); } } }

    // Prologue
    G2_LDG(0)
    G2_STS(0)
    __syncthreads();

    for (int kb = 0; kb < nk; kb++) {
        if (kb + 1 < nk) G2_LDG((kb + 1) << 4)
        G2_COMP(kb & 1)
        if (kb + 1 < nk) G2_STS((kb + 1) & 1)
        __syncthreads();
    }

    #undef G2_LDG
    #undef G2_STS
    #undef G2_COMP

    // Epilogue
    #pragma unroll
    for (int mi = 0; mi < 2; mi++) {
        #pragma unroll
        for (int ni = 0; ni < 8; ni++) {
            int col = m0 + (warp & 1) * 64 + ni * 8 + 2 * lr;
            float bv0 = bias[col], bv1 = bias[col + 1];
            #pragma unroll
            for (int h = 0; h < 2; h++) {
                int n = n0 + (warp >> 1) * 32 + mi * 16 + lq + h * 8;
                float x0 = acc[mi][ni][2 * h] + bv0;
                float x1 = acc[mi][ni][2 * h + 1] + bv1;
                if (MODE == 1) { x0 = fmaxf(x0, 0.f); x1 = fmaxf(x1, 0.f); }
                if (MODE == 0 || MODE == 2) {
                    x0 += res[(size_t)n * M + col];
                    x1 += res[(size_t)n * M + col + 1];
                }
                if (MODE == 3) {
                    int b = n >> 10, s = n & 1023;
                    out[((size_t)(b * BDIM + col)) * SDIM + s]     = x0;
                    out[((size_t)(b * BDIM + col + 1)) * SDIM + s] = x1;
                } else {
                    *(float2*)&out[(size_t)n * M + col] = make_float2(x0, x1);
                }
            }
        }
    }
}

// ===========================================================================
// Fused Q+K conv (R4-exact): block 128(tok) x 32(co) x 2 mats, KT=32,
// single-stage-ahead register staging.
// ===========================================================================
__global__ __launch_bounds__(256) void convqk(const float* __restrict__ A,
                                              const uint32_t* __restrict__ Wt,
                                              const float* __restrict__ bq,
                                              const float* __restrict__ bk,
                                              float* __restrict__ qo,
                                              float* __restrict__ ko) {
    __shared__ uint4 Af[2][8][4][32];        // 32KB
    __shared__ uint2 Bf[2][2][4][4][32];     // 16KB

    const int n0 = blockIdx.x * 128;
    const int c0 = blockIdx.y * 32;
    const int tid = threadIdx.x, lane = tid & 31, warp = tid >> 5;
    const int lq = lane >> 2, lr = lane & 3;
    const int NST = 48;  // 3 taps x 16 kb

    float acc[2][4][4];
    #pragma unroll
    for (int m = 0; m < 2; m++)
        #pragma unroll
        for (int ni = 0; ni < 4; ni++)
            #pragma unroll
            for (int c = 0; c < 4; c++) acc[m][ni][c] = 0.f;

    float4 sa[4];
    uint4  sb[2];

    #define CQ_LDG(T)                                                                 \
        { int t_ = (T);                                                               \
          int tap_ = t_ >> 4, ko_ = (t_ & 15) << 5, roff_ = tap_ - 1;                 \
          _Pragma("unroll")                                                           \
          for (int r = 0; r < 4; r++) {                                               \
              int v = tid + 256 * r;                                                  \
              int row = v >> 3;                                                       \
              int n = n0 + row;                                                       \
              int s = (n & 1023) + roff_;                                             \
              sa[r] = make_float4(0.f, 0.f, 0.f, 0.f);                                \
              if ((unsigned)s < 1024u)                                                \
                  sa[r] = *(const float4*)&A[((size_t)(n & ~1023) + s) * BDIM + ko_ + (v & 7) * 4]; } \
          { int row = tid >> 3;                                                       \
            _Pragma("unroll")                                                         \
            for (int m = 0; m < 2; m++)                                               \
                sb[m] = *(const uint4*)&Wt[((size_t)(m * 3 + tap_) * BDIM + c0 + row) * BDIM + ko_ + (tid & 7) * 4]; } }

    #define CQ_STS(ST)                                                                \
        { _Pragma("unroll")                                                           \
          for (int r = 0; r < 4; r++) {                                               \
              int v = tid + 256 * r;                                                  \
              int row = v >> 3, kc4 = v & 7;                                          \
              int ks = kc4 >> 1, half = kc4 & 1, rb = row >> 4, alq = row & 7, r8 = (row >> 3) & 1; \
              int comp = r8 + 2 * half;                                               \
              uint32_t* base = (uint32_t*)&Af[ST][rb][ks][0];                         \
              uint32_t vals[4] = {f2tf(sa[r].x), f2tf(sa[r].y), f2tf(sa[r].z), f2tf(sa[r].w)}; \
              _Pragma("unroll")                                                       \
              for (int e = 0; e < 4; e++) base[(((alq * 4 + e) ^ ks) << 2) + comp] = vals[e]; } \
          { int row = tid >> 3, kc4 = tid & 7;                                        \
            int ks = kc4 >> 1, half = kc4 & 1, nb = row >> 3, blq = row & 7;          \
            _Pragma("unroll")                                                         \
            for (int m = 0; m < 2; m++) {                                             \
                uint32_t* base = (uint32_t*)&Bf[ST][m][nb][ks][0];                    \
                uint32_t vals[4] = {sb[m].x, sb[m].y, sb[m].z, sb[m].w};              \
                _Pragma("unroll")                                                     \
                for (int e = 0; e < 4; e++) base[(((blq * 4 + e) ^ ks) << 1) + half] = vals[e]; } } }

    #define CQ_COMP(ST)                                                               \
        { _Pragma("unroll")                                                           \
          for (int ks = 0; ks < 4; ks++) {                                            \
              uint4 a = Af[ST][warp][ks][lane ^ ks];                                  \
              uint32_t aa[4] = {a.x, a.y, a.z, a.w};                                  \
              _Pragma("unroll")                                                       \
              for (int m = 0; m < 2; m++)                                             \
                  _Pragma("unroll")                                                   \
                  for (int ni = 0; ni < 4; ni++) {                                    \
                      uint2 b = Bf[ST][m][ni][ks][lane ^ ks];                         \
                      uint32_t bb[2] = {b.x, b.y};                                    \
                      mma_tf32(acc[m][ni], aa, bb); } } }

    CQ_LDG(0)
    CQ_STS(0)
    __syncthreads();

    for (int t = 0; t < NST; t++) {
        if (t + 1 < NST) CQ_LDG(t + 1)
        CQ_COMP(t & 1)
        if (t + 1 < NST) CQ_STS((t + 1) & 1)
        __syncthreads();
    }

    #undef CQ_LDG
    #undef CQ_STS
    #undef CQ_COMP

    #pragma unroll
    for (int m = 0; m < 2; m++) {
        float* outp = m ? ko : qo;
        const float* bp = m ? bk : bq;
        #pragma unroll
        for (int ni = 0; ni < 4; ni++) {
            int col = c0 + ni * 8 + 2 * lr;
            float bv0 = bp[col], bv1 = bp[col + 1];
            int hh = col >> 6, dd = col & 63;
            #pragma unroll
            for (int h = 0; h < 2; h++) {
                int n = n0 + warp * 16 + lq + h * 8;
                int b = n >> 10, s = n & 1023;
                float2 o2 = make_float2(acc[m][ni][2 * h] + bv0, acc[m][ni][2 * h + 1] + bv1);
                *(float2*)&outp[(((size_t)(b * NHEADS + hh)) * SDIM + s) * HD + dd] = o2;
            }
        }
    }
}

// ---------------------------------------------------------------------------
// tf32 tensor-core flash attention (R4-exact).
// ---------------------------------------------------------------------------
__global__ __launch_bounds__(128) void attn_mma(const float* __restrict__ q,
                                                const float* __restrict__ k,
                                                const float* __restrict__ v,
                                                float* __restrict__ av) {
    const int s0 = blockIdx.x * 64;
    const int h  = blockIdx.y;
    const int b  = blockIdx.z;
    const float* qb = q + (size_t)(b * NHEADS + h) * SDIM * HD;
    const float* kb = k + (size_t)(b * NHEADS + h) * SDIM * HD;
    const float* vb = v + (size_t)(b * NHEADS + h) * HD * SDIM;

    __shared__ uint32_t Ks[64][68];
    __shared__ uint32_t Vs[64][68];

    const int tid  = threadIdx.x;
    const int lane = tid & 31;
    const int warp = tid >> 5;
    const int lq = lane >> 2;
    const int lr = lane & 3;

    #pragma unroll
    for (int r = 0; r < 8; r++) {
        int vdx = tid + 128 * r;
        int row = vdx >> 4, col = (vdx & 15) * 4;
        float4 x = *(const float4*)&qb[(size_t)(s0 + row) * HD + col];
        Ks[row][col + 0] = f2tf(x.x * 0.015625f);
        Ks[row][col + 1] = f2tf(x.y * 0.015625f);
        Ks[row][col + 2] = f2tf(x.z * 0.015625f);
        Ks[row][col + 3] = f2tf(x.w * 0.015625f);
    }
    __syncthreads();
    uint32_t qf[8][4];
    #pragma unroll
    for (int ks = 0; ks < 8; ks++) {
        int k8 = ks * 8 + lr;
        int r0 = warp * 16 + lq;
        qf[ks][0] = Ks[r0][k8];
        qf[ks][1] = Ks[r0 + 8][k8];
        qf[ks][2] = Ks[r0][k8 + 4];
        qf[ks][3] = Ks[r0 + 8][k8 + 4];
    }
    __syncthreads();

    float m0v = -1e30f, m1v = -1e30f, l0 = 0.f, l1 = 0.f;
    float o[8][4];
    #pragma unroll
    for (int ni = 0; ni < 8; ni++)
        #pragma unroll
        for (int c = 0; c < 4; c++) o[ni][c] = 0.f;

    for (int t0 = 0; t0 < SDIM; t0 += 64) {
        #pragma unroll
        for (int r = 0; r < 8; r++) {
            int vdx = tid + 128 * r;
            int row = vdx >> 4, col = (vdx & 15) * 4;
            float4 x = *(const float4*)&kb[(size_t)(t0 + row) * HD + col];
            Ks[row][col + 0] = f2tf(x.x);
            Ks[row][col + 1] = f2tf(x.y);
            Ks[row][col + 2] = f2tf(x.z);
            Ks[row][col + 3] = f2tf(x.w);
            float4 y = *(const float4*)&vb[(size_t)row * SDIM + t0 + col];
            Vs[row][col + 0] = f2tf(y.x);
            Vs[row][col + 1] = f2tf(y.y);
            Vs[row][col + 2] = f2tf(y.z);
            Vs[row][col + 3] = f2tf(y.w);
        }
        __syncthreads();

        float sc[8][4];
        #pragma unroll
        for (int ni = 0; ni < 8; ni++)
            #pragma unroll
            for (int c = 0; c < 4; c++) sc[ni][c] = 0.f;
        #pragma unroll
        for (int ks = 0; ks < 8; ks++) {
            int k8 = ks * 8 + lr;
            #pragma unroll
            for (int ni = 0; ni < 8; ni++) {
                uint32_t bb[2];
                bb[0] = Ks[ni * 8 + lq][k8];
                bb[1] = Ks[ni * 8 + lq][k8 + 4];
                mma_tf32(sc[ni], qf[ks], bb);
            }
        }
        __syncthreads();

        float rm0 = -1e30f, rm1 = -1e30f;
        #pragma unroll
        for (int ni = 0; ni < 8; ni++) {
            rm0 = fmaxf(rm0, fmaxf(sc[ni][0], sc[ni][1]));
            rm1 = fmaxf(rm1, fmaxf(sc[ni][2], sc[ni][3]));
        }
        rm0 = fmaxf(rm0, __shfl_xor_sync(0xffffffffu, rm0, 1));
        rm0 = fmaxf(rm0, __shfl_xor_sync(0xffffffffu, rm0, 2));
        rm1 = fmaxf(rm1, __shfl_xor_sync(0xffffffffu, rm1, 1));
        rm1 = fmaxf(rm1, __shfl_xor_sync(0xffffffffu, rm1, 2));
        float mn0 = fmaxf(m0v, rm0), mn1 = fmaxf(m1v, rm1);
        float cr0 = __expf(m0v - mn0), cr1 = __expf(m1v - mn1);
        float rs0 = 0.f, rs1 = 0.f;
        const int prow = warp * 16 + lq;
        #pragma unroll
        for (int ni = 0; ni < 8; ni++) {
            float p0 = __expf(sc[ni][0] - mn0);
            float p1 = __expf(sc[ni][1] - mn0);
            float p2 = __expf(sc[ni][2] - mn1);
            float p3 = __expf(sc[ni][3] - mn1);
            int col = ni * 8 + 2 * lr;
            Ks[prow][col]         = f2tf(p0);
            Ks[prow][col + 1]     = f2tf(p1);
            Ks[prow + 8][col]     = f2tf(p2);
            Ks[prow + 8][col + 1] = f2tf(p3);
            rs0 += p0 + p1;
            rs1 += p2 + p3;
        }
        rs0 += __shfl_xor_sync(0xffffffffu, rs0, 1);
        rs0 += __shfl_xor_sync(0xffffffffu, rs0, 2);
        rs1 += __shfl_xor_sync(0xffffffffu, rs1, 1);
        rs1 += __shfl_xor_sync(0xffffffffu, rs1, 2);
        l0 = l0 * cr0 + rs0;
        l1 = l1 * cr1 + rs1;
        m0v = mn0; m1v = mn1;
        #pragma unroll
        for (int ni = 0; ni < 8; ni++) {
            o[ni][0] *= cr0; o[ni][1] *= cr0;
            o[ni][2] *= cr1; o[ni][3] *= cr1;
        }
        __syncwarp();

        #pragma unroll
        for (int ks = 0; ks < 8; ks++) {
            int k8 = ks * 8 + lr;
            uint32_t a[4];
            a[0] = Ks[prow][k8];
            a[1] = Ks[prow + 8][k8];
            a[2] = Ks[prow][k8 + 4];
            a[3] = Ks[prow + 8][k8 + 4];
            #pragma unroll
            for (int ni = 0; ni < 8; ni++) {
                uint32_t bb[2];
                bb[0] = Vs[ni * 8 + lq][k8];
                bb[1] = Vs[ni * 8 + lq][k8 + 4];
                mma_tf32(o[ni], a, bb);
            }
        }
        __syncthreads();
    }

    float inv0 = 1.0f / l0, inv1 = 1.0f / l1;
    const int rbase = s0 + warp * 16;
    #pragma unroll
    for (int ni = 0; ni < 8; ni++) {
        int col = h * HD + ni * 8 + 2 * lr;
        float2 a = make_float2(o[ni][0] * inv0, o[ni][1] * inv0);
        float2 c = make_float2(o[ni][2] * inv1, o[ni][3] * inv1);
        *(float2*)&av[(size_t)(b * SDIM + rbase + lq) * BDIM + col]     = a;
        *(float2*)&av[(size_t)(b * SDIM + rbase + lq + 8) * BDIM + col] = c;
    }
}

// ---------------------------------------------------------------------------
// LayerNorm over last dim (512).
// ---------------------------------------------------------------------------
__global__ void ln_kernel(const float* __restrict__ in, const float* __restrict__ g,
                          const float* __restrict__ beta, float* __restrict__ out) {
    const int row = blockIdx.x;
    const float* x = in + (size_t)row * BDIM;
    const int tid = threadIdx.x;
    const int wid = tid >> 5, lane = tid & 31;

    float v0 = x[tid], v1 = x[tid + 256];
    __shared__ float red[8];

    float s = v0 + v1;
    #pragma unroll
    for (int off = 16; off > 0; off >>= 1)
        s += __shfl_xor_sync(0xffffffffu, s, off);
    if (lane == 0) red[wid] = s;
    __syncthreads();
    float tot = 0.f;
    #pragma unroll
    for (int i = 0; i < 8; i++) tot += red[i];
    float mu = tot * (1.0f / 512.0f);
    __syncthreads();

    float d0 = v0 - mu, d1 = v1 - mu;
    float sq = d0 * d0 + d1 * d1;
    #pragma unroll
    for (int off = 16; off > 0; off >>= 1)
        sq += __shfl_xor_sync(0xffffffffu, sq, off);
    if (lane == 0) red[wid] = sq;
    __syncthreads();
    float tot2 = 0.f;
    #pragma unroll
    for (int i = 0; i < 8; i++) tot2 += red[i];
    float rstd = rsqrtf(tot2 * (1.0f / 512.0f) + 1e-5f);

    out[(size_t)row * BDIM + tid]       = d0 * rstd * g[tid]       + beta[tid];
    out[(size_t)row * BDIM + tid + 256] = d1 * rstd * g[tid + 256] + beta[tid + 256];
}

// ---------------------------------------------------------------------------
extern "C" void kernel_launch(void* const* d_in, const int* in_sizes, int n_in,
                              void* d_out, int out_size) {
    const float* src = (const float*)d_in[0];
    const float* Wq  = (const float*)d_in[1];
    const float* bq  = (const float*)d_in[2];
    const float* Wk  = (const float*)d_in[3];
    const float* bk  = (const float*)d_in[4];
    const float* Wv  = (const float*)d_in[5];
    const float* bv  = (const float*)d_in[6];
    const float* Wo  = (const float*)d_in[7];
    const float* bo  = (const float*)d_in[8];
    const float* W1  = (const float*)d_in[9];
    const float* b1  = (const float*)d_in[10];
    const float* W2  = (const float*)d_in[11];
    const float* b2  = (const float*)d_in[12];
    const float* g1  = (const float*)d_in[13];
    const float* be1 = (const float*)d_in[14];
    const float* g2  = (const float*)d_in[15];
    const float* be2 = (const float*)d_in[16];
    float* out = (float*)d_out;

    float *q, *k, *v, *av, *t1, *x1, *ff;
    uint32_t *wt, *wc;
    cudaGetSymbolAddress((void**)&q,  g_q);
    cudaGetSymbolAddress((void**)&k,  g_k);
    cudaGetSymbolAddress((void**)&v,  g_v);
    cudaGetSymbolAddress((void**)&av, g_av);
    cudaGetSymbolAddress((void**)&t1, g_t1);
    cudaGetSymbolAddress((void**)&x1, g_x1);
    cudaGetSymbolAddress((void**)&ff, g_ff);
    cudaGetSymbolAddress((void**)&wt, g_wt);
    cudaGetSymbolAddress((void**)&wc, g_wc);

    wprep_kernel<<<(WPREP_TOTAL + 255) / 256, 256>>>(Wq, Wk, Wv, Wo, W1, W2, wt, wc);

    convqk<<<dim3(NTOK / 128, BDIM / 32), 256>>>(src, wt, bq, bk, q, k);
    gemm2<3><<<dim3(NTOK / 128, BDIM / 128), 256>>>(src, wc + WC_WV, bv, nullptr, v, BDIM, BDIM);

    attn_mma<<<dim3(SDIM / 64, NHEADS, BATCH), 128>>>(q, k, v, av);

    gemm2<0><<<dim3(NTOK / 128, BDIM / 128), 256>>>(av, wc + WC_WO, bo, src, t1, BDIM, BDIM);
    ln_kernel<<<NTOK, 256>>>(t1, g1, be1, x1);

    gemm2<1><<<dim3(NTOK / 128, DFF / 128), 256>>>(x1, wc + WC_W1, b1, nullptr, ff, DFF, BDIM);
    gemm2<2><<<dim3(NTOK / 128, BDIM / 128), 256>>>(ff, wc + WC_W2, b2, x1, t1, BDIM, DFF);
    ln_kernel<<<NTOK, 256>>>(t1, g2, be2, out);
}

// round 9
// speedup vs baseline: 1.4615x; 1.2928x over previous
#include <cuda_runtime.h>
#include <cuda_fp16.h>
#include <math.h>
#include <stdint.h>

#define BDIM   512
#define SDIM   1024
#define BATCH  8
#define NHEADS 8
#define HD     64
#define DFF    2048
#define NTOK   (BATCH * SDIM)   // 8192

// Scratch
__device__ float  g_q [BATCH * BDIM * SDIM];   // [B,H,S,64]
__device__ float  g_k [BATCH * BDIM * SDIM];   // [B,H,S,64]
__device__ float  g_v [BATCH * BDIM * SDIM];   // [B,D,S]
__device__ float  g_av[NTOK * BDIM];
__device__ float  g_t1[NTOK * BDIM];
__device__ float  g_x1[NTOK * BDIM];
__device__ float  g_ff[NTOK * DFF];
__device__ __half g_wt[2 * 3 * BDIM * BDIM];                  // fp16 Wq/Wk: [mat][tap][co][ci]
__device__ __half g_wc[2 * BDIM * BDIM + 2 * DFF * BDIM];     // fp16 Wv,Wo,W1,W2

#define WC_WV 0
#define WC_WO (BDIM * BDIM)
#define WC_W1 (2 * BDIM * BDIM)
#define WC_W2 (2 * BDIM * BDIM + DFF * BDIM)

__device__ __forceinline__ uint32_t f2h2(float lo, float hi) {
    __half2 h = __floats2half2_rn(lo, hi);
    return *reinterpret_cast<uint32_t*>(&h);
}

__device__ __forceinline__ void mma_f16(float c[4], const uint32_t a[4], const uint32_t b[2]) {
    asm volatile(
        "mma.sync.aligned.m16n8k16.row.col.f32.f16.f16.f32 "
        "{%0,%1,%2,%3}, {%4,%5,%6,%7}, {%8,%9}, {%0,%1,%2,%3};"
        : "+f"(c[0]), "+f"(c[1]), "+f"(c[2]), "+f"(c[3])
        : "r"(a[0]), "r"(a[1]), "r"(a[2]), "r"(a[3]), "r"(b[0]), "r"(b[1]));
}

// ---------------------------------------------------------------------------
// Merged prep: all weight conversions (f32 -> fp16) in one launch.
// ---------------------------------------------------------------------------
#define WTN (2 * 3 * BDIM * BDIM)
__global__ void wprep_kernel(const float* __restrict__ Wq, const float* __restrict__ Wk,
                             const float* __restrict__ Wv, const float* __restrict__ Wo,
                             const float* __restrict__ W1, const float* __restrict__ W2,
                             __half* __restrict__ wt, __half* __restrict__ wc) {
    int e = blockIdx.x * 256 + threadIdx.x;
    if (e < WTN) {
        int m  = (e >= 3 * BDIM * BDIM);
        int e2 = e - m * 3 * BDIM * BDIM;
        int t  = e2 >> 18;
        int co = (e2 >> 9) & 511;
        int ci = e2 & 511;
        const float* src = m ? Wk : Wq;
        wt[e] = __float2half_rn(src[(size_t)co * 1536 + ci * 3 + t]);
        return;
    }
    int f = e - WTN;
    if (f < BDIM * BDIM)            { wc[WC_WV + f] = __float2half_rn(Wv[f]); return; }
    f -= BDIM * BDIM;
    if (f < BDIM * BDIM)            { wc[WC_WO + f] = __float2half_rn(Wo[f]); return; }
    f -= BDIM * BDIM;
    if (f < DFF * BDIM)             { wc[WC_W1 + f] = __float2half_rn(W1[f]); return; }
    f -= DFF * BDIM;
    if (f < DFF * BDIM)             { wc[WC_W2 + f] = __float2half_rn(W2[f]); return; }
}
#define WPREP_TOTAL (WTN + 2 * BDIM * BDIM + 2 * DFF * BDIM)

// ===========================================================================
// fp16 GEMM: block 128(n) x 64(m), 8 warps (32x32), KT=32 (2 ksteps of k16),
// fragment-major smem, double-buffered, single-stage-ahead register staging.
// MODE 0: +res | 1: relu | 2: +res | 3: V-conv scatter to [B,D,S] (bias only)
// A: f32 gmem (cvt at STS). W: fp16 gmem.
// ===========================================================================
template <int MODE>
__global__ __launch_bounds__(256) void gemm2(const float* __restrict__ A,
                                             const __half* __restrict__ W,
                                             const float* __restrict__ bias,
                                             const float* __restrict__ res,
                                             float* __restrict__ out, int M, int K) {
    __shared__ uint4 Af[2][8][2][33];   // [st][rowblock16][kstep16][slot] ~17KB
    __shared__ uint2 Bf[2][8][2][33];   // [st][nb8][kstep16][slot]       ~8.5KB

    const int n0 = blockIdx.x * 128;
    const int m0 = blockIdx.y * 64;
    const int tid = threadIdx.x, lane = tid & 31, warp = tid >> 5;
    const int lq = lane >> 2, lr = lane & 3;
    const int wiB = (warp >> 1) * 2;
    const int wjB = (warp & 1) * 4;
    const int nk = K >> 5;

    float acc[2][4][4];
    #pragma unroll
    for (int mi = 0; mi < 2; mi++)
        #pragma unroll
        for (int ni = 0; ni < 4; ni++)
            #pragma unroll
            for (int c = 0; c < 4; c++) acc[mi][ni][c] = 0.f;

    float4 sa[2][2];
    uint4  sb;

    #define G2_LDG(KO)                                                                \
        { int ko_ = (KO);                                                             \
          _Pragma("unroll")                                                           \
          for (int r = 0; r < 2; r++) {                                               \
              int v = tid + 256 * r;                                                  \
              int row = v >> 2, k0 = (v & 3) * 8;                                     \
              const float* ap = &A[(size_t)(n0 + row) * K + ko_ + k0];                \
              sa[r][0] = *(const float4*)ap;                                          \
              sa[r][1] = *(const float4*)(ap + 4); }                                  \
          { int row = tid >> 2, k0 = (tid & 3) * 8;                                   \
            sb = *(const uint4*)&W[(size_t)(m0 + row) * K + ko_ + k0]; } }

    #define G2_STS(ST)                                                                \
        { _Pragma("unroll")                                                           \
          for (int r = 0; r < 2; r++) {                                               \
              int v = tid + 256 * r;                                                  \
              int row = v >> 2, kc = v & 3;                                           \
              int ks = kc >> 1, khalf = kc & 1;                                       \
              int rb = row >> 4, alq = row & 7, r8 = (row >> 3) & 1;                  \
              int comp = r8 + 2 * khalf;                                              \
              uint32_t* base = (uint32_t*)&Af[ST][rb][ks][0];                         \
              uint32_t w0 = f2h2(sa[r][0].x, sa[r][0].y);                             \
              uint32_t w1 = f2h2(sa[r][0].z, sa[r][0].w);                             \
              uint32_t w2 = f2h2(sa[r][1].x, sa[r][1].y);                             \
              uint32_t w3 = f2h2(sa[r][1].z, sa[r][1].w);                             \
              base[(alq * 4 + 0) * 4 + comp] = w0;                                    \
              base[(alq * 4 + 1) * 4 + comp] = w1;                                    \
              base[(alq * 4 + 2) * 4 + comp] = w2;                                    \
              base[(alq * 4 + 3) * 4 + comp] = w3; }                                  \
          { int row = tid >> 2, kc = tid & 3;                                         \
            int ks = kc >> 1, khalf = kc & 1;                                         \
            int nb = row >> 3, blq = row & 7;                                         \
            uint32_t* base = (uint32_t*)&Bf[ST][nb][ks][0];                           \
            base[(blq * 4 + 0) * 2 + khalf] = sb.x;                                   \
            base[(blq * 4 + 1) * 2 + khalf] = sb.y;                                   \
            base[(blq * 4 + 2) * 2 + khalf] = sb.z;                                   \
            base[(blq * 4 + 3) * 2 + khalf] = sb.w; } }

    #define G2_COMP(ST)                                                               \
        { _Pragma("unroll")                                                           \
          for (int ks = 0; ks < 2; ks++) {                                            \
              uint4 a0 = Af[ST][wiB][ks][lane];                                       \
              uint4 a1 = Af[ST][wiB + 1][ks][lane];                                   \
              uint32_t aa0[4] = {a0.x, a0.y, a0.z, a0.w};                             \
              uint32_t aa1[4] = {a1.x, a1.y, a1.z, a1.w};                             \
              _Pragma("unroll")                                                       \
              for (int ni = 0; ni < 4; ni++) {                                        \
                  uint2 b = Bf[ST][wjB + ni][ks][lane];                               \
                  uint32_t bb[2] = {b.x, b.y};                                        \
                  mma_f16(acc[0][ni], aa0, bb);                                       \
                  mma_f16(acc[1][ni], aa1, bb); } } }

    G2_LDG(0)
    G2_STS(0)
    __syncthreads();

    for (int kb = 0; kb < nk; kb++) {
        if (kb + 1 < nk) G2_LDG((kb + 1) << 5)
        G2_COMP(kb & 1)
        if (kb + 1 < nk) G2_STS((kb + 1) & 1)
        __syncthreads();
    }

    #undef G2_LDG
    #undef G2_STS
    #undef G2_COMP

    #pragma unroll
    for (int mi = 0; mi < 2; mi++) {
        #pragma unroll
        for (int ni = 0; ni < 4; ni++) {
            int col = m0 + (warp & 1) * 32 + ni * 8 + 2 * lr;
            float bv0 = bias[col], bv1 = bias[col + 1];
            #pragma unroll
            for (int h = 0; h < 2; h++) {
                int n = n0 + (warp >> 1) * 32 + mi * 16 + lq + h * 8;
                float x0 = acc[mi][ni][2 * h] + bv0;
                float x1 = acc[mi][ni][2 * h + 1] + bv1;
                if (MODE == 1) { x0 = fmaxf(x0, 0.f); x1 = fmaxf(x1, 0.f); }
                if (MODE == 0 || MODE == 2) {
                    x0 += res[(size_t)n * M + col];
                    x1 += res[(size_t)n * M + col + 1];
                }
                if (MODE == 3) {
                    int b = n >> 10, s = n & 1023;
                    out[((size_t)(b * BDIM + col)) * SDIM + s]     = x0;
                    out[((size_t)(b * BDIM + col + 1)) * SDIM + s] = x1;
                } else {
                    *(float2*)&out[(size_t)n * M + col] = make_float2(x0, x1);
                }
            }
        }
    }
}

// ===========================================================================
// Fused Q+K conv (fp16): block 128(tok) x 32(co) x 2 mats, KT=32.
// ===========================================================================
__global__ __launch_bounds__(256) void convqk(const float* __restrict__ A,
                                              const __half* __restrict__ Wt,
                                              const float* __restrict__ bq,
                                              const float* __restrict__ bk,
                                              float* __restrict__ qo,
                                              float* __restrict__ ko) {
    __shared__ uint4 Af[2][8][2][33];        // ~17KB
    __shared__ uint2 Bf[2][2][4][2][33];     // ~8.5KB

    const int n0 = blockIdx.x * 128;
    const int c0 = blockIdx.y * 32;
    const int tid = threadIdx.x, lane = tid & 31, warp = tid >> 5;
    const int lq = lane >> 2, lr = lane & 3;
    const int NST = 48;  // 3 taps x 16 kb

    float acc[2][4][4];
    #pragma unroll
    for (int m = 0; m < 2; m++)
        #pragma unroll
        for (int ni = 0; ni < 4; ni++)
            #pragma unroll
            for (int c = 0; c < 4; c++) acc[m][ni][c] = 0.f;

    float4 sa[2][2];
    uint2  sb[2];

    #define CQ_LDG(T)                                                                 \
        { int t_ = (T);                                                               \
          int tap_ = t_ >> 4, ko_ = (t_ & 15) << 5, roff_ = tap_ - 1;                 \
          _Pragma("unroll")                                                           \
          for (int r = 0; r < 2; r++) {                                               \
              int v = tid + 256 * r;                                                  \
              int row = v >> 2, k0 = (v & 3) * 8;                                     \
              int n = n0 + row;                                                       \
              int s = (n & 1023) + roff_;                                             \
              sa[r][0] = make_float4(0.f, 0.f, 0.f, 0.f);                             \
              sa[r][1] = make_float4(0.f, 0.f, 0.f, 0.f);                             \
              if ((unsigned)s < 1024u) {                                              \
                  const float* ap = &A[((size_t)(n & ~1023) + s) * BDIM + ko_ + k0];  \
                  sa[r][0] = *(const float4*)ap;                                      \
                  sa[r][1] = *(const float4*)(ap + 4); } }                            \
          { int row = tid >> 3, k0 = (tid & 7) * 4;                                   \
            _Pragma("unroll")                                                         \
            for (int m = 0; m < 2; m++)                                               \
                sb[m] = *(const uint2*)&Wt[((size_t)(m * 3 + tap_) * BDIM + c0 + row) * BDIM + ko_ + k0]; } }

    #define CQ_STS(ST)                                                                \
        { _Pragma("unroll")                                                           \
          for (int r = 0; r < 2; r++) {                                               \
              int v = tid + 256 * r;                                                  \
              int row = v >> 2, kc = v & 3;                                           \
              int ks = kc >> 1, khalf = kc & 1;                                       \
              int rb = row >> 4, alq = row & 7, r8 = (row >> 3) & 1;                  \
              int comp = r8 + 2 * khalf;                                              \
              uint32_t* base = (uint32_t*)&Af[ST][rb][ks][0];                         \
              base[(alq * 4 + 0) * 4 + comp] = f2h2(sa[r][0].x, sa[r][0].y);          \
              base[(alq * 4 + 1) * 4 + comp] = f2h2(sa[r][0].z, sa[r][0].w);          \
              base[(alq * 4 + 2) * 4 + comp] = f2h2(sa[r][1].x, sa[r][1].y);          \
              base[(alq * 4 + 3) * 4 + comp] = f2h2(sa[r][1].z, sa[r][1].w); }        \
          { int row = tid >> 3, kc8 = tid & 7;                                        \
            int ks = kc8 >> 2, khalf = (kc8 >> 1) & 1, lr0 = (kc8 & 1) * 2;           \
            int nb = row >> 3, blq = row & 7;                                         \
            _Pragma("unroll")                                                         \
            for (int m = 0; m < 2; m++) {                                             \
                uint32_t* base = (uint32_t*)&Bf[ST][m][nb][ks][0];                    \
                base[(blq * 4 + lr0 + 0) * 2 + khalf] = sb[m].x;                      \
                base[(blq * 4 + lr0 + 1) * 2 + khalf] = sb[m].y; } } }

    #define CQ_COMP(ST)                                                               \
        { _Pragma("unroll")                                                           \
          for (int ks = 0; ks < 2; ks++) {                                            \
              uint4 a = Af[ST][warp][ks][lane];                                       \
              uint32_t aa[4] = {a.x, a.y, a.z, a.w};                                  \
              _Pragma("unroll")                                                       \
              for (int m = 0; m < 2; m++)                                             \
                  _Pragma("unroll")                                                   \
                  for (int ni = 0; ni < 4; ni++) {                                    \
                      uint2 b = Bf[ST][m][ni][ks][lane];                              \
                      uint32_t bb[2] = {b.x, b.y};                                    \
                      mma_f16(acc[m][ni], aa, bb); } } }

    CQ_LDG(0)
    CQ_STS(0)
    __syncthreads();

    for (int t = 0; t < NST; t++) {
        if (t + 1 < NST) CQ_LDG(t + 1)
        CQ_COMP(t & 1)
        if (t + 1 < NST) CQ_STS((t + 1) & 1)
        __syncthreads();
    }

    #undef CQ_LDG
    #undef CQ_STS
    #undef CQ_COMP

    #pragma unroll
    for (int m = 0; m < 2; m++) {
        float* outp = m ? ko : qo;
        const float* bp = m ? bk : bq;
        #pragma unroll
        for (int ni = 0; ni < 4; ni++) {
            int col = c0 + ni * 8 + 2 * lr;
            float bv0 = bp[col], bv1 = bp[col + 1];
            int hh = col >> 6, dd = col & 63;
            #pragma unroll
            for (int h = 0; h < 2; h++) {
                int n = n0 + warp * 16 + lq + h * 8;
                int b = n >> 10, s = n & 1023;
                float2 o2 = make_float2(acc[m][ni][2 * h] + bv0, acc[m][ni][2 * h + 1] + bv1);
                *(float2*)&outp[(((size_t)(b * NHEADS + hh)) * SDIM + s) * HD + dd] = o2;
            }
        }
    }
}

// ---------------------------------------------------------------------------
// fp16 tensor-core flash attention. q,k [B,H,S,64] f32; v [B,D,S] f32.
// Smem tiles hold half2 words (word w = elems 2w,2w+1 along the k-dim).
// ---------------------------------------------------------------------------
__global__ __launch_bounds__(128) void attn_mma(const float* __restrict__ q,
                                                const float* __restrict__ k,
                                                const float* __restrict__ v,
                                                float* __restrict__ av) {
    const int s0 = blockIdx.x * 64;
    const int h  = blockIdx.y;
    const int b  = blockIdx.z;
    const float* qb = q + (size_t)(b * NHEADS + h) * SDIM * HD;
    const float* kb = k + (size_t)(b * NHEADS + h) * SDIM * HD;
    const float* vb = v + (size_t)(b * NHEADS + h) * HD * SDIM;

    __shared__ uint32_t Ks[64][36];   // K tile (d-pairs), then P tile (t-pairs)
    __shared__ uint32_t Vs[64][36];   // V tile (t-pairs per d row)

    const int tid  = threadIdx.x;
    const int lane = tid & 31;
    const int warp = tid >> 5;
    const int lq = lane >> 2;
    const int lr = lane & 3;

    // Stage Q (scaled 1/64) into Ks as half2 words, pull A-fragments (k16 steps)
    #pragma unroll
    for (int r = 0; r < 8; r++) {
        int vdx = tid + 128 * r;
        int row = vdx >> 4, col = (vdx & 15) * 4;
        float4 x = *(const float4*)&qb[(size_t)(s0 + row) * HD + col];
        Ks[row][col / 2 + 0] = f2h2(x.x * 0.015625f, x.y * 0.015625f);
        Ks[row][col / 2 + 1] = f2h2(x.z * 0.015625f, x.w * 0.015625f);
    }
    __syncthreads();
    uint32_t qf[4][4];
    #pragma unroll
    for (int ks = 0; ks < 4; ks++) {
        int w8 = ks * 8 + lr;
        int r0 = warp * 16 + lq;
        qf[ks][0] = Ks[r0][w8];
        qf[ks][1] = Ks[r0 + 8][w8];
        qf[ks][2] = Ks[r0][w8 + 4];
        qf[ks][3] = Ks[r0 + 8][w8 + 4];
    }
    __syncthreads();

    float m0v = -1e30f, m1v = -1e30f, l0 = 0.f, l1 = 0.f;
    float o[8][4];
    #pragma unroll
    for (int ni = 0; ni < 8; ni++)
        #pragma unroll
        for (int c = 0; c < 4; c++) o[ni][c] = 0.f;

    const int prow = warp * 16 + lq;

    for (int t0 = 0; t0 < SDIM; t0 += 64) {
        #pragma unroll
        for (int r = 0; r < 8; r++) {
            int vdx = tid + 128 * r;
            int row = vdx >> 4, col = (vdx & 15) * 4;
            float4 x = *(const float4*)&kb[(size_t)(t0 + row) * HD + col];
            Ks[row][col / 2 + 0] = f2h2(x.x, x.y);
            Ks[row][col / 2 + 1] = f2h2(x.z, x.w);
            float4 y = *(const float4*)&vb[(size_t)row * SDIM + t0 + col];
            Vs[row][col / 2 + 0] = f2h2(y.x, y.y);
            Vs[row][col / 2 + 1] = f2h2(y.z, y.w);
        }
        __syncthreads();

        // scores: 16 rows x 64 t (4 k16-steps over d=64)
        float sc[8][4];
        #pragma unroll
        for (int ni = 0; ni < 8; ni++)
            #pragma unroll
            for (int c = 0; c < 4; c++) sc[ni][c] = 0.f;
        #pragma unroll
        for (int ks = 0; ks < 4; ks++) {
            int w8 = ks * 8 + lr;
            #pragma unroll
            for (int ni = 0; ni < 8; ni++) {
                uint32_t bb[2];
                bb[0] = Ks[ni * 8 + lq][w8];
                bb[1] = Ks[ni * 8 + lq][w8 + 4];
                mma_f16(sc[ni], qf[ks], bb);
            }
        }
        __syncthreads();   // done reading K; safe to overwrite with P

        // Online softmax
        float rm0 = -1e30f, rm1 = -1e30f;
        #pragma unroll
        for (int ni = 0; ni < 8; ni++) {
            rm0 = fmaxf(rm0, fmaxf(sc[ni][0], sc[ni][1]));
            rm1 = fmaxf(rm1, fmaxf(sc[ni][2], sc[ni][3]));
        }
        rm0 = fmaxf(rm0, __shfl_xor_sync(0xffffffffu, rm0, 1));
        rm0 = fmaxf(rm0, __shfl_xor_sync(0xffffffffu, rm0, 2));
        rm1 = fmaxf(rm1, __shfl_xor_sync(0xffffffffu, rm1, 1));
        rm1 = fmaxf(rm1, __shfl_xor_sync(0xffffffffu, rm1, 2));
        float mn0 = fmaxf(m0v, rm0), mn1 = fmaxf(m1v, rm1);
        float cr0 = __expf(m0v - mn0), cr1 = __expf(m1v - mn1);
        float rs0 = 0.f, rs1 = 0.f;
        #pragma unroll
        for (int ni = 0; ni < 8; ni++) {
            float p0 = __expf(sc[ni][0] - mn0);
            float p1 = __expf(sc[ni][1] - mn0);
            float p2 = __expf(sc[ni][2] - mn1);
            float p3 = __expf(sc[ni][3] - mn1);
            // P word w holds t = 2w, 2w+1 ; here t = ni*8 + 2*lr (+1)
            Ks[prow][ni * 4 + lr]     = f2h2(p0, p1);
            Ks[prow + 8][ni * 4 + lr] = f2h2(p2, p3);
            rs0 += p0 + p1;
            rs1 += p2 + p3;
        }
        rs0 += __shfl_xor_sync(0xffffffffu, rs0, 1);
        rs0 += __shfl_xor_sync(0xffffffffu, rs0, 2);
        rs1 += __shfl_xor_sync(0xffffffffu, rs1, 1);
        rs1 += __shfl_xor_sync(0xffffffffu, rs1, 2);
        l0 = l0 * cr0 + rs0;
        l1 = l1 * cr1 + rs1;
        m0v = mn0; m1v = mn1;
        #pragma unroll
        for (int ni = 0; ni < 8; ni++) {
            o[ni][0] *= cr0; o[ni][1] *= cr0;
            o[ni][2] *= cr1; o[ni][3] *= cr1;
        }
        __syncwarp();   // warp reads only its own P rows

        // PV: O[16 s][64 d] += P[16 s][64 t] * V[d][t]  (4 k16-steps over t)
        #pragma unroll
        for (int ks = 0; ks < 4; ks++) {
            int w8 = ks * 8 + lr;
            uint32_t a[4];
            a[0] = Ks[prow][w8];
            a[1] = Ks[prow + 8][w8];
            a[2] = Ks[prow][w8 + 4];
            a[3] = Ks[prow + 8][w8 + 4];
            #pragma unroll
            for (int ni = 0; ni < 8; ni++) {
                uint32_t bb[2];
                bb[0] = Vs[ni * 8 + lq][w8];
                bb[1] = Vs[ni * 8 + lq][w8 + 4];
                mma_f16(o[ni], a, bb);
            }
        }
        __syncthreads();
    }

    float inv0 = 1.0f / l0, inv1 = 1.0f / l1;
    const int rbase = s0 + warp * 16;
    #pragma unroll
    for (int ni = 0; ni < 8; ni++) {
        int col = h * HD + ni * 8 + 2 * lr;
        float2 a = make_float2(o[ni][0] * inv0, o[ni][1] * inv0);
        float2 c = make_float2(o[ni][2] * inv1, o[ni][3] * inv1);
        *(float2*)&av[(size_t)(b * SDIM + rbase + lq) * BDIM + col]     = a;
        *(float2*)&av[(size_t)(b * SDIM + rbase + lq + 8) * BDIM + col] = c;
    }
}

// ---------------------------------------------------------------------------
// LayerNorm over last dim (512).
// ---------------------------------------------------------------------------
__global__ void ln_kernel(const float* __restrict__ in, const float* __restrict__ g,
                          const float* __restrict__ beta, float* __restrict__ out) {
    const int row = blockIdx.x;
    const float* x = in + (size_t)row * BDIM;
    const int tid = threadIdx.x;
    const int wid = tid >> 5, lane = tid & 31;

    float v0 = x[tid], v1 = x[tid + 256];
    __shared__ float red[8];

    float s = v0 + v1;
    #pragma unroll
    for (int off = 16; off > 0; off >>= 1)
        s += __shfl_xor_sync(0xffffffffu, s, off);
    if (lane == 0) red[wid] = s;
    __syncthreads();
    float tot = 0.f;
    #pragma unroll
    for (int i = 0; i < 8; i++) tot += red[i];
    float mu = tot * (1.0f / 512.0f);
    __syncthreads();

    float d0 = v0 - mu, d1 = v1 - mu;
    float sq = d0 * d0 + d1 * d1;
    #pragma unroll
    for (int off = 16; off > 0; off >>= 1)
        sq += __shfl_xor_sync(0xffffffffu, sq, off);
    if (lane == 0) red[wid] = sq;
    __syncthreads();
    float tot2 = 0.f;
    #pragma unroll
    for (int i = 0; i < 8; i++) tot2 += red[i];
    float rstd = rsqrtf(tot2 * (1.0f / 512.0f) + 1e-5f);

    out[(size_t)row * BDIM + tid]       = d0 * rstd * g[tid]       + beta[tid];
    out[(size_t)row * BDIM + tid + 256] = d1 * rstd * g[tid + 256] + beta[tid + 256];
}

// ---------------------------------------------------------------------------
extern "C" void kernel_launch(void* const* d_in, const int* in_sizes, int n_in,
                              void* d_out, int out_size) {
    const float* src = (const float*)d_in[0];
    const float* Wq  = (const float*)d_in[1];
    const float* bq  = (const float*)d_in[2];
    const float* Wk  = (const float*)d_in[3];
    const float* bk  = (const float*)d_in[4];
    const float* Wv  = (const float*)d_in[5];
    const float* bv  = (const float*)d_in[6];
    const float* Wo  = (const float*)d_in[7];
    const float* bo  = (const float*)d_in[8];
    const float* W1  = (const float*)d_in[9];
    const float* b1  = (const float*)d_in[10];
    const float* W2  = (const float*)d_in[11];
    const float* b2  = (const float*)d_in[12];
    const float* g1  = (const float*)d_in[13];
    const float* be1 = (const float*)d_in[14];
    const float* g2  = (const float*)d_in[15];
    const float* be2 = (const float*)d_in[16];
    float* out = (float*)d_out;

    float *q, *k, *v, *av, *t1, *x1, *ff;
    __half *wt, *wc;
    cudaGetSymbolAddress((void**)&q,  g_q);
    cudaGetSymbolAddress((void**)&k,  g_k);
    cudaGetSymbolAddress((void**)&v,  g_v);
    cudaGetSymbolAddress((void**)&av, g_av);
    cudaGetSymbolAddress((void**)&t1, g_t1);
    cudaGetSymbolAddress((void**)&x1, g_x1);
    cudaGetSymbolAddress((void**)&ff, g_ff);
    cudaGetSymbolAddress((void**)&wt, g_wt);
    cudaGetSymbolAddress((void**)&wc, g_wc);

    wprep_kernel<<<(WPREP_TOTAL + 255) / 256, 256>>>(Wq, Wk, Wv, Wo, W1, W2, wt, wc);

    convqk<<<dim3(NTOK / 128, BDIM / 32), 256>>>(src, wt, bq, bk, q, k);
    gemm2<3><<<dim3(NTOK / 128, BDIM / 64), 256>>>(src, wc + WC_WV, bv, nullptr, v, BDIM, BDIM);

    attn_mma<<<dim3(SDIM / 64, NHEADS, BATCH), 128>>>(q, k, v, av);

    gemm2<0><<<dim3(NTOK / 128, BDIM / 64), 256>>>(av, wc + WC_WO, bo, src, t1, BDIM, BDIM);
    ln_kernel<<<NTOK, 256>>>(t1, g1, be1, x1);

    gemm2<1><<<dim3(NTOK / 128, DFF / 64), 256>>>(x1, wc + WC_W1, b1, nullptr, ff, DFF, BDIM);
    gemm2<2><<<dim3(NTOK / 128, BDIM / 64), 256>>>(ff, wc + WC_W2, b2, x1, t1, BDIM, DFF);
    ln_kernel<<<NTOK, 256>>>(t1, g2, be2, out);
}

// round 10
// speedup vs baseline: 1.6135x; 1.1040x over previous
#include <cuda_runtime.h>
#include <cuda_fp16.h>
#include <math.h>
#include <stdint.h>

#define BDIM   512
#define SDIM   1024
#define BATCH  8
#define NHEADS 8
#define HD     64
#define DFF    2048
#define NTOK   (BATCH * SDIM)   // 8192

// Scratch
__device__ __half g_srch[NTOK * BDIM];         // fp16 copy of src
__device__ __half g_q [BATCH * BDIM * SDIM];   // [B,H,S,64], pre-scaled by 1/64
__device__ __half g_k [BATCH * BDIM * SDIM];   // [B,H,S,64]
__device__ __half g_v [BATCH * BDIM * SDIM];   // [B,D,S]
__device__ __half g_av[NTOK * BDIM];
__device__ float  g_t1[NTOK * BDIM];
__device__ __half g_x1[NTOK * BDIM];
__device__ __half g_ff[NTOK * DFF];
__device__ __half g_wt[2 * 3 * BDIM * BDIM];                  // fp16 Wq/Wk: [mat][tap][co][ci]
__device__ __half g_wc[2 * BDIM * BDIM + 2 * DFF * BDIM];     // fp16 Wv,Wo,W1,W2

#define WC_WV 0
#define WC_WO (BDIM * BDIM)
#define WC_W1 (2 * BDIM * BDIM)
#define WC_W2 (2 * BDIM * BDIM + DFF * BDIM)

__device__ __forceinline__ uint32_t f2h2(float lo, float hi) {
    __half2 h = __floats2half2_rn(lo, hi);
    return *reinterpret_cast<uint32_t*>(&h);
}

__device__ __forceinline__ void mma_f16(float c[4], const uint32_t a[4], const uint32_t b[2]) {
    asm volatile(
        "mma.sync.aligned.m16n8k16.row.col.f32.f16.f16.f32 "
        "{%0,%1,%2,%3}, {%4,%5,%6,%7}, {%8,%9}, {%0,%1,%2,%3};"
        : "+f"(c[0]), "+f"(c[1]), "+f"(c[2]), "+f"(c[3])
        : "r"(a[0]), "r"(a[1]), "r"(a[2]), "r"(a[3]), "r"(b[0]), "r"(b[1]));
}

// ---------------------------------------------------------------------------
// Merged prep: all weight conversions + src->fp16, one launch.
// ---------------------------------------------------------------------------
#define WTN (2 * 3 * BDIM * BDIM)
#define WPREP_TOTAL (WTN + 2 * BDIM * BDIM + 2 * DFF * BDIM + NTOK * BDIM)
__global__ void wprep_kernel(const float* __restrict__ Wq, const float* __restrict__ Wk,
                             const float* __restrict__ Wv, const float* __restrict__ Wo,
                             const float* __restrict__ W1, const float* __restrict__ W2,
                             const float* __restrict__ src,
                             __half* __restrict__ wt, __half* __restrict__ wc,
                             __half* __restrict__ srch) {
    int e = blockIdx.x * 256 + threadIdx.x;
    if (e < WTN) {
        int m  = (e >= 3 * BDIM * BDIM);
        int e2 = e - m * 3 * BDIM * BDIM;
        int t  = e2 >> 18;
        int co = (e2 >> 9) & 511;
        int ci = e2 & 511;
        const float* s = m ? Wk : Wq;
        wt[e] = __float2half_rn(s[(size_t)co * 1536 + ci * 3 + t]);
        return;
    }
    int f = e - WTN;
    if (f < BDIM * BDIM)            { wc[WC_WV + f] = __float2half_rn(Wv[f]); return; }
    f -= BDIM * BDIM;
    if (f < BDIM * BDIM)            { wc[WC_WO + f] = __float2half_rn(Wo[f]); return; }
    f -= BDIM * BDIM;
    if (f < DFF * BDIM)             { wc[WC_W1 + f] = __float2half_rn(W1[f]); return; }
    f -= DFF * BDIM;
    if (f < DFF * BDIM)             { wc[WC_W2 + f] = __float2half_rn(W2[f]); return; }
    f -= DFF * BDIM;
    if (f < NTOK * BDIM)            { srch[f] = __float2half_rn(src[f]); return; }
}

// ===========================================================================
// fp16 GEMM: block 128(n) x 64(m), 8 warps (32x32), KT=32 (2 k16-steps),
// fragment-major smem, double-buffered, single-stage-ahead register staging.
// A and W both fp16 in gmem (pure-copy STS).
// MODE 0: +res(f32) -> f32 | 1: relu -> fp16 | 2: +res(fp16) -> f32
// MODE 3: scatter [B,D,S] fp16 (bias only)
// ===========================================================================
template <int MODE>
__global__ __launch_bounds__(256) void gemm2(const __half* __restrict__ A,
                                             const __half* __restrict__ W,
                                             const float* __restrict__ bias,
                                             const void* __restrict__ resv,
                                             void* __restrict__ outv, int M, int K) {
    __shared__ uint4 Af[2][8][2][33];
    __shared__ uint2 Bf[2][8][2][33];

    const int n0 = blockIdx.x * 128;
    const int m0 = blockIdx.y * 64;
    const int tid = threadIdx.x, lane = tid & 31, warp = tid >> 5;
    const int lq = lane >> 2, lr = lane & 3;
    const int wiB = (warp >> 1) * 2;
    const int wjB = (warp & 1) * 4;
    const int nk = K >> 5;

    float acc[2][4][4];
    #pragma unroll
    for (int mi = 0; mi < 2; mi++)
        #pragma unroll
        for (int ni = 0; ni < 4; ni++)
            #pragma unroll
            for (int c = 0; c < 4; c++) acc[mi][ni][c] = 0.f;

    uint4 sa[2], sb;

    #define G2_LDG(KO)                                                                \
        { int ko_ = (KO);                                                             \
          _Pragma("unroll")                                                           \
          for (int r = 0; r < 2; r++) {                                               \
              int v = tid + 256 * r;                                                  \
              int row = v >> 2, k0 = (v & 3) * 8;                                     \
              sa[r] = *(const uint4*)&A[(size_t)(n0 + row) * K + ko_ + k0]; }         \
          { int row = tid >> 2, k0 = (tid & 3) * 8;                                   \
            sb = *(const uint4*)&W[(size_t)(m0 + row) * K + ko_ + k0]; } }

    #define G2_STS(ST)                                                                \
        { _Pragma("unroll")                                                           \
          for (int r = 0; r < 2; r++) {                                               \
              int v = tid + 256 * r;                                                  \
              int row = v >> 2, kc = v & 3;                                           \
              int ks = kc >> 1, khalf = kc & 1;                                       \
              int rb = row >> 4, alq = row & 7, r8 = (row >> 3) & 1;                  \
              int comp = r8 + 2 * khalf;                                              \
              uint32_t* base = (uint32_t*)&Af[ST][rb][ks][0];                         \
              base[(alq * 4 + 0) * 4 + comp] = sa[r].x;                               \
              base[(alq * 4 + 1) * 4 + comp] = sa[r].y;                               \
              base[(alq * 4 + 2) * 4 + comp] = sa[r].z;                               \
              base[(alq * 4 + 3) * 4 + comp] = sa[r].w; }                             \
          { int row = tid >> 2, kc = tid & 3;                                         \
            int ks = kc >> 1, khalf = kc & 1;                                         \
            int nb = row >> 3, blq = row & 7;                                         \
            uint32_t* base = (uint32_t*)&Bf[ST][nb][ks][0];                           \
            base[(blq * 4 + 0) * 2 + khalf] = sb.x;                                   \
            base[(blq * 4 + 1) * 2 + khalf] = sb.y;                                   \
            base[(blq * 4 + 2) * 2 + khalf] = sb.z;                                   \
            base[(blq * 4 + 3) * 2 + khalf] = sb.w; } }

    #define G2_COMP(ST)                                                               \
        { _Pragma("unroll")                                                           \
          for (int ks = 0; ks < 2; ks++) {                                            \
              uint4 a0 = Af[ST][wiB][ks][lane];                                       \
              uint4 a1 = Af[ST][wiB + 1][ks][lane];                                   \
              uint32_t aa0[4] = {a0.x, a0.y, a0.z, a0.w};                             \
              uint32_t aa1[4] = {a1.x, a1.y, a1.z, a1.w};                             \
              _Pragma("unroll")                                                       \
              for (int ni = 0; ni < 4; ni++) {                                        \
                  uint2 b = Bf[ST][wjB + ni][ks][lane];                               \
                  uint32_t bb[2] = {b.x, b.y};                                        \
                  mma_f16(acc[0][ni], aa0, bb);                                       \
                  mma_f16(acc[1][ni], aa1, bb); } } }

    G2_LDG(0)
    G2_STS(0)
    __syncthreads();

    for (int kb = 0; kb < nk; kb++) {
        if (kb + 1 < nk) G2_LDG((kb + 1) << 5)
        G2_COMP(kb & 1)
        if (kb + 1 < nk) G2_STS((kb + 1) & 1)
        __syncthreads();
    }

    #undef G2_LDG
    #undef G2_STS
    #undef G2_COMP

    #pragma unroll
    for (int mi = 0; mi < 2; mi++) {
        #pragma unroll
        for (int ni = 0; ni < 4; ni++) {
            int col = m0 + (warp & 1) * 32 + ni * 8 + 2 * lr;
            float bv0 = bias[col], bv1 = bias[col + 1];
            #pragma unroll
            for (int h = 0; h < 2; h++) {
                int n = n0 + (warp >> 1) * 32 + mi * 16 + lq + h * 8;
                float x0 = acc[mi][ni][2 * h] + bv0;
                float x1 = acc[mi][ni][2 * h + 1] + bv1;
                if (MODE == 1) { x0 = fmaxf(x0, 0.f); x1 = fmaxf(x1, 0.f); }
                if (MODE == 0) {
                    const float* res = (const float*)resv;
                    x0 += res[(size_t)n * M + col];
                    x1 += res[(size_t)n * M + col + 1];
                }
                if (MODE == 2) {
                    const __half* res = (const __half*)resv;
                    __half2 rv = *(const __half2*)&res[(size_t)n * M + col];
                    float2 rf = __half22float2(rv);
                    x0 += rf.x; x1 += rf.y;
                }
                if (MODE == 3) {
                    __half* out = (__half*)outv;
                    int b = n >> 10, s = n & 1023;
                    out[((size_t)(b * BDIM + col)) * SDIM + s]     = __float2half_rn(x0);
                    out[((size_t)(b * BDIM + col + 1)) * SDIM + s] = __float2half_rn(x1);
                } else if (MODE == 1) {
                    __half* out = (__half*)outv;
                    *(__half2*)&out[(size_t)n * M + col] = __floats2half2_rn(x0, x1);
                } else {
                    float* out = (float*)outv;
                    *(float2*)&out[(size_t)n * M + col] = make_float2(x0, x1);
                }
            }
        }
    }
}

// ===========================================================================
// Fused Q+K conv (fp16 in/out): block 128(tok) x 32(co) x 2 mats, KT=32.
// Q output pre-scaled by 1/64 (folded softmax scale).
// ===========================================================================
__global__ __launch_bounds__(256) void convqk(const __half* __restrict__ A,
                                              const __half* __restrict__ Wt,
                                              const float* __restrict__ bq,
                                              const float* __restrict__ bk,
                                              __half* __restrict__ qo,
                                              __half* __restrict__ ko) {
    __shared__ uint4 Af[2][8][2][33];
    __shared__ uint2 Bf[2][2][4][2][33];

    const int n0 = blockIdx.x * 128;
    const int c0 = blockIdx.y * 32;
    const int tid = threadIdx.x, lane = tid & 31, warp = tid >> 5;
    const int lq = lane >> 2, lr = lane & 3;
    const int NST = 48;  // 3 taps x 16 kb

    float acc[2][4][4];
    #pragma unroll
    for (int m = 0; m < 2; m++)
        #pragma unroll
        for (int ni = 0; ni < 4; ni++)
            #pragma unroll
            for (int c = 0; c < 4; c++) acc[m][ni][c] = 0.f;

    uint4 sa[2];
    uint2 sb[2];

    #define CQ_LDG(T)                                                                 \
        { int t_ = (T);                                                               \
          int tap_ = t_ >> 4, ko_ = (t_ & 15) << 5, roff_ = tap_ - 1;                 \
          _Pragma("unroll")                                                           \
          for (int r = 0; r < 2; r++) {                                               \
              int v = tid + 256 * r;                                                  \
              int row = v >> 2, k0 = (v & 3) * 8;                                     \
              int n = n0 + row;                                                       \
              int s = (n & 1023) + roff_;                                             \
              sa[r] = make_uint4(0u, 0u, 0u, 0u);                                     \
              if ((unsigned)s < 1024u)                                                \
                  sa[r] = *(const uint4*)&A[((size_t)(n & ~1023) + s) * BDIM + ko_ + k0]; } \
          { int row = tid >> 3, k0 = (tid & 7) * 4;                                   \
            _Pragma("unroll")                                                         \
            for (int m = 0; m < 2; m++)                                               \
                sb[m] = *(const uint2*)&Wt[((size_t)(m * 3 + tap_) * BDIM + c0 + row) * BDIM + ko_ + k0]; } }

    #define CQ_STS(ST)                                                                \
        { _Pragma("unroll")                                                           \
          for (int r = 0; r < 2; r++) {                                               \
              int v = tid + 256 * r;                                                  \
              int row = v >> 2, kc = v & 3;                                           \
              int ks = kc >> 1, khalf = kc & 1;                                       \
              int rb = row >> 4, alq = row & 7, r8 = (row >> 3) & 1;                  \
              int comp = r8 + 2 * khalf;                                              \
              uint32_t* base = (uint32_t*)&Af[ST][rb][ks][0];                         \
              base[(alq * 4 + 0) * 4 + comp] = sa[r].x;                               \
              base[(alq * 4 + 1) * 4 + comp] = sa[r].y;                               \
              base[(alq * 4 + 2) * 4 + comp] = sa[r].z;                               \
              base[(alq * 4 + 3) * 4 + comp] = sa[r].w; }                             \
          { int row = tid >> 3, kc8 = tid & 7;                                        \
            int ks = kc8 >> 2, khalf = (kc8 >> 1) & 1, lr0 = (kc8 & 1) * 2;           \
            int nb = row >> 3, blq = row & 7;                                         \
            _Pragma("unroll")                                                         \
            for (int m = 0; m < 2; m++) {                                             \
                uint32_t* base = (uint32_t*)&Bf[ST][m][nb][ks][0];                    \
                base[(blq * 4 + lr0 + 0) * 2 + khalf] = sb[m].x;                      \
                base[(blq * 4 + lr0 + 1) * 2 + khalf] = sb[m].y; } } }

    #define CQ_COMP(ST)                                                               \
        { _Pragma("unroll")                                                           \
          for (int ks = 0; ks < 2; ks++) {                                            \
              uint4 a = Af[ST][warp][ks][lane];                                       \
              uint32_t aa[4] = {a.x, a.y, a.z, a.w};                                  \
              _Pragma("unroll")                                                       \
              for (int m = 0; m < 2; m++)                                             \
                  _Pragma("unroll")                                                   \
                  for (int ni = 0; ni < 4; ni++) {                                    \
                      uint2 b = Bf[ST][m][ni][ks][lane];                              \
                      uint32_t bb[2] = {b.x, b.y};                                    \
                      mma_f16(acc[m][ni], aa, bb); } } }

    CQ_LDG(0)
    CQ_STS(0)
    __syncthreads();

    for (int t = 0; t < NST; t++) {
        if (t + 1 < NST) CQ_LDG(t + 1)
        CQ_COMP(t & 1)
        if (t + 1 < NST) CQ_STS((t + 1) & 1)
        __syncthreads();
    }

    #undef CQ_LDG
    #undef CQ_STS
    #undef CQ_COMP

    #pragma unroll
    for (int m = 0; m < 2; m++) {
        __half* outp = m ? ko : qo;
        const float* bp = m ? bk : bq;
        const float scl = m ? 1.0f : 0.015625f;   // fold 1/64 into Q
        #pragma unroll
        for (int ni = 0; ni < 4; ni++) {
            int col = c0 + ni * 8 + 2 * lr;
            float bv0 = bp[col], bv1 = bp[col + 1];
            int hh = col >> 6, dd = col & 63;
            #pragma unroll
            for (int h = 0; h < 2; h++) {
                int n = n0 + warp * 16 + lq + h * 8;
                int b = n >> 10, s = n & 1023;
                __half2 o2 = __floats2half2_rn((acc[m][ni][2 * h] + bv0) * scl,
                                               (acc[m][ni][2 * h + 1] + bv1) * scl);
                *(__half2*)&outp[(((size_t)(b * NHEADS + hh)) * SDIM + s) * HD + dd] = o2;
            }
        }
    }
}

// ---------------------------------------------------------------------------
// fp16 flash attention. q(pre-scaled),k [B,H,S,64] fp16; v [B,D,S] fp16.
// av output fp16.
// ---------------------------------------------------------------------------
__global__ __launch_bounds__(128) void attn_mma(const __half* __restrict__ q,
                                                const __half* __restrict__ k,
                                                const __half* __restrict__ v,
                                                __half* __restrict__ av) {
    const int s0 = blockIdx.x * 64;
    const int h  = blockIdx.y;
    const int b  = blockIdx.z;
    const __half* qb = q + (size_t)(b * NHEADS + h) * SDIM * HD;
    const __half* kb = k + (size_t)(b * NHEADS + h) * SDIM * HD;
    const __half* vb = v + (size_t)(b * NHEADS + h) * HD * SDIM;

    __shared__ uint32_t Ks[64][36];   // K tile (d-pairs), then P tile (t-pairs)
    __shared__ uint32_t Vs[64][36];

    const int tid  = threadIdx.x;
    const int lane = tid & 31;
    const int warp = tid >> 5;
    const int lq = lane >> 2;
    const int lr = lane & 3;

    // Stage Q into Ks (pure copy), pull A-fragments
    #pragma unroll
    for (int r = 0; r < 8; r++) {
        int vdx = tid + 128 * r;
        int row = vdx >> 4, col = (vdx & 15) * 4;
        uint2 x = *(const uint2*)&qb[(size_t)(s0 + row) * HD + col];
        Ks[row][col / 2 + 0] = x.x;
        Ks[row][col / 2 + 1] = x.y;
    }
    __syncthreads();
    uint32_t qf[4][4];
    #pragma unroll
    for (int ks = 0; ks < 4; ks++) {
        int w8 = ks * 8 + lr;
        int r0 = warp * 16 + lq;
        qf[ks][0] = Ks[r0][w8];
        qf[ks][1] = Ks[r0 + 8][w8];
        qf[ks][2] = Ks[r0][w8 + 4];
        qf[ks][3] = Ks[r0 + 8][w8 + 4];
    }
    __syncthreads();

    float m0v = -1e30f, m1v = -1e30f, l0 = 0.f, l1 = 0.f;
    float o[8][4];
    #pragma unroll
    for (int ni = 0; ni < 8; ni++)
        #pragma unroll
        for (int c = 0; c < 4; c++) o[ni][c] = 0.f;

    const int prow = warp * 16 + lq;

    for (int t0 = 0; t0 < SDIM; t0 += 64) {
        #pragma unroll
        for (int r = 0; r < 8; r++) {
            int vdx = tid + 128 * r;
            int row = vdx >> 4, col = (vdx & 15) * 4;
            uint2 x = *(const uint2*)&kb[(size_t)(t0 + row) * HD + col];
            Ks[row][col / 2 + 0] = x.x;
            Ks[row][col / 2 + 1] = x.y;
            uint2 y = *(const uint2*)&vb[(size_t)row * SDIM + t0 + col];
            Vs[row][col / 2 + 0] = y.x;
            Vs[row][col / 2 + 1] = y.y;
        }
        __syncthreads();

        float sc[8][4];
        #pragma unroll
        for (int ni = 0; ni < 8; ni++)
            #pragma unroll
            for (int c = 0; c < 4; c++) sc[ni][c] = 0.f;
        #pragma unroll
        for (int ks = 0; ks < 4; ks++) {
            int w8 = ks * 8 + lr;
            #pragma unroll
            for (int ni = 0; ni < 8; ni++) {
                uint32_t bb[2];
                bb[0] = Ks[ni * 8 + lq][w8];
                bb[1] = Ks[ni * 8 + lq][w8 + 4];
                mma_f16(sc[ni], qf[ks], bb);
            }
        }
        __syncthreads();

        float rm0 = -1e30f, rm1 = -1e30f;
        #pragma unroll
        for (int ni = 0; ni < 8; ni++) {
            rm0 = fmaxf(rm0, fmaxf(sc[ni][0], sc[ni][1]));
            rm1 = fmaxf(rm1, fmaxf(sc[ni][2], sc[ni][3]));
        }
        rm0 = fmaxf(rm0, __shfl_xor_sync(0xffffffffu, rm0, 1));
        rm0 = fmaxf(rm0, __shfl_xor_sync(0xffffffffu, rm0, 2));
        rm1 = fmaxf(rm1, __shfl_xor_sync(0xffffffffu, rm1, 1));
        rm1 = fmaxf(rm1, __shfl_xor_sync(0xffffffffu, rm1, 2));
        float mn0 = fmaxf(m0v, rm0), mn1 = fmaxf(m1v, rm1);
        float cr0 = __expf(m0v - mn0), cr1 = __expf(m1v - mn1);
        float rs0 = 0.f, rs1 = 0.f;
        #pragma unroll
        for (int ni = 0; ni < 8; ni++) {
            float p0 = __expf(sc[ni][0] - mn0);
            float p1 = __expf(sc[ni][1] - mn0);
            float p2 = __expf(sc[ni][2] - mn1);
            float p3 = __expf(sc[ni][3] - mn1);
            Ks[prow][ni * 4 + lr]     = f2h2(p0, p1);
            Ks[prow + 8][ni * 4 + lr] = f2h2(p2, p3);
            rs0 += p0 + p1;
            rs1 += p2 + p3;
        }
        rs0 += __shfl_xor_sync(0xffffffffu, rs0, 1);
        rs0 += __shfl_xor_sync(0xffffffffu, rs0, 2);
        rs1 += __shfl_xor_sync(0xffffffffu, rs1, 1);
        rs1 += __shfl_xor_sync(0xffffffffu, rs1, 2);
        l0 = l0 * cr0 + rs0;
        l1 = l1 * cr1 + rs1;
        m0v = mn0; m1v = mn1;
        #pragma unroll
        for (int ni = 0; ni < 8; ni++) {
            o[ni][0] *= cr0; o[ni][1] *= cr0;
            o[ni][2] *= cr1; o[ni][3] *= cr1;
        }
        __syncwarp();

        #pragma unroll
        for (int ks = 0; ks < 4; ks++) {
            int w8 = ks * 8 + lr;
            uint32_t a[4];
            a[0] = Ks[prow][w8];
            a[1] = Ks[prow + 8][w8];
            a[2] = Ks[prow][w8 + 4];
            a[3] = Ks[prow + 8][w8 + 4];
            #pragma unroll
            for (int ni = 0; ni < 8; ni++) {
                uint32_t bb[2];
                bb[0] = Vs[ni * 8 + lq][w8];
                bb[1] = Vs[ni * 8 + lq][w8 + 4];
                mma_f16(o[ni], a, bb);
            }
        }
        __syncthreads();
    }

    float inv0 = 1.0f / l0, inv1 = 1.0f / l1;
    const int rbase = s0 + warp * 16;
    #pragma unroll
    for (int ni = 0; ni < 8; ni++) {
        int col = h * HD + ni * 8 + 2 * lr;
        __half2 a = __floats2half2_rn(o[ni][0] * inv0, o[ni][1] * inv0);
        __half2 c = __floats2half2_rn(o[ni][2] * inv1, o[ni][3] * inv1);
        *(__half2*)&av[(size_t)(b * SDIM + rbase + lq) * BDIM + col]     = a;
        *(__half2*)&av[(size_t)(b * SDIM + rbase + lq + 8) * BDIM + col] = c;
    }
}

// ---------------------------------------------------------------------------
// LayerNorm over last dim (512). f32 in; templated output type.
// ---------------------------------------------------------------------------
template <typename OutT>
__global__ void ln_kernel(const float* __restrict__ in, const float* __restrict__ g,
                          const float* __restrict__ beta, OutT* __restrict__ out) {
    const int row = blockIdx.x;
    const float* x = in + (size_t)row * BDIM;
    const int tid = threadIdx.x;
    const int wid = tid >> 5, lane = tid & 31;

    float v0 = x[tid], v1 = x[tid + 256];
    __shared__ float red[8];

    float s = v0 + v1;
    #pragma unroll
    for (int off = 16; off > 0; off >>= 1)
        s += __shfl_xor_sync(0xffffffffu, s, off);
    if (lane == 0) red[wid] = s;
    __syncthreads();
    float tot = 0.f;
    #pragma unroll
    for (int i = 0; i < 8; i++) tot += red[i];
    float mu = tot * (1.0f / 512.0f);
    __syncthreads();

    float d0 = v0 - mu, d1 = v1 - mu;
    float sq = d0 * d0 + d1 * d1;
    #pragma unroll
    for (int off = 16; off > 0; off >>= 1)
        sq += __shfl_xor_sync(0xffffffffu, sq, off);
    if (lane == 0) red[wid] = sq;
    __syncthreads();
    float tot2 = 0.f;
    #pragma unroll
    for (int i = 0; i < 8; i++) tot2 += red[i];
    float rstd = rsqrtf(tot2 * (1.0f / 512.0f) + 1e-5f);

    float y0 = d0 * rstd * g[tid]       + beta[tid];
    float y1 = d1 * rstd * g[tid + 256] + beta[tid + 256];
    out[(size_t)row * BDIM + tid]       = (OutT)y0;
    out[(size_t)row * BDIM + tid + 256] = (OutT)y1;
}

// ---------------------------------------------------------------------------
extern "C" void kernel_launch(void* const* d_in, const int* in_sizes, int n_in,
                              void* d_out, int out_size) {
    const float* src = (const float*)d_in[0];
    const float* Wq  = (const float*)d_in[1];
    const float* bq  = (const float*)d_in[2];
    const float* Wk  = (const float*)d_in[3];
    const float* bk  = (const float*)d_in[4];
    const float* Wv  = (const float*)d_in[5];
    const float* bv  = (const float*)d_in[6];
    const float* Wo  = (const float*)d_in[7];
    const float* bo  = (const float*)d_in[8];
    const float* W1  = (const float*)d_in[9];
    const float* b1  = (const float*)d_in[10];
    const float* W2  = (const float*)d_in[11];
    const float* b2  = (const float*)d_in[12];
    const float* g1  = (const float*)d_in[13];
    const float* be1 = (const float*)d_in[14];
    const float* g2  = (const float*)d_in[15];
    const float* be2 = (const float*)d_in[16];
    float* out = (float*)d_out;

    float *t1;
    __half *srch, *q, *k, *v, *av, *x1, *ff, *wt, *wc;
    cudaGetSymbolAddress((void**)&srch, g_srch);
    cudaGetSymbolAddress((void**)&q,  g_q);
    cudaGetSymbolAddress((void**)&k,  g_k);
    cudaGetSymbolAddress((void**)&v,  g_v);
    cudaGetSymbolAddress((void**)&av, g_av);
    cudaGetSymbolAddress((void**)&t1, g_t1);
    cudaGetSymbolAddress((void**)&x1, g_x1);
    cudaGetSymbolAddress((void**)&ff, g_ff);
    cudaGetSymbolAddress((void**)&wt, g_wt);
    cudaGetSymbolAddress((void**)&wc, g_wc);

    wprep_kernel<<<(WPREP_TOTAL + 255) / 256, 256>>>(Wq, Wk, Wv, Wo, W1, W2, src, wt, wc, srch);

    convqk<<<dim3(NTOK / 128, BDIM / 32), 256>>>(srch, wt, bq, bk, q, k);
    gemm2<3><<<dim3(NTOK / 128, BDIM / 64), 256>>>(srch, wc + WC_WV, bv, nullptr, v, BDIM, BDIM);

    attn_mma<<<dim3(SDIM / 64, NHEADS, BATCH), 128>>>(q, k, v, av);

    gemm2<0><<<dim3(NTOK / 128, BDIM / 64), 256>>>(av, wc + WC_WO, bo, src, t1, BDIM, BDIM);
    ln_kernel<__half><<<NTOK, 256>>>(t1, g1, be1, x1);

    gemm2<1><<<dim3(NTOK / 128, DFF / 64), 256>>>(x1, wc + WC_W1, b1, nullptr, ff, DFF, BDIM);
    gemm2<2><<<dim3(NTOK / 128, BDIM / 64), 256>>>(ff, wc + WC_W2, b2, x1, t1, BDIM, DFF);
    ln_kernel<float><<<NTOK, 256>>>(t1, g2, be2, out);
}

// round 11
// speedup vs baseline: 2.3200x; 1.4378x over previous
#include <cuda_runtime.h>
#include <cuda_fp16.h>
#include <math.h>
#include <stdint.h>

#define BDIM   512
#define SDIM   1024
#define BATCH  8
#define NHEADS 8
#define HD     64
#define DFF    2048
#define NTOK   (BATCH * SDIM)   // 8192

// Scratch
__device__ __half g_srch[NTOK * BDIM];         // fp16 copy of src
__device__ __half g_q [BATCH * BDIM * SDIM];   // [B,H,S,64], pre-scaled by 1/64
__device__ __half g_k [BATCH * BDIM * SDIM];   // [B,H,S,64]
__device__ __half g_v [BATCH * BDIM * SDIM];   // [B,D,S]
__device__ __half g_av[NTOK * BDIM];
__device__ float  g_t1[NTOK * BDIM];
__device__ __half g_x1[NTOK * BDIM];
__device__ __half g_ff[NTOK * DFF];
__device__ __half g_wt[2 * 3 * BDIM * BDIM];                  // fp16 Wq/Wk: [mat][tap][co][ci]
__device__ __half g_wc[2 * BDIM * BDIM + 2 * DFF * BDIM];     // fp16 Wv,Wo,W1,W2

#define WC_WV 0
#define WC_WO (BDIM * BDIM)
#define WC_W1 (2 * BDIM * BDIM)
#define WC_W2 (2 * BDIM * BDIM + DFF * BDIM)

__device__ __forceinline__ uint32_t f2h2(float lo, float hi) {
    __half2 h = __floats2half2_rn(lo, hi);
    return *reinterpret_cast<uint32_t*>(&h);
}

__device__ __forceinline__ void mma_f16(float c[4], const uint32_t a[4], const uint32_t b[2]) {
    asm volatile(
        "mma.sync.aligned.m16n8k16.row.col.f32.f16.f16.f32 "
        "{%0,%1,%2,%3}, {%4,%5,%6,%7}, {%8,%9}, {%0,%1,%2,%3};"
        : "+f"(c[0]), "+f"(c[1]), "+f"(c[2]), "+f"(c[3])
        : "r"(a[0]), "r"(a[1]), "r"(a[2]), "r"(a[3]), "r"(b[0]), "r"(b[1]));
}

__device__ __forceinline__ uint32_t smem_u32(const void* p) {
    uint32_t a;
    asm("{ .reg .u64 t; cvta.to.shared.u64 t, %1; cvt.u32.u64 %0, t; }" : "=r"(a) : "l"(p));
    return a;
}

#define CP16(dst, src) \
    asm volatile("cp.async.cg.shared.global [%0], [%1], 16;" :: "r"(dst), "l"(src))
#define CP16Z(dst, src, sz) \
    asm volatile("cp.async.cg.shared.global [%0], [%1], 16, %2;" :: "r"(dst), "l"(src), "r"(sz))
#define CP_COMMIT() asm volatile("cp.async.commit_group;")
#define CP_WAIT1()  asm volatile("cp.async.wait_group 1;")

#define LDSM_X4(R, ADDR) \
    asm volatile("ldmatrix.sync.aligned.m8n8.x4.shared.b16 {%0,%1,%2,%3}, [%4];" \
                 : "=r"((R)[0]), "=r"((R)[1]), "=r"((R)[2]), "=r"((R)[3]) : "r"(ADDR))

// ---------------------------------------------------------------------------
// Merged prep: all weight conversions + src->fp16, one launch.
// ---------------------------------------------------------------------------
#define WTN (2 * 3 * BDIM * BDIM)
#define WPREP_TOTAL (WTN + 2 * BDIM * BDIM + 2 * DFF * BDIM + NTOK * BDIM)
__global__ void wprep_kernel(const float* __restrict__ Wq, const float* __restrict__ Wk,
                             const float* __restrict__ Wv, const float* __restrict__ Wo,
                             const float* __restrict__ W1, const float* __restrict__ W2,
                             const float* __restrict__ src,
                             __half* __restrict__ wt, __half* __restrict__ wc,
                             __half* __restrict__ srch) {
    int e = blockIdx.x * 256 + threadIdx.x;
    if (e < WTN) {
        int m  = (e >= 3 * BDIM * BDIM);
        int e2 = e - m * 3 * BDIM * BDIM;
        int t  = e2 >> 18;
        int co = (e2 >> 9) & 511;
        int ci = e2 & 511;
        const float* s = m ? Wk : Wq;
        wt[e] = __float2half_rn(s[(size_t)co * 1536 + ci * 3 + t]);
        return;
    }
    int f = e - WTN;
    if (f < BDIM * BDIM)            { wc[WC_WV + f] = __float2half_rn(Wv[f]); return; }
    f -= BDIM * BDIM;
    if (f < BDIM * BDIM)            { wc[WC_WO + f] = __float2half_rn(Wo[f]); return; }
    f -= BDIM * BDIM;
    if (f < DFF * BDIM)             { wc[WC_W1 + f] = __float2half_rn(W1[f]); return; }
    f -= DFF * BDIM;
    if (f < DFF * BDIM)             { wc[WC_W2 + f] = __float2half_rn(W2[f]); return; }
    f -= DFF * BDIM;
    if (f < NTOK * BDIM)            { srch[f] = __float2half_rn(src[f]); return; }
}

// ===========================================================================
// gemm3: fp16 GEMM, cp.async + ldmatrix. Block 128(n) x 64(m), 8 warps
// (32x32 each), KT=32, 3-stage cp.async ring (one wait + one sync per stage).
// Smem rows: 32 halves (64B) at 80B stride -> conflict-free ldmatrix.
// MODE 0: +res(f32) -> f32 | 1: relu -> fp16 | 2: +res(fp16) -> f32
// MODE 3: scatter [B,D,S] fp16 (bias only)
// ===========================================================================
#define G3_ASTRIDE 10240   // 128 rows * 80B
#define G3_BSTRIDE 5120    // 64 rows * 80B

template <int MODE>
__global__ __launch_bounds__(256) void gemm3(const __half* __restrict__ A,
                                             const __half* __restrict__ W,
                                             const float* __restrict__ bias,
                                             const void* __restrict__ resv,
                                             void* __restrict__ outv, int M, int K) {
    __shared__ __align__(16) char Asm[3 * G3_ASTRIDE];
    __shared__ __align__(16) char Bsm[3 * G3_BSTRIDE];

    const int n0 = blockIdx.x * 128;
    const int m0 = blockIdx.y * 64;
    const int tid = threadIdx.x, lane = tid & 31, warp = tid >> 5;
    const int lq = lane >> 2, lr = lane & 3;
    const int nk = K >> 5;

    const uint32_t aBase = smem_u32(Asm);
    const uint32_t bBase = smem_u32(Bsm);

    // cp.async source/dest (row = tid>>2, chunk = tid&3 covering 8 halves)
    const int crow = tid >> 2, cc = tid & 3;
    const __half* aSrc0 = A + (size_t)(n0 + crow) * K + cc * 8;
    const __half* aSrc1 = A + (size_t)(n0 + crow + 64) * K + cc * 8;
    const __half* bSrc  = W + (size_t)(m0 + crow) * K + cc * 8;
    const uint32_t aDst0 = aBase + crow * 80 + cc * 16;
    const uint32_t aDst1 = aDst0 + 64 * 80;
    const uint32_t bDst  = bBase + crow * 80 + cc * 16;

    // ldmatrix fragment addresses
    const int wiB = (warp >> 1) * 32;     // A row base
    const int wjB = (warp & 1) * 32;      // B row (n) base
    const uint32_t aAddr0 = aBase + (wiB + (lane & 15)) * 80 + (lane >> 4) * 16;
    const uint32_t aAddr1 = aAddr0 + 16 * 80;
    const int bRowOff = (lane & 7) + ((lane >> 4) << 3);
    const int bColB   = ((lane >> 3) & 1) * 16;
    const uint32_t bAddr0 = bBase + (wjB + bRowOff) * 80 + bColB;
    const uint32_t bAddr1 = bAddr0 + 16 * 80;

    float acc[2][4][4];
    #pragma unroll
    for (int mi = 0; mi < 2; mi++)
        #pragma unroll
        for (int ni = 0; ni < 4; ni++)
            #pragma unroll
            for (int c = 0; c < 4; c++) acc[mi][ni][c] = 0.f;

    #define G3_ISSUE(ST, KB)                                                          \
        { size_t o = (size_t)(KB) * 32;                                               \
          CP16(aDst0 + (ST) * G3_ASTRIDE, aSrc0 + o);                                 \
          CP16(aDst1 + (ST) * G3_ASTRIDE, aSrc1 + o);                                 \
          CP16(bDst  + (ST) * G3_BSTRIDE, bSrc  + o); }

    G3_ISSUE(0, 0) CP_COMMIT();
    G3_ISSUE(1, 1) CP_COMMIT();

    int stC = 0, stI = 2;
    for (int kb = 0; kb < nk; kb++) {
        CP_WAIT1();
        __syncthreads();
        if (kb + 2 < nk) G3_ISSUE(stI, kb + 2)
        CP_COMMIT();

        const uint32_t oA = stC * G3_ASTRIDE, oB = stC * G3_BSTRIDE;
        #pragma unroll
        for (int ks = 0; ks < 2; ks++) {
            uint32_t a0[4], a1[4], b0[4], b1[4];
            LDSM_X4(a0, aAddr0 + oA + ks * 32);
            LDSM_X4(a1, aAddr1 + oA + ks * 32);
            LDSM_X4(b0, bAddr0 + oB + ks * 32);
            LDSM_X4(b1, bAddr1 + oB + ks * 32);
            mma_f16(acc[0][0], a0, b0 + 0);
            mma_f16(acc[1][0], a1, b0 + 0);
            mma_f16(acc[0][1], a0, b0 + 2);
            mma_f16(acc[1][1], a1, b0 + 2);
            mma_f16(acc[0][2], a0, b1 + 0);
            mma_f16(acc[1][2], a1, b1 + 0);
            mma_f16(acc[0][3], a0, b1 + 2);
            mma_f16(acc[1][3], a1, b1 + 2);
        }
        stC = (stC == 2) ? 0 : stC + 1;
        stI = (stI == 2) ? 0 : stI + 1;
    }
    #undef G3_ISSUE

    #pragma unroll
    for (int mi = 0; mi < 2; mi++) {
        #pragma unroll
        for (int ni = 0; ni < 4; ni++) {
            int col = m0 + wjB + ni * 8 + 2 * lr;
            float bv0 = bias[col], bv1 = bias[col + 1];
            #pragma unroll
            for (int h = 0; h < 2; h++) {
                int n = n0 + wiB + mi * 16 + lq + h * 8;
                float x0 = acc[mi][ni][2 * h] + bv0;
                float x1 = acc[mi][ni][2 * h + 1] + bv1;
                if (MODE == 1) { x0 = fmaxf(x0, 0.f); x1 = fmaxf(x1, 0.f); }
                if (MODE == 0) {
                    const float* res = (const float*)resv;
                    x0 += res[(size_t)n * M + col];
                    x1 += res[(size_t)n * M + col + 1];
                }
                if (MODE == 2) {
                    const __half* res = (const __half*)resv;
                    float2 rf = __half22float2(*(const __half2*)&res[(size_t)n * M + col]);
                    x0 += rf.x; x1 += rf.y;
                }
                if (MODE == 3) {
                    __half* out = (__half*)outv;
                    int b = n >> 10, s = n & 1023;
                    out[((size_t)(b * BDIM + col)) * SDIM + s]     = __float2half_rn(x0);
                    out[((size_t)(b * BDIM + col + 1)) * SDIM + s] = __float2half_rn(x1);
                } else if (MODE == 1) {
                    __half* out = (__half*)outv;
                    *(__half2*)&out[(size_t)n * M + col] = __floats2half2_rn(x0, x1);
                } else {
                    float* out = (float*)outv;
                    *(float2*)&out[(size_t)n * M + col] = make_float2(x0, x1);
                }
            }
        }
    }
}

// ===========================================================================
// convqk3: fused Q+K conv, cp.async + ldmatrix. Block 128(tok) x 32(co) x
// 2 mats, 48 stages (3 taps x 16 kb), 3-stage ring, zfill at seq edges.
// B smem rows 0-31 = mat0 (Wq), 32-63 = mat1 (Wk).
// ===========================================================================
__global__ __launch_bounds__(256) void convqk3(const __half* __restrict__ A,
                                               const __half* __restrict__ Wt,
                                               const float* __restrict__ bq,
                                               const float* __restrict__ bk,
                                               __half* __restrict__ qo,
                                               __half* __restrict__ ko) {
    __shared__ __align__(16) char Asm[3 * G3_ASTRIDE];
    __shared__ __align__(16) char Bsm[3 * G3_BSTRIDE];

    const int n0 = blockIdx.x * 128;
    const int c0 = blockIdx.y * 32;
    const int tid = threadIdx.x, lane = tid & 31, warp = tid >> 5;
    const int lq = lane >> 2, lr = lane & 3;
    const int NST = 48;

    const uint32_t aBase = smem_u32(Asm);
    const uint32_t bBase = smem_u32(Bsm);

    const int crow = tid >> 2, cc = tid & 3;
    const uint32_t aDst0 = aBase + crow * 80 + cc * 16;
    const uint32_t aDst1 = aDst0 + 64 * 80;
    const uint32_t bDst  = bBase + crow * 80 + cc * 16;
    const int bMat = crow >> 5, bCo = c0 + (crow & 31);

    const uint32_t aAddr = aBase + (warp * 16 + (lane & 15)) * 80 + (lane >> 4) * 16;
    const int bRowOff = (lane & 7) + ((lane >> 4) << 3);
    const int bColB   = ((lane >> 3) & 1) * 16;
    const uint32_t bAddrM0 = bBase + bRowOff * 80 + bColB;          // mat0 n0-15
    const uint32_t bAddrM0b = bAddrM0 + 16 * 80;                    // mat0 n16-31
    const uint32_t bAddrM1 = bBase + (32 + bRowOff) * 80 + bColB;   // mat1
    const uint32_t bAddrM1b = bAddrM1 + 16 * 80;

    float acc[2][4][4];
    #pragma unroll
    for (int m = 0; m < 2; m++)
        #pragma unroll
        for (int ni = 0; ni < 4; ni++)
            #pragma unroll
            for (int c = 0; c < 4; c++) acc[m][ni][c] = 0.f;

    #define CQ_ISSUE(ST, T)                                                           \
        { int t_ = (T);                                                               \
          int tap_ = t_ >> 4; size_t ko_ = (size_t)(t_ & 15) * 32;                    \
          int roff_ = tap_ - 1;                                                       \
          { int n = n0 + crow; int s = (n & 1023) + roff_;                            \
            uint32_t sz = ((unsigned)s < 1024u) ? 16u : 0u;                           \
            int sc = s < 0 ? 0 : (s > 1023 ? 1023 : s);                               \
            const __half* sp = A + ((size_t)(n & ~1023) + sc) * BDIM + ko_ + cc * 8;  \
            CP16Z(aDst0 + (ST) * G3_ASTRIDE, sp, sz); }                               \
          { int n = n0 + crow + 64; int s = (n & 1023) + roff_;                       \
            uint32_t sz = ((unsigned)s < 1024u) ? 16u : 0u;                           \
            int sc = s < 0 ? 0 : (s > 1023 ? 1023 : s);                               \
            const __half* sp = A + ((size_t)(n & ~1023) + sc) * BDIM + ko_ + cc * 8;  \
            CP16Z(aDst1 + (ST) * G3_ASTRIDE, sp, sz); }                               \
          { const __half* sp = Wt + ((size_t)(bMat * 3 + tap_) * BDIM + bCo) * BDIM + ko_ + cc * 8; \
            CP16(bDst + (ST) * G3_BSTRIDE, sp); } }

    CQ_ISSUE(0, 0) CP_COMMIT();
    CQ_ISSUE(1, 1) CP_COMMIT();

    int stC = 0, stI = 2;
    for (int t = 0; t < NST; t++) {
        CP_WAIT1();
        __syncthreads();
        if (t + 2 < NST) CQ_ISSUE(stI, t + 2)
        CP_COMMIT();

        const uint32_t oA = stC * G3_ASTRIDE, oB = stC * G3_BSTRIDE;
        #pragma unroll
        for (int ks = 0; ks < 2; ks++) {
            uint32_t a[4], b00[4], b01[4], b10[4], b11[4];
            LDSM_X4(a, aAddr + oA + ks * 32);
            LDSM_X4(b00, bAddrM0  + oB + ks * 32);
            LDSM_X4(b01, bAddrM0b + oB + ks * 32);
            LDSM_X4(b10, bAddrM1  + oB + ks * 32);
            LDSM_X4(b11, bAddrM1b + oB + ks * 32);
            mma_f16(acc[0][0], a, b00 + 0);
            mma_f16(acc[0][1], a, b00 + 2);
            mma_f16(acc[0][2], a, b01 + 0);
            mma_f16(acc[0][3], a, b01 + 2);
            mma_f16(acc[1][0], a, b10 + 0);
            mma_f16(acc[1][1], a, b10 + 2);
            mma_f16(acc[1][2], a, b11 + 0);
            mma_f16(acc[1][3], a, b11 + 2);
        }
        stC = (stC == 2) ? 0 : stC + 1;
        stI = (stI == 2) ? 0 : stI + 1;
    }
    #undef CQ_ISSUE

    #pragma unroll
    for (int m = 0; m < 2; m++) {
        __half* outp = m ? ko : qo;
        const float* bp = m ? bk : bq;
        const float scl = m ? 1.0f : 0.015625f;   // fold 1/64 into Q
        #pragma unroll
        for (int ni = 0; ni < 4; ni++) {
            int col = c0 + ni * 8 + 2 * lr;
            float bv0 = bp[col], bv1 = bp[col + 1];
            int hh = col >> 6, dd = col & 63;
            #pragma unroll
            for (int h = 0; h < 2; h++) {
                int n = n0 + warp * 16 + lq + h * 8;
                int b = n >> 10, s = n & 1023;
                __half2 o2 = __floats2half2_rn((acc[m][ni][2 * h] + bv0) * scl,
                                               (acc[m][ni][2 * h + 1] + bv1) * scl);
                *(__half2*)&outp[(((size_t)(b * NHEADS + hh)) * SDIM + s) * HD + dd] = o2;
            }
        }
    }
}

// ---------------------------------------------------------------------------
// fp16 flash attention (R10-exact). q(pre-scaled),k [B,H,S,64]; v [B,D,S].
// ---------------------------------------------------------------------------
__global__ __launch_bounds__(128) void attn_mma(const __half* __restrict__ q,
                                                const __half* __restrict__ k,
                                                const __half* __restrict__ v,
                                                __half* __restrict__ av) {
    const int s0 = blockIdx.x * 64;
    const int h  = blockIdx.y;
    const int b  = blockIdx.z;
    const __half* qb = q + (size_t)(b * NHEADS + h) * SDIM * HD;
    const __half* kb = k + (size_t)(b * NHEADS + h) * SDIM * HD;
    const __half* vb = v + (size_t)(b * NHEADS + h) * HD * SDIM;

    __shared__ uint32_t Ks[64][36];
    __shared__ uint32_t Vs[64][36];

    const int tid  = threadIdx.x;
    const int lane = tid & 31;
    const int warp = tid >> 5;
    const int lq = lane >> 2;
    const int lr = lane & 3;

    #pragma unroll
    for (int r = 0; r < 8; r++) {
        int vdx = tid + 128 * r;
        int row = vdx >> 4, col = (vdx & 15) * 4;
        uint2 x = *(const uint2*)&qb[(size_t)(s0 + row) * HD + col];
        Ks[row][col / 2 + 0] = x.x;
        Ks[row][col / 2 + 1] = x.y;
    }
    __syncthreads();
    uint32_t qf[4][4];
    #pragma unroll
    for (int ks = 0; ks < 4; ks++) {
        int w8 = ks * 8 + lr;
        int r0 = warp * 16 + lq;
        qf[ks][0] = Ks[r0][w8];
        qf[ks][1] = Ks[r0 + 8][w8];
        qf[ks][2] = Ks[r0][w8 + 4];
        qf[ks][3] = Ks[r0 + 8][w8 + 4];
    }
    __syncthreads();

    float m0v = -1e30f, m1v = -1e30f, l0 = 0.f, l1 = 0.f;
    float o[8][4];
    #pragma unroll
    for (int ni = 0; ni < 8; ni++)
        #pragma unroll
        for (int c = 0; c < 4; c++) o[ni][c] = 0.f;

    const int prow = warp * 16 + lq;

    for (int t0 = 0; t0 < SDIM; t0 += 64) {
        #pragma unroll
        for (int r = 0; r < 8; r++) {
            int vdx = tid + 128 * r;
            int row = vdx >> 4, col = (vdx & 15) * 4;
            uint2 x = *(const uint2*)&kb[(size_t)(t0 + row) * HD + col];
            Ks[row][col / 2 + 0] = x.x;
            Ks[row][col / 2 + 1] = x.y;
            uint2 y = *(const uint2*)&vb[(size_t)row * SDIM + t0 + col];
            Vs[row][col / 2 + 0] = y.x;
            Vs[row][col / 2 + 1] = y.y;
        }
        __syncthreads();

        float sc[8][4];
        #pragma unroll
        for (int ni = 0; ni < 8; ni++)
            #pragma unroll
            for (int c = 0; c < 4; c++) sc[ni][c] = 0.f;
        #pragma unroll
        for (int ks = 0; ks < 4; ks++) {
            int w8 = ks * 8 + lr;
            #pragma unroll
            for (int ni = 0; ni < 8; ni++) {
                uint32_t bb[2];
                bb[0] = Ks[ni * 8 + lq][w8];
                bb[1] = Ks[ni * 8 + lq][w8 + 4];
                mma_f16(sc[ni], qf[ks], bb);
            }
        }
        __syncthreads();

        float rm0 = -1e30f, rm1 = -1e30f;
        #pragma unroll
        for (int ni = 0; ni < 8; ni++) {
            rm0 = fmaxf(rm0, fmaxf(sc[ni][0], sc[ni][1]));
            rm1 = fmaxf(rm1, fmaxf(sc[ni][2], sc[ni][3]));
        }
        rm0 = fmaxf(rm0, __shfl_xor_sync(0xffffffffu, rm0, 1));
        rm0 = fmaxf(rm0, __shfl_xor_sync(0xffffffffu, rm0, 2));
        rm1 = fmaxf(rm1, __shfl_xor_sync(0xffffffffu, rm1, 1));
        rm1 = fmaxf(rm1, __shfl_xor_sync(0xffffffffu, rm1, 2));
        float mn0 = fmaxf(m0v, rm0), mn1 = fmaxf(m1v, rm1);
        float cr0 = __expf(m0v - mn0), cr1 = __expf(m1v - mn1);
        float rs0 = 0.f, rs1 = 0.f;
        #pragma unroll
        for (int ni = 0; ni < 8; ni++) {
            float p0 = __expf(sc[ni][0] - mn0);
            float p1 = __expf(sc[ni][1] - mn0);
            float p2 = __expf(sc[ni][2] - mn1);
            float p3 = __expf(sc[ni][3] - mn1);
            Ks[prow][ni * 4 + lr]     = f2h2(p0, p1);
            Ks[prow + 8][ni * 4 + lr] = f2h2(p2, p3);
            rs0 += p0 + p1;
            rs1 += p2 + p3;
        }
        rs0 += __shfl_xor_sync(0xffffffffu, rs0, 1);
        rs0 += __shfl_xor_sync(0xffffffffu, rs0, 2);
        rs1 += __shfl_xor_sync(0xffffffffu, rs1, 1);
        rs1 += __shfl_xor_sync(0xffffffffu, rs1, 2);
        l0 = l0 * cr0 + rs0;
        l1 = l1 * cr1 + rs1;
        m0v = mn0; m1v = mn1;
        #pragma unroll
        for (int ni = 0; ni < 8; ni++) {
            o[ni][0] *= cr0; o[ni][1] *= cr0;
            o[ni][2] *= cr1; o[ni][3] *= cr1;
        }
        __syncwarp();

        #pragma unroll
        for (int ks = 0; ks < 4; ks++) {
            int w8 = ks * 8 + lr;
            uint32_t a[4];
            a[0] = Ks[prow][w8];
            a[1] = Ks[prow + 8][w8];
            a[2] = Ks[prow][w8 + 4];
            a[3] = Ks[prow + 8][w8 + 4];
            #pragma unroll
            for (int ni = 0; ni < 8; ni++) {
                uint32_t bb[2];
                bb[0] = Vs[ni * 8 + lq][w8];
                bb[1] = Vs[ni * 8 + lq][w8 + 4];
                mma_f16(o[ni], a, bb);
            }
        }
        __syncthreads();
    }

    float inv0 = 1.0f / l0, inv1 = 1.0f / l1;
    const int rbase = s0 + warp * 16;
    #pragma unroll
    for (int ni = 0; ni < 8; ni++) {
        int col = h * HD + ni * 8 + 2 * lr;
        __half2 a = __floats2half2_rn(o[ni][0] * inv0, o[ni][1] * inv0);
        __half2 c = __floats2half2_rn(o[ni][2] * inv1, o[ni][3] * inv1);
        *(__half2*)&av[(size_t)(b * SDIM + rbase + lq) * BDIM + col]     = a;
        *(__half2*)&av[(size_t)(b * SDIM + rbase + lq + 8) * BDIM + col] = c;
    }
}

// ---------------------------------------------------------------------------
// LayerNorm over last dim (512). f32 in; templated output type.
// ---------------------------------------------------------------------------
template <typename OutT>
__global__ void ln_kernel(const float* __restrict__ in, const float* __restrict__ g,
                          const float* __restrict__ beta, OutT* __restrict__ out) {
    const int row = blockIdx.x;
    const float* x = in + (size_t)row * BDIM;
    const int tid = threadIdx.x;
    const int wid = tid >> 5, lane = tid & 31;

    float v0 = x[tid], v1 = x[tid + 256];
    __shared__ float red[8];

    float s = v0 + v1;
    #pragma unroll
    for (int off = 16; off > 0; off >>= 1)
        s += __shfl_xor_sync(0xffffffffu, s, off);
    if (lane == 0) red[wid] = s;
    __syncthreads();
    float tot = 0.f;
    #pragma unroll
    for (int i = 0; i < 8; i++) tot += red[i];
    float mu = tot * (1.0f / 512.0f);
    __syncthreads();

    float d0 = v0 - mu, d1 = v1 - mu;
    float sq = d0 * d0 + d1 * d1;
    #pragma unroll
    for (int off = 16; off > 0; off >>= 1)
        sq += __shfl_xor_sync(0xffffffffu, sq, off);
    if (lane == 0) red[wid] = sq;
    __syncthreads();
    float tot2 = 0.f;
    #pragma unroll
    for (int i = 0; i < 8; i++) tot2 += red[i];
    float rstd = rsqrtf(tot2 * (1.0f / 512.0f) + 1e-5f);

    float y0 = d0 * rstd * g[tid]       + beta[tid];
    float y1 = d1 * rstd * g[tid + 256] + beta[tid + 256];
    out[(size_t)row * BDIM + tid]       = (OutT)y0;
    out[(size_t)row * BDIM + tid + 256] = (OutT)y1;
}

// ---------------------------------------------------------------------------
extern "C" void kernel_launch(void* const* d_in, const int* in_sizes, int n_in,
                              void* d_out, int out_size) {
    const float* src = (const float*)d_in[0];
    const float* Wq  = (const float*)d_in[1];
    const float* bq  = (const float*)d_in[2];
    const float* Wk  = (const float*)d_in[3];
    const float* bk  = (const float*)d_in[4];
    const float* Wv  = (const float*)d_in[5];
    const float* bv  = (const float*)d_in[6];
    const float* Wo  = (const float*)d_in[7];
    const float* bo  = (const float*)d_in[8];
    const float* W1  = (const float*)d_in[9];
    const float* b1  = (const float*)d_in[10];
    const float* W2  = (const float*)d_in[11];
    const float* b2  = (const float*)d_in[12];
    const float* g1  = (const float*)d_in[13];
    const float* be1 = (const float*)d_in[14];
    const float* g2  = (const float*)d_in[15];
    const float* be2 = (const float*)d_in[16];
    float* out = (float*)d_out;

    float *t1;
    __half *srch, *q, *k, *v, *av, *x1, *ff, *wt, *wc;
    cudaGetSymbolAddress((void**)&srch, g_srch);
    cudaGetSymbolAddress((void**)&q,  g_q);
    cudaGetSymbolAddress((void**)&k,  g_k);
    cudaGetSymbolAddress((void**)&v,  g_v);
    cudaGetSymbolAddress((void**)&av, g_av);
    cudaGetSymbolAddress((void**)&t1, g_t1);
    cudaGetSymbolAddress((void**)&x1, g_x1);
    cudaGetSymbolAddress((void**)&ff, g_ff);
    cudaGetSymbolAddress((void**)&wt, g_wt);
    cudaGetSymbolAddress((void**)&wc, g_wc);

    wprep_kernel<<<(WPREP_TOTAL + 255) / 256, 256>>>(Wq, Wk, Wv, Wo, W1, W2, src, wt, wc, srch);

    convqk3<<<dim3(NTOK / 128, BDIM / 32), 256>>>(srch, wt, bq, bk, q, k);
    gemm3<3><<<dim3(NTOK / 128, BDIM / 64), 256>>>(srch, wc + WC_WV, bv, nullptr, v, BDIM, BDIM);

    attn_mma<<<dim3(SDIM / 64, NHEADS, BATCH), 128>>>(q, k, v, av);

    gemm3<0><<<dim3(NTOK / 128, BDIM / 64), 256>>>(av, wc + WC_WO, bo, src, t1, BDIM, BDIM);
    ln_kernel<__half><<<NTOK, 256>>>(t1, g1, be1, x1);

    gemm3<1><<<dim3(NTOK / 128, DFF / 64), 256>>>(x1, wc + WC_W1, b1, nullptr, ff, DFF, BDIM);
    gemm3<2><<<dim3(NTOK / 128, BDIM / 64), 256>>>(ff, wc + WC_W2, b2, x1, t1, BDIM, DFF);
    ln_kernel<float><<<NTOK, 256>>>(t1, g2, be2, out);
}

// round 12
// speedup vs baseline: 2.3924x; 1.0312x over previous
#include <cuda_runtime.h>
#include <cuda_fp16.h>
#include <math.h>
#include <stdint.h>

#define BDIM   512
#define SDIM   1024
#define BATCH  8
#define NHEADS 8
#define HD     64
#define DFF    2048
#define NTOK   (BATCH * SDIM)   // 8192

// Scratch
__device__ __half g_srch[NTOK * BDIM];         // fp16 copy of src
__device__ __half g_q [BATCH * BDIM * SDIM];   // [B,H,S,64], pre-scaled by 1/64
__device__ __half g_k [BATCH * BDIM * SDIM];   // [B,H,S,64]
__device__ __half g_v [BATCH * BDIM * SDIM];   // [B,D,S]
__device__ __half g_av[NTOK * BDIM];
__device__ float  g_t1[NTOK * BDIM];
__device__ __half g_x1[NTOK * BDIM];
__device__ __half g_ff[NTOK * DFF];
__device__ __half g_wt[2 * 3 * BDIM * BDIM];                  // fp16 Wq/Wk: [mat][tap][co][ci]
__device__ __half g_wc[2 * BDIM * BDIM + 2 * DFF * BDIM];     // fp16 Wv,Wo,W1,W2

#define WC_WV 0
#define WC_WO (BDIM * BDIM)
#define WC_W1 (2 * BDIM * BDIM)
#define WC_W2 (2 * BDIM * BDIM + DFF * BDIM)

__device__ __forceinline__ uint32_t f2h2(float lo, float hi) {
    __half2 h = __floats2half2_rn(lo, hi);
    return *reinterpret_cast<uint32_t*>(&h);
}

__device__ __forceinline__ void mma_f16(float c[4], const uint32_t a[4], const uint32_t b[2]) {
    asm volatile(
        "mma.sync.aligned.m16n8k16.row.col.f32.f16.f16.f32 "
        "{%0,%1,%2,%3}, {%4,%5,%6,%7}, {%8,%9}, {%0,%1,%2,%3};"
        : "+f"(c[0]), "+f"(c[1]), "+f"(c[2]), "+f"(c[3])
        : "r"(a[0]), "r"(a[1]), "r"(a[2]), "r"(a[3]), "r"(b[0]), "r"(b[1]));
}

__device__ __forceinline__ uint32_t smem_u32(const void* p) {
    uint32_t a;
    asm("{ .reg .u64 t; cvta.to.shared.u64 t, %1; cvt.u32.u64 %0, t; }" : "=r"(a) : "l"(p));
    return a;
}

#define CP16(dst, src) \
    asm volatile("cp.async.cg.shared.global [%0], [%1], 16;" :: "r"(dst), "l"(src))
#define CP16Z(dst, src, sz) \
    asm volatile("cp.async.cg.shared.global [%0], [%1], 16, %2;" :: "r"(dst), "l"(src), "r"(sz))
#define CP_COMMIT() asm volatile("cp.async.commit_group;")
#define CP_WAIT1()  asm volatile("cp.async.wait_group 1;")
#define CP_WAIT0()  asm volatile("cp.async.wait_group 0;")

#define LDSM_X4(R, ADDR) \
    asm volatile("ldmatrix.sync.aligned.m8n8.x4.shared.b16 {%0,%1,%2,%3}, [%4];" \
                 : "=r"((R)[0]), "=r"((R)[1]), "=r"((R)[2]), "=r"((R)[3]) : "r"(ADDR))

// ---------------------------------------------------------------------------
// Merged prep: all weight conversions + src->fp16, one launch.
// ---------------------------------------------------------------------------
#define WTN (2 * 3 * BDIM * BDIM)
#define WPREP_TOTAL (WTN + 2 * BDIM * BDIM + 2 * DFF * BDIM + NTOK * BDIM)
__global__ void wprep_kernel(const float* __restrict__ Wq, const float* __restrict__ Wk,
                             const float* __restrict__ Wv, const float* __restrict__ Wo,
                             const float* __restrict__ W1, const float* __restrict__ W2,
                             const float* __restrict__ src,
                             __half* __restrict__ wt, __half* __restrict__ wc,
                             __half* __restrict__ srch) {
    int e = blockIdx.x * 256 + threadIdx.x;
    if (e < WTN) {
        int m  = (e >= 3 * BDIM * BDIM);
        int e2 = e - m * 3 * BDIM * BDIM;
        int t  = e2 >> 18;
        int co = (e2 >> 9) & 511;
        int ci = e2 & 511;
        const float* s = m ? Wk : Wq;
        wt[e] = __float2half_rn(s[(size_t)co * 1536 + ci * 3 + t]);
        return;
    }
    int f = e - WTN;
    if (f < BDIM * BDIM)            { wc[WC_WV + f] = __float2half_rn(Wv[f]); return; }
    f -= BDIM * BDIM;
    if (f < BDIM * BDIM)            { wc[WC_WO + f] = __float2half_rn(Wo[f]); return; }
    f -= BDIM * BDIM;
    if (f < DFF * BDIM)             { wc[WC_W1 + f] = __float2half_rn(W1[f]); return; }
    f -= DFF * BDIM;
    if (f < DFF * BDIM)             { wc[WC_W2 + f] = __float2half_rn(W2[f]); return; }
    f -= DFF * BDIM;
    if (f < NTOK * BDIM)            { srch[f] = __float2half_rn(src[f]); return; }
}

// ===========================================================================
// gemm3: fp16 GEMM, cp.async + ldmatrix. Block 128(n) x 64(m), 8 warps
// (32x32 each), KT=32, 3-stage cp.async ring.
// MODE 0: +res(f32) -> f32 | 1: relu -> fp16 | 2: +res(fp16) -> f32
// MODE 3: scatter [B,D,S] fp16 (bias only)
// ===========================================================================
#define G3_ASTRIDE 10240   // 128 rows * 80B
#define G3_BSTRIDE 5120    // 64 rows * 80B

template <int MODE>
__global__ __launch_bounds__(256) void gemm3(const __half* __restrict__ A,
                                             const __half* __restrict__ W,
                                             const float* __restrict__ bias,
                                             const void* __restrict__ resv,
                                             void* __restrict__ outv, int M, int K) {
    __shared__ __align__(16) char Asm[3 * G3_ASTRIDE];
    __shared__ __align__(16) char Bsm[3 * G3_BSTRIDE];

    const int n0 = blockIdx.x * 128;
    const int m0 = blockIdx.y * 64;
    const int tid = threadIdx.x, lane = tid & 31, warp = tid >> 5;
    const int lq = lane >> 2, lr = lane & 3;
    const int nk = K >> 5;

    const uint32_t aBase = smem_u32(Asm);
    const uint32_t bBase = smem_u32(Bsm);

    const int crow = tid >> 2, cc = tid & 3;
    const __half* aSrc0 = A + (size_t)(n0 + crow) * K + cc * 8;
    const __half* aSrc1 = A + (size_t)(n0 + crow + 64) * K + cc * 8;
    const __half* bSrc  = W + (size_t)(m0 + crow) * K + cc * 8;
    const uint32_t aDst0 = aBase + crow * 80 + cc * 16;
    const uint32_t aDst1 = aDst0 + 64 * 80;
    const uint32_t bDst  = bBase + crow * 80 + cc * 16;

    const int wiB = (warp >> 1) * 32;
    const int wjB = (warp & 1) * 32;
    const uint32_t aAddr0 = aBase + (wiB + (lane & 15)) * 80 + (lane >> 4) * 16;
    const uint32_t aAddr1 = aAddr0 + 16 * 80;
    const int bRowOff = (lane & 7) + ((lane >> 4) << 3);
    const int bColB   = ((lane >> 3) & 1) * 16;
    const uint32_t bAddr0 = bBase + (wjB + bRowOff) * 80 + bColB;
    const uint32_t bAddr1 = bAddr0 + 16 * 80;

    float acc[2][4][4];
    #pragma unroll
    for (int mi = 0; mi < 2; mi++)
        #pragma unroll
        for (int ni = 0; ni < 4; ni++)
            #pragma unroll
            for (int c = 0; c < 4; c++) acc[mi][ni][c] = 0.f;

    #define G3_ISSUE(ST, KB)                                                          \
        { size_t o = (size_t)(KB) * 32;                                               \
          CP16(aDst0 + (ST) * G3_ASTRIDE, aSrc0 + o);                                 \
          CP16(aDst1 + (ST) * G3_ASTRIDE, aSrc1 + o);                                 \
          CP16(bDst  + (ST) * G3_BSTRIDE, bSrc  + o); }

    G3_ISSUE(0, 0) CP_COMMIT();
    G3_ISSUE(1, 1) CP_COMMIT();

    int stC = 0, stI = 2;
    for (int kb = 0; kb < nk; kb++) {
        if (kb + 1 < nk) CP_WAIT1(); else CP_WAIT0();
        __syncthreads();
        if (kb + 2 < nk) G3_ISSUE(stI, kb + 2)
        CP_COMMIT();

        const uint32_t oA = stC * G3_ASTRIDE, oB = stC * G3_BSTRIDE;
        #pragma unroll
        for (int ks = 0; ks < 2; ks++) {
            uint32_t a0[4], a1[4], b0[4], b1[4];
            LDSM_X4(a0, aAddr0 + oA + ks * 32);
            LDSM_X4(a1, aAddr1 + oA + ks * 32);
            LDSM_X4(b0, bAddr0 + oB + ks * 32);
            LDSM_X4(b1, bAddr1 + oB + ks * 32);
            mma_f16(acc[0][0], a0, b0 + 0);
            mma_f16(acc[1][0], a1, b0 + 0);
            mma_f16(acc[0][1], a0, b0 + 2);
            mma_f16(acc[1][1], a1, b0 + 2);
            mma_f16(acc[0][2], a0, b1 + 0);
            mma_f16(acc[1][2], a1, b1 + 0);
            mma_f16(acc[0][3], a0, b1 + 2);
            mma_f16(acc[1][3], a1, b1 + 2);
        }
        stC = (stC == 2) ? 0 : stC + 1;
        stI = (stI == 2) ? 0 : stI + 1;
    }
    #undef G3_ISSUE

    #pragma unroll
    for (int mi = 0; mi < 2; mi++) {
        #pragma unroll
        for (int ni = 0; ni < 4; ni++) {
            int col = m0 + wjB + ni * 8 + 2 * lr;
            float bv0 = bias[col], bv1 = bias[col + 1];
            #pragma unroll
            for (int h = 0; h < 2; h++) {
                int n = n0 + wiB + mi * 16 + lq + h * 8;
                float x0 = acc[mi][ni][2 * h] + bv0;
                float x1 = acc[mi][ni][2 * h + 1] + bv1;
                if (MODE == 1) { x0 = fmaxf(x0, 0.f); x1 = fmaxf(x1, 0.f); }
                if (MODE == 0) {
                    const float* res = (const float*)resv;
                    x0 += res[(size_t)n * M + col];
                    x1 += res[(size_t)n * M + col + 1];
                }
                if (MODE == 2) {
                    const __half* res = (const __half*)resv;
                    float2 rf = __half22float2(*(const __half2*)&res[(size_t)n * M + col]);
                    x0 += rf.x; x1 += rf.y;
                }
                if (MODE == 3) {
                    __half* out = (__half*)outv;
                    int b = n >> 10, s = n & 1023;
                    out[((size_t)(b * BDIM + col)) * SDIM + s]     = __float2half_rn(x0);
                    out[((size_t)(b * BDIM + col + 1)) * SDIM + s] = __float2half_rn(x1);
                } else if (MODE == 1) {
                    __half* out = (__half*)outv;
                    *(__half2*)&out[(size_t)n * M + col] = __floats2half2_rn(x0, x1);
                } else {
                    float* out = (float*)outv;
                    *(float2*)&out[(size_t)n * M + col] = make_float2(x0, x1);
                }
            }
        }
    }
}

// ===========================================================================
// convqk3: fused Q+K conv, cp.async + ldmatrix (unchanged except tail wait).
// ===========================================================================
__global__ __launch_bounds__(256) void convqk3(const __half* __restrict__ A,
                                               const __half* __restrict__ Wt,
                                               const float* __restrict__ bq,
                                               const float* __restrict__ bk,
                                               __half* __restrict__ qo,
                                               __half* __restrict__ ko) {
    __shared__ __align__(16) char Asm[3 * G3_ASTRIDE];
    __shared__ __align__(16) char Bsm[3 * G3_BSTRIDE];

    const int n0 = blockIdx.x * 128;
    const int c0 = blockIdx.y * 32;
    const int tid = threadIdx.x, lane = tid & 31, warp = tid >> 5;
    const int lq = lane >> 2, lr = lane & 3;
    const int NST = 48;

    const uint32_t aBase = smem_u32(Asm);
    const uint32_t bBase = smem_u32(Bsm);

    const int crow = tid >> 2, cc = tid & 3;
    const uint32_t aDst0 = aBase + crow * 80 + cc * 16;
    const uint32_t aDst1 = aDst0 + 64 * 80;
    const uint32_t bDst  = bBase + crow * 80 + cc * 16;
    const int bMat = crow >> 5, bCo = c0 + (crow & 31);

    const uint32_t aAddr = aBase + (warp * 16 + (lane & 15)) * 80 + (lane >> 4) * 16;
    const int bRowOff = (lane & 7) + ((lane >> 4) << 3);
    const int bColB   = ((lane >> 3) & 1) * 16;
    const uint32_t bAddrM0 = bBase + bRowOff * 80 + bColB;
    const uint32_t bAddrM0b = bAddrM0 + 16 * 80;
    const uint32_t bAddrM1 = bBase + (32 + bRowOff) * 80 + bColB;
    const uint32_t bAddrM1b = bAddrM1 + 16 * 80;

    float acc[2][4][4];
    #pragma unroll
    for (int m = 0; m < 2; m++)
        #pragma unroll
        for (int ni = 0; ni < 4; ni++)
            #pragma unroll
            for (int c = 0; c < 4; c++) acc[m][ni][c] = 0.f;

    #define CQ_ISSUE(ST, T)                                                           \
        { int t_ = (T);                                                               \
          int tap_ = t_ >> 4; size_t ko_ = (size_t)(t_ & 15) * 32;                    \
          int roff_ = tap_ - 1;                                                       \
          { int n = n0 + crow; int s = (n & 1023) + roff_;                            \
            uint32_t sz = ((unsigned)s < 1024u) ? 16u : 0u;                           \
            int sc = s < 0 ? 0 : (s > 1023 ? 1023 : s);                               \
            const __half* sp = A + ((size_t)(n & ~1023) + sc) * BDIM + ko_ + cc * 8;  \
            CP16Z(aDst0 + (ST) * G3_ASTRIDE, sp, sz); }                               \
          { int n = n0 + crow + 64; int s = (n & 1023) + roff_;                       \
            uint32_t sz = ((unsigned)s < 1024u) ? 16u : 0u;                           \
            int sc = s < 0 ? 0 : (s > 1023 ? 1023 : s);                               \
            const __half* sp = A + ((size_t)(n & ~1023) + sc) * BDIM + ko_ + cc * 8;  \
            CP16Z(aDst1 + (ST) * G3_ASTRIDE, sp, sz); }                               \
          { const __half* sp = Wt + ((size_t)(bMat * 3 + tap_) * BDIM + bCo) * BDIM + ko_ + cc * 8; \
            CP16(bDst + (ST) * G3_BSTRIDE, sp); } }

    CQ_ISSUE(0, 0) CP_COMMIT();
    CQ_ISSUE(1, 1) CP_COMMIT();

    int stC = 0, stI = 2;
    for (int t = 0; t < NST; t++) {
        if (t + 1 < NST) CP_WAIT1(); else CP_WAIT0();
        __syncthreads();
        if (t + 2 < NST) CQ_ISSUE(stI, t + 2)
        CP_COMMIT();

        const uint32_t oA = stC * G3_ASTRIDE, oB = stC * G3_BSTRIDE;
        #pragma unroll
        for (int ks = 0; ks < 2; ks++) {
            uint32_t a[4], b00[4], b01[4], b10[4], b11[4];
            LDSM_X4(a, aAddr + oA + ks * 32);
            LDSM_X4(b00, bAddrM0  + oB + ks * 32);
            LDSM_X4(b01, bAddrM0b + oB + ks * 32);
            LDSM_X4(b10, bAddrM1  + oB + ks * 32);
            LDSM_X4(b11, bAddrM1b + oB + ks * 32);
            mma_f16(acc[0][0], a, b00 + 0);
            mma_f16(acc[0][1], a, b00 + 2);
            mma_f16(acc[0][2], a, b01 + 0);
            mma_f16(acc[0][3], a, b01 + 2);
            mma_f16(acc[1][0], a, b10 + 0);
            mma_f16(acc[1][1], a, b10 + 2);
            mma_f16(acc[1][2], a, b11 + 0);
            mma_f16(acc[1][3], a, b11 + 2);
        }
        stC = (stC == 2) ? 0 : stC + 1;
        stI = (stI == 2) ? 0 : stI + 1;
    }
    #undef CQ_ISSUE

    #pragma unroll
    for (int m = 0; m < 2; m++) {
        __half* outp = m ? ko : qo;
        const float* bp = m ? bk : bq;
        const float scl = m ? 1.0f : 0.015625f;
        #pragma unroll
        for (int ni = 0; ni < 4; ni++) {
            int col = c0 + ni * 8 + 2 * lr;
            float bv0 = bp[col], bv1 = bp[col + 1];
            int hh = col >> 6, dd = col & 63;
            #pragma unroll
            for (int h = 0; h < 2; h++) {
                int n = n0 + warp * 16 + lq + h * 8;
                int b = n >> 10, s = n & 1023;
                __half2 o2 = __floats2half2_rn((acc[m][ni][2 * h] + bv0) * scl,
                                               (acc[m][ni][2 * h + 1] + bv1) * scl);
                *(__half2*)&outp[(((size_t)(b * NHEADS + hh)) * SDIM + s) * HD + dd] = o2;
            }
        }
    }
}

// ===========================================================================
// attn_mma2: fp16 flash attention, cp.async + ldmatrix, P-in-register PV.
// q(pre-scaled),k [B,H,S,64]; v [B,D,S]. 128 threads, 64-query tile.
// K/V tiles 64x64 halves at 144B row stride (conflict-free ldmatrix),
// double-buffered cp.async.
// ===========================================================================
#define AT_STRIDE 144
#define AT_TILE   (64 * AT_STRIDE)   // 9216B

__global__ __launch_bounds__(128) void attn_mma2(const __half* __restrict__ q,
                                                 const __half* __restrict__ k,
                                                 const __half* __restrict__ v,
                                                 __half* __restrict__ av) {
    __shared__ __align__(16) char Ksm[2 * AT_TILE];
    __shared__ __align__(16) char Vsm[2 * AT_TILE];

    const int s0 = blockIdx.x * 64;
    const int h  = blockIdx.y;
    const int b  = blockIdx.z;
    const __half* qb = q + (size_t)(b * NHEADS + h) * SDIM * HD;
    const __half* kb = k + (size_t)(b * NHEADS + h) * SDIM * HD;
    const __half* vb = v + (size_t)(b * NHEADS + h) * HD * SDIM;

    const int tid  = threadIdx.x;
    const int lane = tid & 31;
    const int warp = tid >> 5;
    const int lq = lane >> 2;
    const int lr = lane & 3;

    const uint32_t kBase = smem_u32(Ksm);
    const uint32_t vBase = smem_u32(Vsm);

    // cp.async chunk mapping: 512 chunks of 16B per tile, 4 per thread
    // chunk id = tid + 128*r : row = id>>3, c = id&7
    const int bRowOff = (lane & 7) + ((lane >> 4) << 3);
    const int bColB   = ((lane >> 3) & 1) * 16;
    const uint32_t kFrag = kBase + bRowOff * AT_STRIDE + bColB;
    const uint32_t vFrag = vBase + bRowOff * AT_STRIDE + bColB;

    // ---- Q fragments via cp.async stage into Ksm buf0 ----
    #pragma unroll
    for (int r = 0; r < 4; r++) {
        int id = tid + 128 * r;
        int row = id >> 3, c = id & 7;
        CP16(kBase + row * AT_STRIDE + c * 16, qb + (size_t)(s0 + row) * HD + c * 8);
    }
    CP_COMMIT();
    CP_WAIT0();
    __syncthreads();
    uint32_t qf[4][4];
    {
        const uint32_t qAddr = kBase + (warp * 16 + (lane & 15)) * AT_STRIDE + (lane >> 4) * 16;
        #pragma unroll
        for (int ks = 0; ks < 4; ks++)
            LDSM_X4(qf[ks], qAddr + ks * 32);
    }
    __syncthreads();

    // ---- issue K/V tile 0 ----
    #define AT_ISSUE(BUF, T0)                                                          \
        { _Pragma("unroll")                                                            \
          for (int r = 0; r < 4; r++) {                                                \
              int id = tid + 128 * r;                                                  \
              int row = id >> 3, c = id & 7;                                           \
              uint32_t d = row * AT_STRIDE + c * 16 + (BUF) * AT_TILE;                 \
              CP16(kBase + d, kb + (size_t)((T0) + row) * HD + c * 8);                 \
              CP16(vBase + d, vb + (size_t)row * SDIM + (T0) + c * 8); } }

    AT_ISSUE(0, 0)
    CP_COMMIT();

    float m0v = -1e30f, m1v = -1e30f, l0 = 0.f, l1 = 0.f;
    float o[8][4];
    #pragma unroll
    for (int ni = 0; ni < 8; ni++)
        #pragma unroll
        for (int c = 0; c < 4; c++) o[ni][c] = 0.f;

    for (int t = 0; t < 16; t++) {
        if (t + 1 < 16) AT_ISSUE((t + 1) & 1, (t + 1) * 64)
        CP_COMMIT();
        if (t + 1 < 16) CP_WAIT1(); else CP_WAIT0();
        __syncthreads();

        const uint32_t off = (t & 1) * AT_TILE;

        // QK scores: 16 rows x 64 t
        float sc[8][4];
        #pragma unroll
        for (int ni = 0; ni < 8; ni++)
            #pragma unroll
            for (int c = 0; c < 4; c++) sc[ni][c] = 0.f;
        #pragma unroll
        for (int ks = 0; ks < 4; ks++) {
            #pragma unroll
            for (int g = 0; g < 4; g++) {
                uint32_t kf[4];
                LDSM_X4(kf, kFrag + off + g * 16 * AT_STRIDE + ks * 32);
                mma_f16(sc[2 * g],     qf[ks], kf + 0);
                mma_f16(sc[2 * g + 1], qf[ks], kf + 2);
            }
        }

        // Online softmax (rows lq -> c0,c1 ; lq+8 -> c2,c3)
        float rm0 = -1e30f, rm1 = -1e30f;
        #pragma unroll
        for (int ni = 0; ni < 8; ni++) {
            rm0 = fmaxf(rm0, fmaxf(sc[ni][0], sc[ni][1]));
            rm1 = fmaxf(rm1, fmaxf(sc[ni][2], sc[ni][3]));
        }
        rm0 = fmaxf(rm0, __shfl_xor_sync(0xffffffffu, rm0, 1));
        rm0 = fmaxf(rm0, __shfl_xor_sync(0xffffffffu, rm0, 2));
        rm1 = fmaxf(rm1, __shfl_xor_sync(0xffffffffu, rm1, 1));
        rm1 = fmaxf(rm1, __shfl_xor_sync(0xffffffffu, rm1, 2));
        float mn0 = fmaxf(m0v, rm0), mn1 = fmaxf(m1v, rm1);
        float cr0 = __expf(m0v - mn0), cr1 = __expf(m1v - mn1);
        float rs0 = 0.f, rs1 = 0.f;
        #pragma unroll
        for (int ni = 0; ni < 8; ni++) {
            sc[ni][0] = __expf(sc[ni][0] - mn0);
            sc[ni][1] = __expf(sc[ni][1] - mn0);
            sc[ni][2] = __expf(sc[ni][2] - mn1);
            sc[ni][3] = __expf(sc[ni][3] - mn1);
            rs0 += sc[ni][0] + sc[ni][1];
            rs1 += sc[ni][2] + sc[ni][3];
        }
        rs0 += __shfl_xor_sync(0xffffffffu, rs0, 1);
        rs0 += __shfl_xor_sync(0xffffffffu, rs0, 2);
        rs1 += __shfl_xor_sync(0xffffffffu, rs1, 1);
        rs1 += __shfl_xor_sync(0xffffffffu, rs1, 2);
        l0 = l0 * cr0 + rs0;
        l1 = l1 * cr1 + rs1;
        m0v = mn0; m1v = mn1;
        #pragma unroll
        for (int ni = 0; ni < 8; ni++) {
            o[ni][0] *= cr0; o[ni][1] *= cr0;
            o[ni][2] *= cr1; o[ni][3] *= cr1;
        }

        // PV: P fragments come straight from registers (exact A-fragment layout)
        #pragma unroll
        for (int ks = 0; ks < 4; ks++) {
            uint32_t pa[4];
            pa[0] = f2h2(sc[2 * ks][0],     sc[2 * ks][1]);
            pa[1] = f2h2(sc[2 * ks][2],     sc[2 * ks][3]);
            pa[2] = f2h2(sc[2 * ks + 1][0], sc[2 * ks + 1][1]);
            pa[3] = f2h2(sc[2 * ks + 1][2], sc[2 * ks + 1][3]);
            #pragma unroll
            for (int g = 0; g < 4; g++) {
                uint32_t vf[4];
                LDSM_X4(vf, vFrag + off + g * 16 * AT_STRIDE + ks * 32);
                mma_f16(o[2 * g],     pa, vf + 0);
                mma_f16(o[2 * g + 1], pa, vf + 2);
            }
        }
        __syncthreads();   // all reads of this buffer done before reuse
    }
    #undef AT_ISSUE

    float inv0 = 1.0f / l0, inv1 = 1.0f / l1;
    const int rbase = s0 + warp * 16;
    #pragma unroll
    for (int ni = 0; ni < 8; ni++) {
        int col = h * HD + ni * 8 + 2 * lr;
        __half2 a = __floats2half2_rn(o[ni][0] * inv0, o[ni][1] * inv0);
        __half2 c = __floats2half2_rn(o[ni][2] * inv1, o[ni][3] * inv1);
        *(__half2*)&av[(size_t)(b * SDIM + rbase + lq) * BDIM + col]     = a;
        *(__half2*)&av[(size_t)(b * SDIM + rbase + lq + 8) * BDIM + col] = c;
    }
}

// ---------------------------------------------------------------------------
// LayerNorm over last dim (512). f32 in; templated output type.
// ---------------------------------------------------------------------------
template <typename OutT>
__global__ void ln_kernel(const float* __restrict__ in, const float* __restrict__ g,
                          const float* __restrict__ beta, OutT* __restrict__ out) {
    const int row = blockIdx.x;
    const float* x = in + (size_t)row * BDIM;
    const int tid = threadIdx.x;
    const int wid = tid >> 5, lane = tid & 31;

    float v0 = x[tid], v1 = x[tid + 256];
    __shared__ float red[8];

    float s = v0 + v1;
    #pragma unroll
    for (int off = 16; off > 0; off >>= 1)
        s += __shfl_xor_sync(0xffffffffu, s, off);
    if (lane == 0) red[wid] = s;
    __syncthreads();
    float tot = 0.f;
    #pragma unroll
    for (int i = 0; i < 8; i++) tot += red[i];
    float mu = tot * (1.0f / 512.0f);
    __syncthreads();

    float d0 = v0 - mu, d1 = v1 - mu;
    float sq = d0 * d0 + d1 * d1;
    #pragma unroll
    for (int off = 16; off > 0; off >>= 1)
        sq += __shfl_xor_sync(0xffffffffu, sq, off);
    if (lane == 0) red[wid] = sq;
    __syncthreads();
    float tot2 = 0.f;
    #pragma unroll
    for (int i = 0; i < 8; i++) tot2 += red[i];
    float rstd = rsqrtf(tot2 * (1.0f / 512.0f) + 1e-5f);

    float y0 = d0 * rstd * g[tid]       + beta[tid];
    float y1 = d1 * rstd * g[tid + 256] + beta[tid + 256];
    out[(size_t)row * BDIM + tid]       = (OutT)y0;
    out[(size_t)row * BDIM + tid + 256] = (OutT)y1;
}

// ---------------------------------------------------------------------------
extern "C" void kernel_launch(void* const* d_in, const int* in_sizes, int n_in,
                              void* d_out, int out_size) {
    const float* src = (const float*)d_in[0];
    const float* Wq  = (const float*)d_in[1];
    const float* bq  = (const float*)d_in[2];
    const float* Wk  = (const float*)d_in[3];
    const float* bk  = (const float*)d_in[4];
    const float* Wv  = (const float*)d_in[5];
    const float* bv  = (const float*)d_in[6];
    const float* Wo  = (const float*)d_in[7];
    const float* bo  = (const float*)d_in[8];
    const float* W1  = (const float*)d_in[9];
    const float* b1  = (const float*)d_in[10];
    const float* W2  = (const float*)d_in[11];
    const float* b2  = (const float*)d_in[12];
    const float* g1  = (const float*)d_in[13];
    const float* be1 = (const float*)d_in[14];
    const float* g2  = (const float*)d_in[15];
    const float* be2 = (const float*)d_in[16];
    float* out = (float*)d_out;

    float *t1;
    __half *srch, *q, *k, *v, *av, *x1, *ff, *wt, *wc;
    cudaGetSymbolAddress((void**)&srch, g_srch);
    cudaGetSymbolAddress((void**)&q,  g_q);
    cudaGetSymbolAddress((void**)&k,  g_k);
    cudaGetSymbolAddress((void**)&v,  g_v);
    cudaGetSymbolAddress((void**)&av, g_av);
    cudaGetSymbolAddress((void**)&t1, g_t1);
    cudaGetSymbolAddress((void**)&x1, g_x1);
    cudaGetSymbolAddress((void**)&ff, g_ff);
    cudaGetSymbolAddress((void**)&wt, g_wt);
    cudaGetSymbolAddress((void**)&wc, g_wc);

    wprep_kernel<<<(WPREP_TOTAL + 255) / 256, 256>>>(Wq, Wk, Wv, Wo, W1, W2, src, wt, wc, srch);

    convqk3<<<dim3(NTOK / 128, BDIM / 32), 256>>>(srch, wt, bq, bk, q, k);
    gemm3<3><<<dim3(NTOK / 128, BDIM / 64), 256>>>(srch, wc + WC_WV, bv, nullptr, v, BDIM, BDIM);

    attn_mma2<<<dim3(SDIM / 64, NHEADS, BATCH), 128>>>(q, k, v, av);

    gemm3<0><<<dim3(NTOK / 128, BDIM / 64), 256>>>(av, wc + WC_WO, bo, src, t1, BDIM, BDIM);
    ln_kernel<__half><<<NTOK, 256>>>(t1, g1, be1, x1);

    gemm3<1><<<dim3(NTOK / 128, DFF / 64), 256>>>(x1, wc + WC_W1, b1, nullptr, ff, DFF, BDIM);
    gemm3<2><<<dim3(NTOK / 128, BDIM / 64), 256>>>(ff, wc + WC_W2, b2, x1, t1, BDIM, DFF);
    ln_kernel<float><<<NTOK, 256>>>(t1, g2, be2, out);
}

// round 13
// speedup vs baseline: 2.5081x; 1.0484x over previous
#include <cuda_runtime.h>
#include <cuda_fp16.h>
#include <math.h>
#include <stdint.h>

#define BDIM   512
#define SDIM   1024
#define BATCH  8
#define NHEADS 8
#define HD     64
#define DFF    2048
#define NTOK   (BATCH * SDIM)   // 8192

// Scratch
__device__ __half g_srch[NTOK * BDIM];
__device__ __half g_q [BATCH * BDIM * SDIM];   // [B,H,S,64], pre-scaled by 1/64
__device__ __half g_k [BATCH * BDIM * SDIM];   // [B,H,S,64]
__device__ __half g_v [BATCH * BDIM * SDIM];   // [B,D,S]
__device__ __half g_av[NTOK * BDIM];
__device__ float  g_t1[NTOK * BDIM];
__device__ __half g_x1[NTOK * BDIM];
__device__ __half g_ff[NTOK * DFF];
__device__ __half g_wt[2 * 3 * BDIM * BDIM];
__device__ __half g_wc[2 * BDIM * BDIM + 2 * DFF * BDIM];

#define WC_WV 0
#define WC_WO (BDIM * BDIM)
#define WC_W1 (2 * BDIM * BDIM)
#define WC_W2 (2 * BDIM * BDIM + DFF * BDIM)

__device__ __forceinline__ uint32_t f2h2(float lo, float hi) {
    __half2 h = __floats2half2_rn(lo, hi);
    return *reinterpret_cast<uint32_t*>(&h);
}

__device__ __forceinline__ void mma_f16(float c[4], const uint32_t a[4], const uint32_t b[2]) {
    asm volatile(
        "mma.sync.aligned.m16n8k16.row.col.f32.f16.f16.f32 "
        "{%0,%1,%2,%3}, {%4,%5,%6,%7}, {%8,%9}, {%0,%1,%2,%3};"
        : "+f"(c[0]), "+f"(c[1]), "+f"(c[2]), "+f"(c[3])
        : "r"(a[0]), "r"(a[1]), "r"(a[2]), "r"(a[3]), "r"(b[0]), "r"(b[1]));
}

__device__ __forceinline__ uint32_t smem_u32(const void* p) {
    uint32_t a;
    asm("{ .reg .u64 t; cvta.to.shared.u64 t, %1; cvt.u32.u64 %0, t; }" : "=r"(a) : "l"(p));
    return a;
}

#define CP16(dst, src) \
    asm volatile("cp.async.cg.shared.global [%0], [%1], 16;" :: "r"(dst), "l"(src))
#define CP16Z(dst, src, sz) \
    asm volatile("cp.async.cg.shared.global [%0], [%1], 16, %2;" :: "r"(dst), "l"(src), "r"(sz))
#define CP_COMMIT() asm volatile("cp.async.commit_group;")
#define CP_WAIT1()  asm volatile("cp.async.wait_group 1;")
#define CP_WAIT0()  asm volatile("cp.async.wait_group 0;")

#define LDSM_X4(R, ADDR) \
    asm volatile("ldmatrix.sync.aligned.m8n8.x4.shared.b16 {%0,%1,%2,%3}, [%4];" \
                 : "=r"((R)[0]), "=r"((R)[1]), "=r"((R)[2]), "=r"((R)[3]) : "r"(ADDR))

// ---------------------------------------------------------------------------
// Merged prep
// ---------------------------------------------------------------------------
#define WTN (2 * 3 * BDIM * BDIM)
#define WPREP_TOTAL (WTN + 2 * BDIM * BDIM + 2 * DFF * BDIM + NTOK * BDIM)
__global__ void wprep_kernel(const float* __restrict__ Wq, const float* __restrict__ Wk,
                             const float* __restrict__ Wv, const float* __restrict__ Wo,
                             const float* __restrict__ W1, const float* __restrict__ W2,
                             const float* __restrict__ src,
                             __half* __restrict__ wt, __half* __restrict__ wc,
                             __half* __restrict__ srch) {
    int e = blockIdx.x * 256 + threadIdx.x;
    if (e < WTN) {
        int m  = (e >= 3 * BDIM * BDIM);
        int e2 = e - m * 3 * BDIM * BDIM;
        int t  = e2 >> 18;
        int co = (e2 >> 9) & 511;
        int ci = e2 & 511;
        const float* s = m ? Wk : Wq;
        wt[e] = __float2half_rn(s[(size_t)co * 1536 + ci * 3 + t]);
        return;
    }
    int f = e - WTN;
    if (f < BDIM * BDIM)            { wc[WC_WV + f] = __float2half_rn(Wv[f]); return; }
    f -= BDIM * BDIM;
    if (f < BDIM * BDIM)            { wc[WC_WO + f] = __float2half_rn(Wo[f]); return; }
    f -= BDIM * BDIM;
    if (f < DFF * BDIM)             { wc[WC_W1 + f] = __float2half_rn(W1[f]); return; }
    f -= DFF * BDIM;
    if (f < DFF * BDIM)             { wc[WC_W2 + f] = __float2half_rn(W2[f]); return; }
    f -= DFF * BDIM;
    if (f < NTOK * BDIM)            { srch[f] = __float2half_rn(src[f]); return; }
}

// ===========================================================================
// gemm4: fp16 GEMM, 128(n) x 128(m) tile, 8 warps (32x64 each), KT=32,
// 2-stage cp.async ring (wait0 + sync before issue; 1 stage of overlap).
// MODE 0: +res(f32) -> f32 | 1: relu -> fp16 | 2: +res(fp16) -> f32
// MODE 3: scatter [B,D,S] fp16 (bias only)
// ===========================================================================
#define G4_STRIDE 10240   // 128 rows * 80B

template <int MODE>
__global__ __launch_bounds__(256) void gemm4(const __half* __restrict__ A,
                                             const __half* __restrict__ W,
                                             const float* __restrict__ bias,
                                             const void* __restrict__ resv,
                                             void* __restrict__ outv, int M, int K) {
    __shared__ __align__(16) char Asm[2 * G4_STRIDE];
    __shared__ __align__(16) char Bsm[2 * G4_STRIDE];

    const int n0 = blockIdx.x * 128;
    const int m0 = blockIdx.y * 128;
    const int tid = threadIdx.x, lane = tid & 31, warp = tid >> 5;
    const int lq = lane >> 2, lr = lane & 3;
    const int nk = K >> 5;

    const uint32_t aBase = smem_u32(Asm);
    const uint32_t bBase = smem_u32(Bsm);

    // cp.async mapping: 512 chunks per tile, 2 per thread (rows crow, crow+64)
    const int crow = tid >> 2, cc = tid & 3;
    const __half* aSrc0 = A + (size_t)(n0 + crow) * K + cc * 8;
    const __half* aSrc1 = A + (size_t)(n0 + crow + 64) * K + cc * 8;
    const __half* bSrc0 = W + (size_t)(m0 + crow) * K + cc * 8;
    const __half* bSrc1 = W + (size_t)(m0 + crow + 64) * K + cc * 8;
    const uint32_t aDst0 = aBase + crow * 80 + cc * 16;
    const uint32_t aDst1 = aDst0 + 64 * 80;
    const uint32_t bDst0 = bBase + crow * 80 + cc * 16;
    const uint32_t bDst1 = bDst0 + 64 * 80;

    const int wiB = (warp >> 1) * 32;     // n rows
    const int wjB = (warp & 1) * 64;      // m rows
    const uint32_t aAddr0 = aBase + (wiB + (lane & 15)) * 80 + (lane >> 4) * 16;
    const uint32_t aAddr1 = aAddr0 + 16 * 80;
    const int bRowOff = (lane & 7) + ((lane >> 4) << 3);
    const int bColB   = ((lane >> 3) & 1) * 16;
    const uint32_t bAddr = bBase + (wjB + bRowOff) * 80 + bColB;

    float acc[2][8][4];
    #pragma unroll
    for (int mi = 0; mi < 2; mi++)
        #pragma unroll
        for (int ni = 0; ni < 8; ni++)
            #pragma unroll
            for (int c = 0; c < 4; c++) acc[mi][ni][c] = 0.f;

    #define G4_ISSUE(ST, KB)                                                          \
        { size_t o = (size_t)(KB) * 32;                                               \
          CP16(aDst0 + (ST) * G4_STRIDE, aSrc0 + o);                                  \
          CP16(aDst1 + (ST) * G4_STRIDE, aSrc1 + o);                                  \
          CP16(bDst0 + (ST) * G4_STRIDE, bSrc0 + o);                                  \
          CP16(bDst1 + (ST) * G4_STRIDE, bSrc1 + o); }

    G4_ISSUE(0, 0) CP_COMMIT();

    int st = 0;
    for (int kb = 0; kb < nk; kb++) {
        CP_WAIT0();
        __syncthreads();
        if (kb + 1 < nk) { G4_ISSUE(st ^ 1, kb + 1) CP_COMMIT(); }

        const uint32_t oS = st * G4_STRIDE;
        #pragma unroll
        for (int ks = 0; ks < 2; ks++) {
            uint32_t a0[4], a1[4];
            LDSM_X4(a0, aAddr0 + oS + ks * 32);
            LDSM_X4(a1, aAddr1 + oS + ks * 32);
            #pragma unroll
            for (int g = 0; g < 4; g++) {
                uint32_t bg[4];
                LDSM_X4(bg, bAddr + oS + g * 16 * 80 + ks * 32);
                mma_f16(acc[0][2 * g],     a0, bg + 0);
                mma_f16(acc[1][2 * g],     a1, bg + 0);
                mma_f16(acc[0][2 * g + 1], a0, bg + 2);
                mma_f16(acc[1][2 * g + 1], a1, bg + 2);
            }
        }
        st ^= 1;
    }
    #undef G4_ISSUE

    #pragma unroll
    for (int mi = 0; mi < 2; mi++) {
        #pragma unroll
        for (int ni = 0; ni < 8; ni++) {
            int col = m0 + wjB + ni * 8 + 2 * lr;
            float bv0 = bias[col], bv1 = bias[col + 1];
            #pragma unroll
            for (int h = 0; h < 2; h++) {
                int n = n0 + wiB + mi * 16 + lq + h * 8;
                float x0 = acc[mi][ni][2 * h] + bv0;
                float x1 = acc[mi][ni][2 * h + 1] + bv1;
                if (MODE == 1) { x0 = fmaxf(x0, 0.f); x1 = fmaxf(x1, 0.f); }
                if (MODE == 0) {
                    const float* res = (const float*)resv;
                    x0 += res[(size_t)n * M + col];
                    x1 += res[(size_t)n * M + col + 1];
                }
                if (MODE == 2) {
                    const __half* res = (const __half*)resv;
                    float2 rf = __half22float2(*(const __half2*)&res[(size_t)n * M + col]);
                    x0 += rf.x; x1 += rf.y;
                }
                if (MODE == 3) {
                    __half* out = (__half*)outv;
                    int b = n >> 10, s = n & 1023;
                    out[((size_t)(b * BDIM + col)) * SDIM + s]     = __float2half_rn(x0);
                    out[((size_t)(b * BDIM + col + 1)) * SDIM + s] = __float2half_rn(x1);
                } else if (MODE == 1) {
                    __half* out = (__half*)outv;
                    *(__half2*)&out[(size_t)n * M + col] = __floats2half2_rn(x0, x1);
                } else {
                    float* out = (float*)outv;
                    *(float2*)&out[(size_t)n * M + col] = make_float2(x0, x1);
                }
            }
        }
    }
}

// ===========================================================================
// convqk4: fused Q+K conv, 128(tok) x 64(co) x 2 mats, 48 stages,
// 2-stage cp.async ring. B smem rows 0-63 = mat0 (Wq), 64-127 = mat1 (Wk).
// Warp tile: 16 tok x 64 co x 2 mats.
// ===========================================================================
__global__ __launch_bounds__(256) void convqk4(const __half* __restrict__ A,
                                               const __half* __restrict__ Wt,
                                               const float* __restrict__ bq,
                                               const float* __restrict__ bk,
                                               __half* __restrict__ qo,
                                               __half* __restrict__ ko) {
    __shared__ __align__(16) char Asm[2 * G4_STRIDE];
    __shared__ __align__(16) char Bsm[2 * G4_STRIDE];

    const int n0 = blockIdx.x * 128;
    const int c0 = blockIdx.y * 64;
    const int tid = threadIdx.x, lane = tid & 31, warp = tid >> 5;
    const int lq = lane >> 2, lr = lane & 3;
    const int NST = 48;

    const uint32_t aBase = smem_u32(Asm);
    const uint32_t bBase = smem_u32(Bsm);

    const int crow = tid >> 2, cc = tid & 3;
    const uint32_t aDst0 = aBase + crow * 80 + cc * 16;
    const uint32_t aDst1 = aDst0 + 64 * 80;
    const uint32_t bDst0 = bBase + crow * 80 + cc * 16;     // rows 0-63: mat0
    const uint32_t bDst1 = bDst0 + 64 * 80;                 // rows 64-127: mat1

    const uint32_t aAddr = aBase + (warp * 16 + (lane & 15)) * 80 + (lane >> 4) * 16;
    const int bRowOff = (lane & 7) + ((lane >> 4) << 3);
    const int bColB   = ((lane >> 3) & 1) * 16;
    const uint32_t bAddr0 = bBase + bRowOff * 80 + bColB;           // mat0
    const uint32_t bAddr1 = bBase + (64 + bRowOff) * 80 + bColB;    // mat1

    float acc[2][8][4];
    #pragma unroll
    for (int m = 0; m < 2; m++)
        #pragma unroll
        for (int ni = 0; ni < 8; ni++)
            #pragma unroll
            for (int c = 0; c < 4; c++) acc[m][ni][c] = 0.f;

    #define CQ_ISSUE(ST, T)                                                           \
        { int t_ = (T);                                                               \
          int tap_ = t_ >> 4; size_t ko_ = (size_t)(t_ & 15) * 32;                    \
          int roff_ = tap_ - 1;                                                       \
          { int n = n0 + crow; int s = (n & 1023) + roff_;                            \
            uint32_t sz = ((unsigned)s < 1024u) ? 16u : 0u;                           \
            int sc = s < 0 ? 0 : (s > 1023 ? 1023 : s);                               \
            const __half* sp = A + ((size_t)(n & ~1023) + sc) * BDIM + ko_ + cc * 8;  \
            CP16Z(aDst0 + (ST) * G4_STRIDE, sp, sz); }                                \
          { int n = n0 + crow + 64; int s = (n & 1023) + roff_;                       \
            uint32_t sz = ((unsigned)s < 1024u) ? 16u : 0u;                           \
            int sc = s < 0 ? 0 : (s > 1023 ? 1023 : s);                               \
            const __half* sp = A + ((size_t)(n & ~1023) + sc) * BDIM + ko_ + cc * 8;  \
            CP16Z(aDst1 + (ST) * G4_STRIDE, sp, sz); }                                \
          { const __half* sp0 = Wt + ((size_t)(0 * 3 + tap_) * BDIM + c0 + crow) * BDIM + ko_ + cc * 8; \
            CP16(bDst0 + (ST) * G4_STRIDE, sp0);                                      \
            const __half* sp1 = Wt + ((size_t)(1 * 3 + tap_) * BDIM + c0 + crow) * BDIM + ko_ + cc * 8; \
            CP16(bDst1 + (ST) * G4_STRIDE, sp1); } }

    CQ_ISSUE(0, 0) CP_COMMIT();

    int st = 0;
    for (int t = 0; t < NST; t++) {
        CP_WAIT0();
        __syncthreads();
        if (t + 1 < NST) { CQ_ISSUE(st ^ 1, t + 1) CP_COMMIT(); }

        const uint32_t oS = st * G4_STRIDE;
        #pragma unroll
        for (int ks = 0; ks < 2; ks++) {
            uint32_t a[4];
            LDSM_X4(a, aAddr + oS + ks * 32);
            #pragma unroll
            for (int g = 0; g < 4; g++) {
                uint32_t b0[4], b1[4];
                LDSM_X4(b0, bAddr0 + oS + g * 16 * 80 + ks * 32);
                LDSM_X4(b1, bAddr1 + oS + g * 16 * 80 + ks * 32);
                mma_f16(acc[0][2 * g],     a, b0 + 0);
                mma_f16(acc[0][2 * g + 1], a, b0 + 2);
                mma_f16(acc[1][2 * g],     a, b1 + 0);
                mma_f16(acc[1][2 * g + 1], a, b1 + 2);
            }
        }
        st ^= 1;
    }
    #undef CQ_ISSUE

    #pragma unroll
    for (int m = 0; m < 2; m++) {
        __half* outp = m ? ko : qo;
        const float* bp = m ? bk : bq;
        const float scl = m ? 1.0f : 0.015625f;   // fold 1/64 into Q
        #pragma unroll
        for (int ni = 0; ni < 8; ni++) {
            int col = c0 + ni * 8 + 2 * lr;
            float bv0 = bp[col], bv1 = bp[col + 1];
            int hh = col >> 6, dd = col & 63;
            #pragma unroll
            for (int h = 0; h < 2; h++) {
                int n = n0 + warp * 16 + lq + h * 8;
                int b = n >> 10, s = n & 1023;
                __half2 o2 = __floats2half2_rn((acc[m][ni][2 * h] + bv0) * scl,
                                               (acc[m][ni][2 * h + 1] + bv1) * scl);
                *(__half2*)&outp[(((size_t)(b * NHEADS + hh)) * SDIM + s) * HD + dd] = o2;
            }
        }
    }
}

// ===========================================================================
// attn_mma2: fp16 flash attention (R12-exact).
// ===========================================================================
#define AT_STRIDE 144
#define AT_TILE   (64 * AT_STRIDE)

__global__ __launch_bounds__(128) void attn_mma2(const __half* __restrict__ q,
                                                 const __half* __restrict__ k,
                                                 const __half* __restrict__ v,
                                                 __half* __restrict__ av) {
    __shared__ __align__(16) char Ksm[2 * AT_TILE];
    __shared__ __align__(16) char Vsm[2 * AT_TILE];

    const int s0 = blockIdx.x * 64;
    const int h  = blockIdx.y;
    const int b  = blockIdx.z;
    const __half* qb = q + (size_t)(b * NHEADS + h) * SDIM * HD;
    const __half* kb = k + (size_t)(b * NHEADS + h) * SDIM * HD;
    const __half* vb = v + (size_t)(b * NHEADS + h) * HD * SDIM;

    const int tid  = threadIdx.x;
    const int lane = tid & 31;
    const int warp = tid >> 5;
    const int lq = lane >> 2;
    const int lr = lane & 3;

    const uint32_t kBase = smem_u32(Ksm);
    const uint32_t vBase = smem_u32(Vsm);

    const int bRowOff = (lane & 7) + ((lane >> 4) << 3);
    const int bColB   = ((lane >> 3) & 1) * 16;
    const uint32_t kFrag = kBase + bRowOff * AT_STRIDE + bColB;
    const uint32_t vFrag = vBase + bRowOff * AT_STRIDE + bColB;

    #pragma unroll
    for (int r = 0; r < 4; r++) {
        int id = tid + 128 * r;
        int row = id >> 3, c = id & 7;
        CP16(kBase + row * AT_STRIDE + c * 16, qb + (size_t)(s0 + row) * HD + c * 8);
    }
    CP_COMMIT();
    CP_WAIT0();
    __syncthreads();
    uint32_t qf[4][4];
    {
        const uint32_t qAddr = kBase + (warp * 16 + (lane & 15)) * AT_STRIDE + (lane >> 4) * 16;
        #pragma unroll
        for (int ks = 0; ks < 4; ks++)
            LDSM_X4(qf[ks], qAddr + ks * 32);
    }
    __syncthreads();

    #define AT_ISSUE(BUF, T0)                                                          \
        { _Pragma("unroll")                                                            \
          for (int r = 0; r < 4; r++) {                                                \
              int id = tid + 128 * r;                                                  \
              int row = id >> 3, c = id & 7;                                           \
              uint32_t d = row * AT_STRIDE + c * 16 + (BUF) * AT_TILE;                 \
              CP16(kBase + d, kb + (size_t)((T0) + row) * HD + c * 8);                 \
              CP16(vBase + d, vb + (size_t)row * SDIM + (T0) + c * 8); } }

    AT_ISSUE(0, 0)
    CP_COMMIT();

    float m0v = -1e30f, m1v = -1e30f, l0 = 0.f, l1 = 0.f;
    float o[8][4];
    #pragma unroll
    for (int ni = 0; ni < 8; ni++)
        #pragma unroll
        for (int c = 0; c < 4; c++) o[ni][c] = 0.f;

    for (int t = 0; t < 16; t++) {
        if (t + 1 < 16) AT_ISSUE((t + 1) & 1, (t + 1) * 64)
        CP_COMMIT();
        if (t + 1 < 16) CP_WAIT1(); else CP_WAIT0();
        __syncthreads();

        const uint32_t off = (t & 1) * AT_TILE;

        float sc[8][4];
        #pragma unroll
        for (int ni = 0; ni < 8; ni++)
            #pragma unroll
            for (int c = 0; c < 4; c++) sc[ni][c] = 0.f;
        #pragma unroll
        for (int ks = 0; ks < 4; ks++) {
            #pragma unroll
            for (int g = 0; g < 4; g++) {
                uint32_t kf[4];
                LDSM_X4(kf, kFrag + off + g * 16 * AT_STRIDE + ks * 32);
                mma_f16(sc[2 * g],     qf[ks], kf + 0);
                mma_f16(sc[2 * g + 1], qf[ks], kf + 2);
            }
        }

        float rm0 = -1e30f, rm1 = -1e30f;
        #pragma unroll
        for (int ni = 0; ni < 8; ni++) {
            rm0 = fmaxf(rm0, fmaxf(sc[ni][0], sc[ni][1]));
            rm1 = fmaxf(rm1, fmaxf(sc[ni][2], sc[ni][3]));
        }
        rm0 = fmaxf(rm0, __shfl_xor_sync(0xffffffffu, rm0, 1));
        rm0 = fmaxf(rm0, __shfl_xor_sync(0xffffffffu, rm0, 2));
        rm1 = fmaxf(rm1, __shfl_xor_sync(0xffffffffu, rm1, 1));
        rm1 = fmaxf(rm1, __shfl_xor_sync(0xffffffffu, rm1, 2));
        float mn0 = fmaxf(m0v, rm0), mn1 = fmaxf(m1v, rm1);
        float cr0 = __expf(m0v - mn0), cr1 = __expf(m1v - mn1);
        float rs0 = 0.f, rs1 = 0.f;
        #pragma unroll
        for (int ni = 0; ni < 8; ni++) {
            sc[ni][0] = __expf(sc[ni][0] - mn0);
            sc[ni][1] = __expf(sc[ni][1] - mn0);
            sc[ni][2] = __expf(sc[ni][2] - mn1);
            sc[ni][3] = __expf(sc[ni][3] - mn1);
            rs0 += sc[ni][0] + sc[ni][1];
            rs1 += sc[ni][2] + sc[ni][3];
        }
        rs0 += __shfl_xor_sync(0xffffffffu, rs0, 1);
        rs0 += __shfl_xor_sync(0xffffffffu, rs0, 2);
        rs1 += __shfl_xor_sync(0xffffffffu, rs1, 1);
        rs1 += __shfl_xor_sync(0xffffffffu, rs1, 2);
        l0 = l0 * cr0 + rs0;
        l1 = l1 * cr1 + rs1;
        m0v = mn0; m1v = mn1;
        #pragma unroll
        for (int ni = 0; ni < 8; ni++) {
            o[ni][0] *= cr0; o[ni][1] *= cr0;
            o[ni][2] *= cr1; o[ni][3] *= cr1;
        }

        #pragma unroll
        for (int ks = 0; ks < 4; ks++) {
            uint32_t pa[4];
            pa[0] = f2h2(sc[2 * ks][0],     sc[2 * ks][1]);
            pa[1] = f2h2(sc[2 * ks][2],     sc[2 * ks][3]);
            pa[2] = f2h2(sc[2 * ks + 1][0], sc[2 * ks + 1][1]);
            pa[3] = f2h2(sc[2 * ks + 1][2], sc[2 * ks + 1][3]);
            #pragma unroll
            for (int g = 0; g < 4; g++) {
                uint32_t vf[4];
                LDSM_X4(vf, vFrag + off + g * 16 * AT_STRIDE + ks * 32);
                mma_f16(o[2 * g],     pa, vf + 0);
                mma_f16(o[2 * g + 1], pa, vf + 2);
            }
        }
        __syncthreads();
    }
    #undef AT_ISSUE

    float inv0 = 1.0f / l0, inv1 = 1.0f / l1;
    const int rbase = s0 + warp * 16;
    #pragma unroll
    for (int ni = 0; ni < 8; ni++) {
        int col = h * HD + ni * 8 + 2 * lr;
        __half2 a = __floats2half2_rn(o[ni][0] * inv0, o[ni][1] * inv0);
        __half2 c = __floats2half2_rn(o[ni][2] * inv1, o[ni][3] * inv1);
        *(__half2*)&av[(size_t)(b * SDIM + rbase + lq) * BDIM + col]     = a;
        *(__half2*)&av[(size_t)(b * SDIM + rbase + lq + 8) * BDIM + col] = c;
    }
}

// ---------------------------------------------------------------------------
// LayerNorm over last dim (512). f32 in; templated output type.
// ---------------------------------------------------------------------------
template <typename OutT>
__global__ void ln_kernel(const float* __restrict__ in, const float* __restrict__ g,
                          const float* __restrict__ beta, OutT* __restrict__ out) {
    const int row = blockIdx.x;
    const float* x = in + (size_t)row * BDIM;
    const int tid = threadIdx.x;
    const int wid = tid >> 5, lane = tid & 31;

    float v0 = x[tid], v1 = x[tid + 256];
    __shared__ float red[8];

    float s = v0 + v1;
    #pragma unroll
    for (int off = 16; off > 0; off >>= 1)
        s += __shfl_xor_sync(0xffffffffu, s, off);
    if (lane == 0) red[wid] = s;
    __syncthreads();
    float tot = 0.f;
    #pragma unroll
    for (int i = 0; i < 8; i++) tot += red[i];
    float mu = tot * (1.0f / 512.0f);
    __syncthreads();

    float d0 = v0 - mu, d1 = v1 - mu;
    float sq = d0 * d0 + d1 * d1;
    #pragma unroll
    for (int off = 16; off > 0; off >>= 1)
        sq += __shfl_xor_sync(0xffffffffu, sq, off);
    if (lane == 0) red[wid] = sq;
    __syncthreads();
    float tot2 = 0.f;
    #pragma unroll
    for (int i = 0; i < 8; i++) tot2 += red[i];
    float rstd = rsqrtf(tot2 * (1.0f / 512.0f) + 1e-5f);

    float y0 = d0 * rstd * g[tid]       + beta[tid];
    float y1 = d1 * rstd * g[tid + 256] + beta[tid + 256];
    out[(size_t)row * BDIM + tid]       = (OutT)y0;
    out[(size_t)row * BDIM + tid + 256] = (OutT)y1;
}

// ---------------------------------------------------------------------------
extern "C" void kernel_launch(void* const* d_in, const int* in_sizes, int n_in,
                              void* d_out, int out_size) {
    const float* src = (const float*)d_in[0];
    const float* Wq  = (const float*)d_in[1];
    const float* bq  = (const float*)d_in[2];
    const float* Wk  = (const float*)d_in[3];
    const float* bk  = (const float*)d_in[4];
    const float* Wv  = (const float*)d_in[5];
    const float* bv  = (const float*)d_in[6];
    const float* Wo  = (const float*)d_in[7];
    const float* bo  = (const float*)d_in[8];
    const float* W1  = (const float*)d_in[9];
    const float* b1  = (const float*)d_in[10];
    const float* W2  = (const float*)d_in[11];
    const float* b2  = (const float*)d_in[12];
    const float* g1  = (const float*)d_in[13];
    const float* be1 = (const float*)d_in[14];
    const float* g2  = (const float*)d_in[15];
    const float* be2 = (const float*)d_in[16];
    float* out = (float*)d_out;

    float *t1;
    __half *srch, *q, *k, *v, *av, *x1, *ff, *wt, *wc;
    cudaGetSymbolAddress((void**)&srch, g_srch);
    cudaGetSymbolAddress((void**)&q,  g_q);
    cudaGetSymbolAddress((void**)&k,  g_k);
    cudaGetSymbolAddress((void**)&v,  g_v);
    cudaGetSymbolAddress((void**)&av, g_av);
    cudaGetSymbolAddress((void**)&t1, g_t1);
    cudaGetSymbolAddress((void**)&x1, g_x1);
    cudaGetSymbolAddress((void**)&ff, g_ff);
    cudaGetSymbolAddress((void**)&wt, g_wt);
    cudaGetSymbolAddress((void**)&wc, g_wc);

    wprep_kernel<<<(WPREP_TOTAL + 255) / 256, 256>>>(Wq, Wk, Wv, Wo, W1, W2, src, wt, wc, srch);

    convqk4<<<dim3(NTOK / 128, BDIM / 64), 256>>>(srch, wt, bq, bk, q, k);
    gemm4<3><<<dim3(NTOK / 128, BDIM / 128), 256>>>(srch, wc + WC_WV, bv, nullptr, v, BDIM, BDIM);

    attn_mma2<<<dim3(SDIM / 64, NHEADS, BATCH), 128>>>(q, k, v, av);

    gemm4<0><<<dim3(NTOK / 128, BDIM / 128), 256>>>(av, wc + WC_WO, bo, src, t1, BDIM, BDIM);
    ln_kernel<__half><<<NTOK, 256>>>(t1, g1, be1, x1);

    gemm4<1><<<dim3(NTOK / 128, DFF / 128), 256>>>(x1, wc + WC_W1, b1, nullptr, ff, DFF, BDIM);
    gemm4<2><<<dim3(NTOK / 128, BDIM / 128), 256>>>(ff, wc + WC_W2, b2, x1, t1, BDIM, DFF);
    ln_kernel<float><<<NTOK, 256>>>(t1, g2, be2, out);
}